// round 1
// baseline (speedup 1.0000x reference)
#include <cuda_runtime.h>
#include <math.h>
#include <float.h>

#define B_ 16
#define N_ 2048
#define C_ 512
#define EPS_ 1e-9f
#define BNEPS_ 1e-5f

// ---------------- device scratch (no cudaMalloc allowed) ----------------
__device__ float g_Q[B_ * N_ * C_];        // 64 MB
__device__ float g_K[B_ * N_ * C_];        // 64 MB
__device__ float g_V[B_ * N_ * C_];        // 64 MB
__device__ float g_VO[B_ * N_ * C_];       // 64 MB
__device__ float g_S[67108864];            // B*N*N fp32 scores, 256 MB
__device__ float g_rmax[B_ * N_];
__device__ float g_rinv[B_ * N_];
__device__ float g_scale[B_ * N_];

// packed f32x2 FMA (sm_100+ packed-f32 pipe): d = a*b + c elementwise on 2 lanes
union F2U { float2 f; unsigned long long u; };
__device__ __forceinline__ float2 ffma2(float2 a, float2 b, float2 c) {
    F2U A, Bv, Cv, D;
    A.f = a; Bv.f = b; Cv.f = c;
    asm("fma.rn.f32x2 %0, %1, %2, %3;" : "=l"(D.u) : "l"(A.u), "l"(Bv.u), "l"(Cv.u));
    return D.f;
}

// ---------------------------------------------------------------------------
// GEMM: out[M=32768, 512] = A[M,512] @ W[512,512] (+ bias), fp32.
// 128x128 block tile, BK=8, 256 threads, 8x8 per-thread microtile (f32x2 packed).
// mode: 0 -> out=g_Q, 1 -> out=g_K, 2 -> out=g_V, 3 -> A=g_V, out=g_VO
// ---------------------------------------------------------------------------
__global__ __launch_bounds__(256) void sgemm512(const float* __restrict__ Aext,
                                                const float* __restrict__ W,
                                                const float* __restrict__ bias,
                                                int mode)
{
    __shared__ __align__(16) float As[8][128];
    __shared__ __align__(16) float Bs[8][128];

    const float* A = (mode == 3) ? g_V : Aext;
    float* out = (mode == 0) ? g_Q : (mode == 1) ? g_K : (mode == 2) ? g_V : g_VO;

    const int tid = threadIdx.x;
    const int bm = blockIdx.y * 128;
    const int bn = blockIdx.x * 128;
    const int tx = tid & 15;          // 16 cols of threads  -> 128 n
    const int ty = tid >> 4;          // 16 rows of threads  -> 128 m

    // A tile load: 128 rows x 8 k, 1 float4 per thread
    const int arow = tid >> 1;            // 0..127
    const int acol = (tid & 1) * 4;       // 0 or 4
    // W tile load: 8 k x 128 n, 1 float4 per thread
    const int brow = tid >> 5;            // 0..7
    const int bcol = (tid & 31) * 4;      // 0..124

    const float* Ap = A + (size_t)(bm + arow) * C_ + acol;
    const float* Wp = W + (size_t)brow * C_ + bn + bcol;

    float2 acc[8][4];
#pragma unroll
    for (int i = 0; i < 8; i++)
#pragma unroll
        for (int j = 0; j < 4; j++) acc[i][j] = make_float2(0.f, 0.f);

    for (int k0 = 0; k0 < C_; k0 += 8) {
        float4 av = *(const float4*)(Ap + k0);
        float4 wv = *(const float4*)(Wp + (size_t)k0 * C_);
        As[acol + 0][arow] = av.x;
        As[acol + 1][arow] = av.y;
        As[acol + 2][arow] = av.z;
        As[acol + 3][arow] = av.w;
        *(float4*)(&Bs[brow][bcol]) = wv;
        __syncthreads();
#pragma unroll
        for (int k = 0; k < 8; k++) {
            float4 a0 = *(const float4*)(&As[k][ty * 8]);
            float4 a1 = *(const float4*)(&As[k][ty * 8 + 4]);
            float4 b0 = *(const float4*)(&Bs[k][tx * 8]);
            float4 b1 = *(const float4*)(&Bs[k][tx * 8 + 4]);
            float av8[8] = {a0.x, a0.y, a0.z, a0.w, a1.x, a1.y, a1.z, a1.w};
            float2 bv2[4] = {make_float2(b0.x, b0.y), make_float2(b0.z, b0.w),
                             make_float2(b1.x, b1.y), make_float2(b1.z, b1.w)};
#pragma unroll
            for (int i = 0; i < 8; i++) {
                float2 ab = make_float2(av8[i], av8[i]);
#pragma unroll
                for (int j = 0; j < 4; j++) acc[i][j] = ffma2(ab, bv2[j], acc[i][j]);
            }
        }
        __syncthreads();
    }

#pragma unroll
    for (int i = 0; i < 8; i++) {
        const int row = bm + ty * 8 + i;
        const int col = bn + tx * 8;
        float4 o0 = make_float4(acc[i][0].x, acc[i][0].y, acc[i][1].x, acc[i][1].y);
        float4 o1 = make_float4(acc[i][2].x, acc[i][2].y, acc[i][3].x, acc[i][3].y);
        if (bias) {
            float4 bb0 = *(const float4*)(bias + col);
            float4 bb1 = *(const float4*)(bias + col + 4);
            o0.x += bb0.x; o0.y += bb0.y; o0.z += bb0.z; o0.w += bb0.w;
            o1.x += bb1.x; o1.y += bb1.y; o1.z += bb1.z; o1.w += bb1.w;
        }
        *(float4*)(out + (size_t)row * C_ + col) = o0;
        *(float4*)(out + (size_t)row * C_ + col + 4) = o1;
    }
}

// ---------------------------------------------------------------------------
// QK^T per batch with fused online row-softmax stats.
// Block = (batch, 64-row tile). Loops over 16 column tiles of 128.
// Each thread: 4 rows x 8 cols. Stores raw scores to g_S, writes rowmax + 1/sumexp.
// ---------------------------------------------------------------------------
__global__ __launch_bounds__(256) void qk_stats()
{
    const int b = blockIdx.y;
    const int m0 = blockIdx.x * 64;
    const float* Qb = g_Q + (size_t)b * N_ * C_;
    const float* Kb = g_K + (size_t)b * N_ * C_;
    float* Sb = g_S + (size_t)b * N_ * N_;

    __shared__ __align__(16) float Qs[8][64];
    __shared__ __align__(16) float Ks[8][128];

    const int tid = threadIdx.x;
    const int tx = tid & 15;      // 16 -> 128 cols (8 each)
    const int ty = tid >> 4;      // 16 -> 64 rows (4 each)

    // Q tile load: 64 rows x 8 k -> float2 per thread
    const int qm = tid >> 2;              // 0..63
    const int qk = (tid & 3) * 2;         // 0,2,4,6
    // K tile load: 128 rows x 8 k -> float4 per thread
    const int kn = tid >> 1;              // 0..127
    const int kk = (tid & 1) * 4;         // 0 or 4

    float rmax[4], rsum[4];
#pragma unroll
    for (int i = 0; i < 4; i++) { rmax[i] = -FLT_MAX; rsum[i] = 0.f; }

    const float* Qp = Qb + (size_t)(m0 + qm) * C_ + qk;

    for (int n0 = 0; n0 < N_; n0 += 128) {
        const float* Kp = Kb + (size_t)(n0 + kn) * C_ + kk;
        float2 acc[4][4];
#pragma unroll
        for (int i = 0; i < 4; i++)
#pragma unroll
            for (int j = 0; j < 4; j++) acc[i][j] = make_float2(0.f, 0.f);

        for (int k0 = 0; k0 < C_; k0 += 8) {
            float2 qv = *(const float2*)(Qp + k0);
            float4 kv = *(const float4*)(Kp + k0);
            Qs[qk + 0][qm] = qv.x;
            Qs[qk + 1][qm] = qv.y;
            Ks[kk + 0][kn] = kv.x;
            Ks[kk + 1][kn] = kv.y;
            Ks[kk + 2][kn] = kv.z;
            Ks[kk + 3][kn] = kv.w;
            __syncthreads();
#pragma unroll
            for (int k = 0; k < 8; k++) {
                float4 q4 = *(const float4*)(&Qs[k][ty * 4]);
                float4 b0 = *(const float4*)(&Ks[k][tx * 8]);
                float4 b1 = *(const float4*)(&Ks[k][tx * 8 + 4]);
                float qa[4] = {q4.x, q4.y, q4.z, q4.w};
                float2 bv[4] = {make_float2(b0.x, b0.y), make_float2(b0.z, b0.w),
                                make_float2(b1.x, b1.y), make_float2(b1.z, b1.w)};
#pragma unroll
                for (int i = 0; i < 4; i++) {
                    float2 qb = make_float2(qa[i], qa[i]);
#pragma unroll
                    for (int j = 0; j < 4; j++) acc[i][j] = ffma2(qb, bv[j], acc[i][j]);
                }
            }
            __syncthreads();
        }

        // store scores + online stats
#pragma unroll
        for (int i = 0; i < 4; i++) {
            const int m = m0 + ty * 4 + i;
            float s[8] = {acc[i][0].x, acc[i][0].y, acc[i][1].x, acc[i][1].y,
                          acc[i][2].x, acc[i][2].y, acc[i][3].x, acc[i][3].y};
            float* sp = Sb + (size_t)m * N_ + n0 + tx * 8;
            *(float4*)sp = make_float4(s[0], s[1], s[2], s[3]);
            *(float4*)(sp + 4) = make_float4(s[4], s[5], s[6], s[7]);

            float tmax = s[0];
#pragma unroll
            for (int j = 1; j < 8; j++) tmax = fmaxf(tmax, s[j]);
#pragma unroll
            for (int off = 1; off < 16; off <<= 1)
                tmax = fmaxf(tmax, __shfl_xor_sync(0xffffffffu, tmax, off));

            const float mnew = fmaxf(rmax[i], tmax);
            float tsum = 0.f;
#pragma unroll
            for (int j = 0; j < 8; j++) tsum += expf(s[j] - mnew);
#pragma unroll
            for (int off = 1; off < 16; off <<= 1)
                tsum += __shfl_xor_sync(0xffffffffu, tsum, off);

            rsum[i] = rsum[i] * expf(rmax[i] - mnew) + tsum;
            rmax[i] = mnew;
        }
    }

    if (tx == 0) {
#pragma unroll
        for (int i = 0; i < 4; i++) {
            const int m = m0 + ty * 4 + i;
            g_rmax[b * N_ + m] = rmax[i];
            g_rinv[b * N_ + m] = 1.f / rsum[i];
        }
    }
}

// ---------------------------------------------------------------------------
// Column sums of softmax: col[b,n] = sum_m exp(S[m,n]-rowmax[m]) * rinv[m].
// Coalesced over n; rowmax/rinv staged through smem. Writes scale directly.
// ---------------------------------------------------------------------------
__global__ __launch_bounds__(256) void colsum_kernel()
{
    const int b = blockIdx.y;
    const int n = blockIdx.x * 256 + threadIdx.x;
    __shared__ float sm[256];
    __shared__ float si[256];
    const float* Sb = g_S + (size_t)b * N_ * N_;

    float acc = 0.f;
    for (int m0 = 0; m0 < N_; m0 += 256) {
        __syncthreads();
        sm[threadIdx.x] = g_rmax[b * N_ + m0 + threadIdx.x];
        si[threadIdx.x] = g_rinv[b * N_ + m0 + threadIdx.x];
        __syncthreads();
#pragma unroll 8
        for (int mm = 0; mm < 256; mm++)
            acc += expf(Sb[(size_t)(m0 + mm) * N_ + n] - sm[mm]) * si[mm];
    }
    g_scale[b * N_ + n] = acc / (EPS_ + acc);
}

// ---------------------------------------------------------------------------
// Fused epilogue: y = scale*(V@Wo) + bo -> BatchNorm(running stats) -> ReLU -> +x
// ---------------------------------------------------------------------------
__global__ __launch_bounds__(256) void epilogue_kernel(const float* __restrict__ x,
                                                       const float* __restrict__ bo,
                                                       const float* __restrict__ bns,
                                                       const float* __restrict__ bnb,
                                                       const float* __restrict__ bnm,
                                                       const float* __restrict__ bnv,
                                                       float* __restrict__ out)
{
    const size_t idx = (size_t)blockIdx.x * 256 + threadIdx.x;
    const int c = (int)(idx & (C_ - 1));
    const int rn = (int)(idx >> 9);   // b*N + n
    float y = g_scale[rn] * g_VO[idx] + __ldg(bo + c);
    y = (y - __ldg(bnm + c)) * rsqrtf(__ldg(bnv + c) + BNEPS_) * __ldg(bns + c) + __ldg(bnb + c);
    out[idx] = fmaxf(y, 0.f) + x[idx];
}

// ---------------------------------------------------------------------------
extern "C" void kernel_launch(void* const* d_in, const int* in_sizes, int n_in,
                              void* d_out, int out_size)
{
    const float* x   = (const float*)d_in[0];
    const float* Wq  = (const float*)d_in[1];
    const float* bq  = (const float*)d_in[2];
    const float* Wk  = (const float*)d_in[3];
    const float* bk  = (const float*)d_in[4];
    const float* Wv  = (const float*)d_in[5];
    const float* bv  = (const float*)d_in[6];
    const float* Wo  = (const float*)d_in[7];
    const float* bo  = (const float*)d_in[8];
    const float* bns = (const float*)d_in[9];
    const float* bnb = (const float*)d_in[10];
    const float* bnm = (const float*)d_in[11];
    const float* bnv = (const float*)d_in[12];
    float* out = (float*)d_out;

    const dim3 gg(C_ / 128, (B_ * N_) / 128);   // (4, 256)

    sgemm512<<<gg, 256>>>(x, Wq, bq, 0);        // g_Q
    sgemm512<<<gg, 256>>>(x, Wk, bk, 1);        // g_K
    sgemm512<<<gg, 256>>>(x, Wv, bv, 2);        // g_V

    qk_stats<<<dim3(N_ / 64, B_), 256>>>();     // S + row stats
    colsum_kernel<<<dim3(N_ / 256, B_), 256>>>();   // scale

    sgemm512<<<gg, 256>>>(nullptr, Wo, nullptr, 3); // g_VO = g_V @ Wo

    epilogue_kernel<<<(B_ * N_ * C_) / 256, 256>>>(x, bo, bns, bnb, bnm, bnv, out);
}

// round 5
// speedup vs baseline: 3.8884x; 3.8884x over previous
#include <cuda_runtime.h>
#include <cuda_bf16.h>
#include <math.h>
#include <float.h>
#include <stdint.h>

#define B_ 16
#define N_ 2048
#define C_ 512
#define EPS_ 1e-9f
#define BNEPS_ 1e-5f

typedef __nv_bfloat16 bf16;

// ------------------------- device scratch ---------------------------------
__device__ bf16 g_xh[B_ * N_ * C_], g_xl[B_ * N_ * C_];
__device__ bf16 g_qh[B_ * N_ * C_], g_ql[B_ * N_ * C_];
__device__ bf16 g_kh[B_ * N_ * C_], g_kl[B_ * N_ * C_];
__device__ bf16 g_vh[B_ * N_ * C_], g_vl[B_ * N_ * C_];
__device__ bf16 g_wth[4][C_ * C_], g_wtl[4][C_ * C_];
__device__ float g_S[(size_t)B_ * N_ * N_];          // 256 MB raw scores
__device__ float g_pmax[B_ * 16 * N_], g_psum[B_ * 16 * N_];
__device__ float g_rmax[B_ * N_], g_rinv[B_ * N_], g_scale[B_ * N_];
__device__ float g_kmul[C_], g_kadd[C_];

// ------------------------------ helpers ------------------------------------
__device__ __forceinline__ uint32_t smem_u32(const void* p) {
    uint32_t a;
    asm("{ .reg .u64 t; cvta.to.shared.u64 t, %1; cvt.u32.u64 %0, t; }" : "=r"(a) : "l"(p));
    return a;
}
#define SWZ(o) ((o) ^ (((o) >> 3) & 0x70))

#define CPASYNC(s, g) asm volatile("cp.async.cg.shared.global [%0], [%1], 16;" :: "r"(s), "l"(g))
#define CPCOMMIT()    asm volatile("cp.async.commit_group;" ::: "memory")
#define CPWAIT1()     asm volatile("cp.async.wait_group 1;" ::: "memory")
#define CPWAIT0()     asm volatile("cp.async.wait_group 0;" ::: "memory")

__device__ __forceinline__ void ldsm4(uint32_t addr, uint32_t& r0, uint32_t& r1,
                                      uint32_t& r2, uint32_t& r3) {
    asm volatile("ldmatrix.sync.aligned.m8n8.x4.shared.b16 {%0,%1,%2,%3}, [%4];"
                 : "=r"(r0), "=r"(r1), "=r"(r2), "=r"(r3) : "r"(addr));
}

__device__ __forceinline__ void mma16816(float* c, uint32_t a0, uint32_t a1,
                                         uint32_t a2, uint32_t a3,
                                         uint32_t b0, uint32_t b1) {
    asm volatile(
        "mma.sync.aligned.m16n8k16.row.col.f32.bf16.bf16.f32 "
        "{%0,%1,%2,%3}, {%4,%5,%6,%7}, {%8,%9}, {%0,%1,%2,%3};"
        : "+f"(c[0]), "+f"(c[1]), "+f"(c[2]), "+f"(c[3])
        : "r"(a0), "r"(a1), "r"(a2), "r"(a3), "r"(b0), "r"(b1));
}

// ----------------------------- smem layout ----------------------------------
// stage (0/1): Ah +0, Al +16384, Bh +32768, Bl +49152 ; stage stride 65536
#define STAGE_STRIDE 65536
#define OFF_RED 131072
#define DYN_SMEM (131072 + 2048)

// ------------------------- cp.async stage loader -----------------------------
__device__ __forceinline__ void load_stage(uint32_t sb, int s, int tid,
        const bf16* __restrict__ Ah, const bf16* __restrict__ Al, size_t arow0,
        const bf16* __restrict__ Bh, const bf16* __restrict__ Bl, size_t brow0)
{
    const int k0 = s * 64;
    const uint32_t stb = sb + (uint32_t)(s & 1) * STAGE_STRIDE;
#pragma unroll
    for (int i = 0; i < 4; ++i) {
        const int idx = tid + i * 256;       // 0..1023
        const int row = idx >> 3;            // 0..127
        const int c = idx & 7;               // 16B chunk
        const uint32_t off = SWZ((uint32_t)(row * 128 + c * 16));
        const size_t ga = (arow0 + row) * C_ + k0 + c * 8;
        const size_t gb = (brow0 + row) * C_ + k0 + c * 8;
        CPASYNC(stb + off,         Ah + ga);
        CPASYNC(stb + 16384 + off, Al + ga);
        CPASYNC(stb + 32768 + off, Bh + gb);
        CPASYNC(stb + 49152 + off, Bl + gb);
    }
    CPCOMMIT();
}

// -------------------- compute one 64-K stage into acc ------------------------
__device__ __forceinline__ void compute_stage(uint32_t sb, int s, int lane,
                                              int wm, int wn, float acc[2][8][4])
{
    const uint32_t stb = sb + (uint32_t)(s & 1) * STAGE_STRIDE;
#pragma unroll
    for (int k16 = 0; k16 < 4; ++k16) {
        uint32_t ah[2][4], al[2][4], bh[4][4], bl[4][4];
        // A fragments: rows wm*32 + mt*16 + (lane&15), k chunk (lane>>4)*8
        const uint32_t akoff = (uint32_t)(k16 * 32 + (lane >> 4) * 16);
#pragma unroll
        for (int mt = 0; mt < 2; ++mt) {
            const int row = wm * 32 + mt * 16 + (lane & 15);
            const uint32_t a = SWZ((uint32_t)(row * 128) + akoff);
            ldsm4(stb + a,         ah[mt][0], ah[mt][1], ah[mt][2], ah[mt][3]);
            ldsm4(stb + 16384 + a, al[mt][0], al[mt][1], al[mt][2], al[mt][3]);
        }
        // B fragments: groups g=lane>>3: {n0-7 k0, n0-7 k8, n8-15 k0, n8-15 k8}
        const int g = lane >> 3;
        const int nofs = (lane & 7) + (g >> 1) * 8;
        const uint32_t bk = (uint32_t)(k16 * 32 + (g & 1) * 16);
#pragma unroll
        for (int nt4 = 0; nt4 < 4; ++nt4) {
            const int n = wn * 64 + nt4 * 16 + nofs;
            const uint32_t a = SWZ((uint32_t)(n * 128) + bk);
            ldsm4(stb + 32768 + a, bh[nt4][0], bh[nt4][1], bh[nt4][2], bh[nt4][3]);
            ldsm4(stb + 49152 + a, bl[nt4][0], bl[nt4][1], bl[nt4][2], bl[nt4][3]);
        }
        // hh combo
#pragma unroll
        for (int mt = 0; mt < 2; ++mt)
#pragma unroll
            for (int j = 0; j < 8; ++j) {
                const int p = j >> 1, hi = (j & 1) * 2;
                mma16816(acc[mt][j], ah[mt][0], ah[mt][1], ah[mt][2], ah[mt][3],
                         bh[p][hi], bh[p][hi + 1]);
            }
        // hl combo
#pragma unroll
        for (int mt = 0; mt < 2; ++mt)
#pragma unroll
            for (int j = 0; j < 8; ++j) {
                const int p = j >> 1, hi = (j & 1) * 2;
                mma16816(acc[mt][j], ah[mt][0], ah[mt][1], ah[mt][2], ah[mt][3],
                         bl[p][hi], bl[p][hi + 1]);
            }
        // lh combo
#pragma unroll
        for (int mt = 0; mt < 2; ++mt)
#pragma unroll
            for (int j = 0; j < 8; ++j) {
                const int p = j >> 1, hi = (j & 1) * 2;
                mma16816(acc[mt][j], al[mt][0], al[mt][1], al[mt][2], al[mt][3],
                         bh[p][hi], bh[p][hi + 1]);
            }
    }
}

// ------------------- full mainloop: D[128,128] = A·B^T (split) ---------------
__device__ __forceinline__ void mma_mainloop(uint32_t sb,
        const bf16* __restrict__ Ah, const bf16* __restrict__ Al, size_t arow0,
        const bf16* __restrict__ Bh, const bf16* __restrict__ Bl, size_t brow0,
        float acc[2][8][4])
{
    const int tid = threadIdx.x;
    const int lane = tid & 31;
    const int w = tid >> 5;
    const int wm = w & 3, wn = w >> 2;

#pragma unroll
    for (int mt = 0; mt < 2; ++mt)
#pragma unroll
        for (int j = 0; j < 8; ++j)
#pragma unroll
            for (int q = 0; q < 4; ++q) acc[mt][j][q] = 0.f;

    load_stage(sb, 0, tid, Ah, Al, arow0, Bh, Bl, brow0);
#pragma unroll 1
    for (int s = 0; s < 8; ++s) {
        if (s < 7) {
            load_stage(sb, s + 1, tid, Ah, Al, arow0, Bh, Bl, brow0);
            CPWAIT1();
        } else {
            CPWAIT0();
        }
        __syncthreads();
        compute_stage(sb, s, lane, wm, wn, acc);
        __syncthreads();
    }
}

// ------------------------- projection GEMM -----------------------------------
__global__ __launch_bounds__(256, 1)
void gemm_proj(const bf16* __restrict__ Bh, const bf16* __restrict__ Bl,
               const float* __restrict__ bias,
               bf16* __restrict__ outH, bf16* __restrict__ outL)
{
    extern __shared__ __align__(128) char smem[];
    const uint32_t sb = smem_u32(smem);
    const size_t arow0 = (size_t)blockIdx.x * 128;
    const size_t brow0 = (size_t)blockIdx.y * 128;

    float acc[2][8][4];
    mma_mainloop(sb, g_xh, g_xl, arow0, Bh, Bl, brow0, acc);

    const int tid = threadIdx.x, lane = tid & 31, w = tid >> 5;
    const int wm = w & 3, wn = w >> 2;
#pragma unroll
    for (int mt = 0; mt < 2; ++mt) {
        const int r0 = wm * 32 + mt * 16 + lane / 4;
#pragma unroll
        for (int half = 0; half < 2; ++half) {
            const size_t grow = arow0 + r0 + half * 8;
#pragma unroll
            for (int j = 0; j < 8; ++j) {
                const int col = (int)brow0 + wn * 64 + j * 8 + (lane & 3) * 2;
                const float v0 = acc[mt][j][half * 2 + 0] + __ldg(bias + col);
                const float v1 = acc[mt][j][half * 2 + 1] + __ldg(bias + col + 1);
                const bf16 h0 = __float2bfloat16(v0);
                const bf16 h1 = __float2bfloat16(v1);
                __nv_bfloat162 hh; hh.x = h0; hh.y = h1;
                __nv_bfloat162 ll;
                ll.x = __float2bfloat16(v0 - __bfloat162float(h0));
                ll.y = __float2bfloat16(v1 - __bfloat162float(h1));
                *(__nv_bfloat162*)(outH + grow * C_ + col) = hh;
                *(__nv_bfloat162*)(outL + grow * C_ + col) = ll;
            }
        }
    }
}

// ----------------------- QK^T GEMM + tile stats ------------------------------
__global__ __launch_bounds__(256, 1)
void gemm_qk()
{
    extern __shared__ __align__(128) char smem[];
    const uint32_t sb = smem_u32(smem);
    float* red = (float*)(smem + OFF_RED);

    const int it = blockIdx.x, jt = blockIdx.y, bb = blockIdx.z;
    const size_t arow0 = (size_t)bb * N_ + (size_t)it * 128;
    const size_t brow0 = (size_t)bb * N_ + (size_t)jt * 128;

    float acc[2][8][4];
    mma_mainloop(sb, g_qh, g_ql, arow0, g_kh, g_kl, brow0, acc);

    const int tid = threadIdx.x, lane = tid & 31, w = tid >> 5;
    const int wm = w & 3, wn = w >> 2;

    // ---- row max: each thread owns 4 row-slots (mt x half), 16 vals each
    float rmx[4];
#pragma unroll
    for (int slot = 0; slot < 4; ++slot) {
        const int mt = slot >> 1, half = slot & 1;
        float m = -FLT_MAX;
#pragma unroll
        for (int j = 0; j < 8; ++j) {
            m = fmaxf(m, acc[mt][j][half * 2 + 0]);
            m = fmaxf(m, acc[mt][j][half * 2 + 1]);
        }
        m = fmaxf(m, __shfl_xor_sync(0xffffffffu, m, 1));
        m = fmaxf(m, __shfl_xor_sync(0xffffffffu, m, 2));
        rmx[slot] = m;
    }
    if ((lane & 3) == 0) {
#pragma unroll
        for (int slot = 0; slot < 4; ++slot) {
            const int row = wm * 32 + (slot >> 1) * 16 + (slot & 1) * 8 + lane / 4;
            red[row * 2 + wn] = rmx[slot];
        }
    }
    __syncthreads();
    float rowmax[4];
#pragma unroll
    for (int slot = 0; slot < 4; ++slot) {
        const int row = wm * 32 + (slot >> 1) * 16 + (slot & 1) * 8 + lane / 4;
        rowmax[slot] = fmaxf(red[row * 2], red[row * 2 + 1]);
    }
    __syncthreads();

    // ---- store raw S + sumexp
    float rsm[4];
#pragma unroll
    for (int slot = 0; slot < 4; ++slot) {
        const int mt = slot >> 1, half = slot & 1;
        const int row = wm * 32 + mt * 16 + half * 8 + lane / 4;
        float* Srow = g_S + ((size_t)bb * N_ + it * 128 + row) * N_ + jt * 128;
        float s = 0.f;
#pragma unroll
        for (int j = 0; j < 8; ++j) {
            const int col = wn * 64 + j * 8 + (lane & 3) * 2;
            const float v0 = acc[mt][j][half * 2 + 0];
            const float v1 = acc[mt][j][half * 2 + 1];
            *(float2*)(Srow + col) = make_float2(v0, v1);
            s += __expf(v0 - rowmax[slot]) + __expf(v1 - rowmax[slot]);
        }
        s += __shfl_xor_sync(0xffffffffu, s, 1);
        s += __shfl_xor_sync(0xffffffffu, s, 2);
        rsm[slot] = s;
    }
    if ((lane & 3) == 0) {
#pragma unroll
        for (int slot = 0; slot < 4; ++slot) {
            const int row = wm * 32 + (slot >> 1) * 16 + (slot & 1) * 8 + lane / 4;
            red[row * 2 + wn] = rsm[slot];
        }
    }
    __syncthreads();
    if (wn == 0 && (lane & 3) == 0) {
#pragma unroll
        for (int slot = 0; slot < 4; ++slot) {
            const int row = wm * 32 + (slot >> 1) * 16 + (slot & 1) * 8 + lane / 4;
            const size_t p = ((size_t)bb * 16 + jt) * N_ + it * 128 + row;
            g_pmax[p] = rowmax[slot];
            g_psum[p] = red[row * 2] + red[row * 2 + 1];
        }
    }
}

// ------------- final GEMM: (V @ Wo) with fully fused epilogue ----------------
__global__ __launch_bounds__(256, 1)
void gemm_out(const bf16* __restrict__ Bh, const bf16* __restrict__ Bl,
              const float* __restrict__ x, float* __restrict__ out)
{
    extern __shared__ __align__(128) char smem[];
    const uint32_t sb = smem_u32(smem);
    const size_t arow0 = (size_t)blockIdx.x * 128;
    const size_t brow0 = (size_t)blockIdx.y * 128;

    float acc[2][8][4];
    mma_mainloop(sb, g_vh, g_vl, arow0, Bh, Bl, brow0, acc);

    const int tid = threadIdx.x, lane = tid & 31, w = tid >> 5;
    const int wm = w & 3, wn = w >> 2;
#pragma unroll
    for (int mt = 0; mt < 2; ++mt) {
#pragma unroll
        for (int half = 0; half < 2; ++half) {
            const size_t grow = arow0 + wm * 32 + mt * 16 + half * 8 + lane / 4;
            const float sc = g_scale[grow];
#pragma unroll
            for (int j = 0; j < 8; ++j) {
                const int col = (int)brow0 + wn * 64 + j * 8 + (lane & 3) * 2;
                const float2 xv = *(const float2*)(x + grow * C_ + col);
                float y0 = sc * acc[mt][j][half * 2 + 0] * g_kmul[col] + g_kadd[col];
                float y1 = sc * acc[mt][j][half * 2 + 1] * g_kmul[col + 1] + g_kadd[col + 1];
                float2 o;
                o.x = fmaxf(y0, 0.f) + xv.x;
                o.y = fmaxf(y1, 0.f) + xv.y;
                *(float2*)(out + grow * C_ + col) = o;
            }
        }
    }
}

// ------------------------------- small kernels -------------------------------
__global__ __launch_bounds__(512) void xsplit_kernel(const float* __restrict__ x)
{
    const size_t i4 = (size_t)blockIdx.x * 512 + threadIdx.x;
    const float4 v = *(const float4*)(x + i4 * 4);
    const float a[4] = {v.x, v.y, v.z, v.w};
#pragma unroll
    for (int j = 0; j < 4; ++j) {
        bf16 h = __float2bfloat16(a[j]);
        g_xh[i4 * 4 + j] = h;
        g_xl[i4 * 4 + j] = __float2bfloat16(a[j] - __bfloat162float(h));
    }
}

__global__ void wtsplit_kernel(const float* __restrict__ W, int widx)
{
    __shared__ float t[32][33];
    const int x0 = blockIdx.x * 32, y0 = blockIdx.y * 32;
    for (int yy = threadIdx.y; yy < 32; yy += 8)
        t[yy][threadIdx.x] = W[(size_t)(y0 + yy) * C_ + x0 + threadIdx.x];
    __syncthreads();
    bf16* oh = g_wth[widx];
    bf16* ol = g_wtl[widx];
    for (int yy = threadIdx.y; yy < 32; yy += 8) {
        const float v = t[threadIdx.x][yy];        // = W[y0+tx][x0+yy]
        bf16 h = __float2bfloat16(v);
        const size_t o = (size_t)(x0 + yy) * C_ + y0 + threadIdx.x;
        oh[o] = h;
        ol[o] = __float2bfloat16(v - __bfloat162float(h));
    }
}

__global__ void bnprep_kernel(const float* __restrict__ bo,
                              const float* __restrict__ bns, const float* __restrict__ bnb,
                              const float* __restrict__ bnm, const float* __restrict__ bnv)
{
    const int c = threadIdx.x;
    const float ka = bns[c] * rsqrtf(bnv[c] + BNEPS_);
    g_kmul[c] = ka;
    g_kadd[c] = (bo[c] - bnm[c]) * ka + bnb[c];
}

__global__ __launch_bounds__(256) void combine_kernel()
{
    const int t = blockIdx.x * 256 + threadIdx.x;     // b*2048 + m
    const int b = t >> 11, m = t & (N_ - 1);
    float rmax = -FLT_MAX;
#pragma unroll
    for (int j = 0; j < 16; ++j)
        rmax = fmaxf(rmax, g_pmax[((size_t)b * 16 + j) * N_ + m]);
    float rsum = 0.f;
#pragma unroll
    for (int j = 0; j < 16; ++j) {
        const size_t p = ((size_t)b * 16 + j) * N_ + m;
        rsum += g_psum[p] * __expf(g_pmax[p] - rmax);
    }
    g_rmax[t] = rmax;
    g_rinv[t] = 1.f / rsum;
}

__global__ __launch_bounds__(256) void colsum_kernel()
{
    const int b = blockIdx.y;
    const int n = blockIdx.x * 256 + threadIdx.x;
    __shared__ float sm[256], si[256];
    const float* Sb = g_S + (size_t)b * N_ * N_;

    float acc = 0.f;
    for (int m0 = 0; m0 < N_; m0 += 256) {
        __syncthreads();
        sm[threadIdx.x] = g_rmax[b * N_ + m0 + threadIdx.x];
        si[threadIdx.x] = g_rinv[b * N_ + m0 + threadIdx.x];
        __syncthreads();
#pragma unroll 8
        for (int mm = 0; mm < 256; mm++)
            acc += __expf(Sb[(size_t)(m0 + mm) * N_ + n] - sm[mm]) * si[mm];
    }
    g_scale[b * N_ + n] = acc / (EPS_ + acc);
}

// --------------------------------- launch ------------------------------------
extern "C" void kernel_launch(void* const* d_in, const int* in_sizes, int n_in,
                              void* d_out, int out_size)
{
    const float* x   = (const float*)d_in[0];
    const float* Wq  = (const float*)d_in[1];
    const float* bq  = (const float*)d_in[2];
    const float* Wk  = (const float*)d_in[3];
    const float* bk  = (const float*)d_in[4];
    const float* Wv  = (const float*)d_in[5];
    const float* bv  = (const float*)d_in[6];
    const float* Wo  = (const float*)d_in[7];
    const float* bo  = (const float*)d_in[8];
    const float* bns = (const float*)d_in[9];
    const float* bnb = (const float*)d_in[10];
    const float* bnm = (const float*)d_in[11];
    const float* bnv = (const float*)d_in[12];
    float* out = (float*)d_out;

    cudaFuncSetAttribute(gemm_proj, cudaFuncAttributeMaxDynamicSharedMemorySize, DYN_SMEM);
    cudaFuncSetAttribute(gemm_qk,   cudaFuncAttributeMaxDynamicSharedMemorySize, DYN_SMEM);
    cudaFuncSetAttribute(gemm_out,  cudaFuncAttributeMaxDynamicSharedMemorySize, DYN_SMEM);

    bf16 *wth, *wtl, *qh, *ql, *kh, *kl, *vh, *vl;
    cudaGetSymbolAddress((void**)&wth, g_wth);
    cudaGetSymbolAddress((void**)&wtl, g_wtl);
    cudaGetSymbolAddress((void**)&qh, g_qh);
    cudaGetSymbolAddress((void**)&ql, g_ql);
    cudaGetSymbolAddress((void**)&kh, g_kh);
    cudaGetSymbolAddress((void**)&kl, g_kl);
    cudaGetSymbolAddress((void**)&vh, g_vh);
    cudaGetSymbolAddress((void**)&vl, g_vl);

    wtsplit_kernel<<<dim3(16, 16), dim3(32, 8)>>>(Wq, 0);
    wtsplit_kernel<<<dim3(16, 16), dim3(32, 8)>>>(Wk, 1);
    wtsplit_kernel<<<dim3(16, 16), dim3(32, 8)>>>(Wv, 2);
    wtsplit_kernel<<<dim3(16, 16), dim3(32, 8)>>>(Wo, 3);

    xsplit_kernel<<<(B_ * N_ * C_) / (512 * 4), 512>>>(x);
    bnprep_kernel<<<1, C_>>>(bo, bns, bnb, bnm, bnv);

    const dim3 gp(256, 4);   // 256 M-tiles x 4 N-tiles of 128
    gemm_proj<<<gp, 256, DYN_SMEM>>>(wth + 0 * C_ * C_, wtl + 0 * C_ * C_, bq, qh, ql);
    gemm_proj<<<gp, 256, DYN_SMEM>>>(wth + 1 * C_ * C_, wtl + 1 * C_ * C_, bk, kh, kl);
    gemm_proj<<<gp, 256, DYN_SMEM>>>(wth + 2 * C_ * C_, wtl + 2 * C_ * C_, bv, vh, vl);

    gemm_qk<<<dim3(16, 16, 16), 256, DYN_SMEM>>>();

    combine_kernel<<<(B_ * N_) / 256, 256>>>();
    colsum_kernel<<<dim3(N_ / 256, B_), 256>>>();

    gemm_out<<<gp, 256, DYN_SMEM>>>(wth + 3 * C_ * C_, wtl + 3 * C_ * C_, x, out);
}

// round 6
// speedup vs baseline: 4.5847x; 1.1791x over previous
#include <cuda_runtime.h>
#include <cuda_bf16.h>
#include <math.h>
#include <float.h>
#include <stdint.h>

#define B_ 16
#define N_ 2048
#define C_ 512
#define EPS_ 1e-9f
#define BNEPS_ 1e-5f

typedef __nv_bfloat16 bf16;

// ------------------------- device scratch ---------------------------------
__device__ bf16 g_xh[B_ * N_ * C_], g_xl[B_ * N_ * C_];
__device__ bf16 g_th[B_ * N_ * C_], g_tl[B_ * N_ * C_];
__device__ bf16 g_mth[C_ * C_], g_mtl[C_ * C_];   // (WqWk^T)^T split
__device__ bf16 g_pth[C_ * C_], g_ptl[C_ * C_];   // (WvWo)^T split
__device__ bf16 g_E[(size_t)B_ * N_ * N_];        // 128 MB: exp(s - pmax_tile)
__device__ float g_pmax[B_ * 16 * N_], g_psum[B_ * 16 * N_], g_w[B_ * 16 * N_];
__device__ float g_scale[B_ * N_], g_bcol[B_ * N_];
__device__ float g_v1[C_], g_c1[C_], g_kmul[C_], g_kadd[C_];

// ------------------------------ helpers ------------------------------------
__device__ __forceinline__ uint32_t smem_u32(const void* p) {
    uint32_t a;
    asm("{ .reg .u64 t; cvta.to.shared.u64 t, %1; cvt.u32.u64 %0, t; }" : "=r"(a) : "l"(p));
    return a;
}
#define SWZ(o) ((o) ^ (((o) >> 3) & 0x70))

#define CPASYNC(s, g) asm volatile("cp.async.cg.shared.global [%0], [%1], 16;" :: "r"(s), "l"(g))
#define CPCOMMIT()    asm volatile("cp.async.commit_group;" ::: "memory")
#define CPWAIT1()     asm volatile("cp.async.wait_group 1;" ::: "memory")
#define CPWAIT0()     asm volatile("cp.async.wait_group 0;" ::: "memory")

__device__ __forceinline__ void ldsm4(uint32_t addr, uint32_t& r0, uint32_t& r1,
                                      uint32_t& r2, uint32_t& r3) {
    asm volatile("ldmatrix.sync.aligned.m8n8.x4.shared.b16 {%0,%1,%2,%3}, [%4];"
                 : "=r"(r0), "=r"(r1), "=r"(r2), "=r"(r3) : "r"(addr));
}

__device__ __forceinline__ void mma16816(float* c, uint32_t a0, uint32_t a1,
                                         uint32_t a2, uint32_t a3,
                                         uint32_t b0, uint32_t b1) {
    asm volatile(
        "mma.sync.aligned.m16n8k16.row.col.f32.bf16.bf16.f32 "
        "{%0,%1,%2,%3}, {%4,%5,%6,%7}, {%8,%9}, {%0,%1,%2,%3};"
        : "+f"(c[0]), "+f"(c[1]), "+f"(c[2]), "+f"(c[3])
        : "r"(a0), "r"(a1), "r"(a2), "r"(a3), "r"(b0), "r"(b1));
}

// ----------------------------- smem layout ----------------------------------
#define STAGE_STRIDE 65536
#define OFF_RED 131072
#define DYN_SMEM (131072 + 2048)

// ------------------------- cp.async stage loader -----------------------------
__device__ __forceinline__ void load_stage(uint32_t sb, int s, int tid,
        const bf16* __restrict__ Ah, const bf16* __restrict__ Al, size_t arow0,
        const bf16* __restrict__ Bh, const bf16* __restrict__ Bl, size_t brow0)
{
    const int k0 = s * 64;
    const uint32_t stb = sb + (uint32_t)(s & 1) * STAGE_STRIDE;
#pragma unroll
    for (int i = 0; i < 4; ++i) {
        const int idx = tid + i * 256;
        const int row = idx >> 3;
        const int c = idx & 7;
        const uint32_t off = SWZ((uint32_t)(row * 128 + c * 16));
        const size_t ga = (arow0 + row) * C_ + k0 + c * 8;
        const size_t gb = (brow0 + row) * C_ + k0 + c * 8;
        CPASYNC(stb + off,         Ah + ga);
        CPASYNC(stb + 16384 + off, Al + ga);
        CPASYNC(stb + 32768 + off, Bh + gb);
        CPASYNC(stb + 49152 + off, Bl + gb);
    }
    CPCOMMIT();
}

// -------------------- compute one 64-K stage into acc ------------------------
__device__ __forceinline__ void compute_stage(uint32_t sb, int s, int lane,
                                              int wm, int wn, float acc[2][8][4])
{
    const uint32_t stb = sb + (uint32_t)(s & 1) * STAGE_STRIDE;
#pragma unroll
    for (int k16 = 0; k16 < 4; ++k16) {
        uint32_t ah[2][4], al[2][4], bh[4][4], bl[4][4];
        const uint32_t akoff = (uint32_t)(k16 * 32 + (lane >> 4) * 16);
#pragma unroll
        for (int mt = 0; mt < 2; ++mt) {
            const int row = wm * 32 + mt * 16 + (lane & 15);
            const uint32_t a = SWZ((uint32_t)(row * 128) + akoff);
            ldsm4(stb + a,         ah[mt][0], ah[mt][1], ah[mt][2], ah[mt][3]);
            ldsm4(stb + 16384 + a, al[mt][0], al[mt][1], al[mt][2], al[mt][3]);
        }
        const int g = lane >> 3;
        const int nofs = (lane & 7) + (g >> 1) * 8;
        const uint32_t bk = (uint32_t)(k16 * 32 + (g & 1) * 16);
#pragma unroll
        for (int nt4 = 0; nt4 < 4; ++nt4) {
            const int n = wn * 64 + nt4 * 16 + nofs;
            const uint32_t a = SWZ((uint32_t)(n * 128) + bk);
            ldsm4(stb + 32768 + a, bh[nt4][0], bh[nt4][1], bh[nt4][2], bh[nt4][3]);
            ldsm4(stb + 49152 + a, bl[nt4][0], bl[nt4][1], bl[nt4][2], bl[nt4][3]);
        }
#pragma unroll
        for (int mt = 0; mt < 2; ++mt)
#pragma unroll
            for (int j = 0; j < 8; ++j) {
                const int p = j >> 1, hi = (j & 1) * 2;
                mma16816(acc[mt][j], ah[mt][0], ah[mt][1], ah[mt][2], ah[mt][3],
                         bh[p][hi], bh[p][hi + 1]);
            }
#pragma unroll
        for (int mt = 0; mt < 2; ++mt)
#pragma unroll
            for (int j = 0; j < 8; ++j) {
                const int p = j >> 1, hi = (j & 1) * 2;
                mma16816(acc[mt][j], ah[mt][0], ah[mt][1], ah[mt][2], ah[mt][3],
                         bl[p][hi], bl[p][hi + 1]);
            }
#pragma unroll
        for (int mt = 0; mt < 2; ++mt)
#pragma unroll
            for (int j = 0; j < 8; ++j) {
                const int p = j >> 1, hi = (j & 1) * 2;
                mma16816(acc[mt][j], al[mt][0], al[mt][1], al[mt][2], al[mt][3],
                         bh[p][hi], bh[p][hi + 1]);
            }
    }
}

// ------------------- full mainloop: D[128,128] = A·B^T (split) ---------------
__device__ __forceinline__ void mma_mainloop(uint32_t sb,
        const bf16* __restrict__ Ah, const bf16* __restrict__ Al, size_t arow0,
        const bf16* __restrict__ Bh, const bf16* __restrict__ Bl, size_t brow0,
        float acc[2][8][4])
{
    const int tid = threadIdx.x;
    const int lane = tid & 31;
    const int w = tid >> 5;
    const int wm = w & 3, wn = w >> 2;

#pragma unroll
    for (int mt = 0; mt < 2; ++mt)
#pragma unroll
        for (int j = 0; j < 8; ++j)
#pragma unroll
            for (int q = 0; q < 4; ++q) acc[mt][j][q] = 0.f;

    load_stage(sb, 0, tid, Ah, Al, arow0, Bh, Bl, brow0);
#pragma unroll 1
    for (int s = 0; s < 8; ++s) {
        if (s < 7) {
            load_stage(sb, s + 1, tid, Ah, Al, arow0, Bh, Bl, brow0);
            CPWAIT1();
        } else {
            CPWAIT0();
        }
        __syncthreads();
        compute_stage(sb, s, lane, wm, wn, acc);
        __syncthreads();
    }
}

// ------------------- t = x·M GEMM (split store, no bias) ---------------------
__global__ __launch_bounds__(256, 1)
void gemm_t(const bf16* __restrict__ Bh, const bf16* __restrict__ Bl)
{
    extern __shared__ __align__(128) char smem[];
    const uint32_t sb = smem_u32(smem);
    const size_t arow0 = (size_t)blockIdx.x * 128;
    const size_t brow0 = (size_t)blockIdx.y * 128;

    float acc[2][8][4];
    mma_mainloop(sb, g_xh, g_xl, arow0, Bh, Bl, brow0, acc);

    const int tid = threadIdx.x, lane = tid & 31, w = tid >> 5;
    const int wm = w & 3, wn = w >> 2;
#pragma unroll
    for (int mt = 0; mt < 2; ++mt) {
        const int r0 = wm * 32 + mt * 16 + lane / 4;
#pragma unroll
        for (int half = 0; half < 2; ++half) {
            const size_t grow = arow0 + r0 + half * 8;
#pragma unroll
            for (int j = 0; j < 8; ++j) {
                const int col = (int)brow0 + wn * 64 + j * 8 + (lane & 3) * 2;
                const float v0 = acc[mt][j][half * 2 + 0];
                const float v1 = acc[mt][j][half * 2 + 1];
                const bf16 h0 = __float2bfloat16(v0);
                const bf16 h1 = __float2bfloat16(v1);
                __nv_bfloat162 hh; hh.x = h0; hh.y = h1;
                __nv_bfloat162 ll;
                ll.x = __float2bfloat16(v0 - __bfloat162float(h0));
                ll.y = __float2bfloat16(v1 - __bfloat162float(h1));
                *(__nv_bfloat162*)(g_th + grow * C_ + col) = hh;
                *(__nv_bfloat162*)(g_tl + grow * C_ + col) = ll;
            }
        }
    }
}

// -------------- S-pass: s = t·x^T + b_n ; stats + bf16 exp store -------------
__global__ __launch_bounds__(256, 1)
void gemm_s()
{
    extern __shared__ __align__(128) char smem[];
    const uint32_t sb = smem_u32(smem);
    float* red = (float*)(smem + OFF_RED);

    const int it = blockIdx.x, jt = blockIdx.y, bb = blockIdx.z;
    const size_t arow0 = (size_t)bb * N_ + (size_t)it * 128;
    const size_t brow0 = (size_t)bb * N_ + (size_t)jt * 128;

    float acc[2][8][4];
    mma_mainloop(sb, g_th, g_tl, arow0, g_xh, g_xl, brow0, acc);

    const int tid = threadIdx.x, lane = tid & 31, w = tid >> 5;
    const int wm = w & 3, wn = w >> 2;

    // column-bias values for this thread's 16 columns
    const int base_n = bb * N_ + jt * 128;
    float bc[8][2];
#pragma unroll
    for (int j = 0; j < 8; ++j) {
        const int col = wn * 64 + j * 8 + (lane & 3) * 2;
        bc[j][0] = __ldg(g_bcol + base_n + col);
        bc[j][1] = __ldg(g_bcol + base_n + col + 1);
    }

    // ---- row max over tile
    float rmx[4];
#pragma unroll
    for (int slot = 0; slot < 4; ++slot) {
        const int mt = slot >> 1, half = slot & 1;
        float m = -FLT_MAX;
#pragma unroll
        for (int j = 0; j < 8; ++j) {
            m = fmaxf(m, acc[mt][j][half * 2 + 0] + bc[j][0]);
            m = fmaxf(m, acc[mt][j][half * 2 + 1] + bc[j][1]);
        }
        m = fmaxf(m, __shfl_xor_sync(0xffffffffu, m, 1));
        m = fmaxf(m, __shfl_xor_sync(0xffffffffu, m, 2));
        rmx[slot] = m;
    }
    if ((lane & 3) == 0) {
#pragma unroll
        for (int slot = 0; slot < 4; ++slot) {
            const int row = wm * 32 + (slot >> 1) * 16 + (slot & 1) * 8 + lane / 4;
            red[row * 2 + wn] = rmx[slot];
        }
    }
    __syncthreads();
    float rowmax[4];
#pragma unroll
    for (int slot = 0; slot < 4; ++slot) {
        const int row = wm * 32 + (slot >> 1) * 16 + (slot & 1) * 8 + lane / 4;
        rowmax[slot] = fmaxf(red[row * 2], red[row * 2 + 1]);
    }
    __syncthreads();

    // ---- store e = exp(s - rowmax) in bf16, accumulate sumexp
    float rsm[4];
#pragma unroll
    for (int slot = 0; slot < 4; ++slot) {
        const int mt = slot >> 1, half = slot & 1;
        const int row = wm * 32 + mt * 16 + half * 8 + lane / 4;
        bf16* Erow = g_E + ((size_t)bb * N_ + it * 128 + row) * N_ + jt * 128;
        float s = 0.f;
#pragma unroll
        for (int j = 0; j < 8; ++j) {
            const int col = wn * 64 + j * 8 + (lane & 3) * 2;
            const float e0 = __expf(acc[mt][j][half * 2 + 0] + bc[j][0] - rowmax[slot]);
            const float e1 = __expf(acc[mt][j][half * 2 + 1] + bc[j][1] - rowmax[slot]);
            __nv_bfloat162 e2;
            e2.x = __float2bfloat16(e0);
            e2.y = __float2bfloat16(e1);
            *(__nv_bfloat162*)(Erow + col) = e2;
            s += e0 + e1;
        }
        s += __shfl_xor_sync(0xffffffffu, s, 1);
        s += __shfl_xor_sync(0xffffffffu, s, 2);
        rsm[slot] = s;
    }
    if ((lane & 3) == 0) {
#pragma unroll
        for (int slot = 0; slot < 4; ++slot) {
            const int row = wm * 32 + (slot >> 1) * 16 + (slot & 1) * 8 + lane / 4;
            red[row * 2 + wn] = rsm[slot];
        }
    }
    __syncthreads();
    if (wn == 0 && (lane & 3) == 0) {
#pragma unroll
        for (int slot = 0; slot < 4; ++slot) {
            const int row = wm * 32 + (slot >> 1) * 16 + (slot & 1) * 8 + lane / 4;
            const size_t p = ((size_t)bb * 16 + jt) * N_ + it * 128 + row;
            g_pmax[p] = rowmax[slot];
            g_psum[p] = red[row * 2] + red[row * 2 + 1];
        }
    }
}

// ---------- final GEMM: x·P with fused scale/bias/BN/ReLU/residual ----------
__global__ __launch_bounds__(256, 1)
void gemm_out(const bf16* __restrict__ Bh, const bf16* __restrict__ Bl,
              const float* __restrict__ x, float* __restrict__ out)
{
    extern __shared__ __align__(128) char smem[];
    const uint32_t sb = smem_u32(smem);
    const size_t arow0 = (size_t)blockIdx.x * 128;
    const size_t brow0 = (size_t)blockIdx.y * 128;

    float acc[2][8][4];
    mma_mainloop(sb, g_xh, g_xl, arow0, Bh, Bl, brow0, acc);

    const int tid = threadIdx.x, lane = tid & 31, w = tid >> 5;
    const int wm = w & 3, wn = w >> 2;
#pragma unroll
    for (int mt = 0; mt < 2; ++mt) {
#pragma unroll
        for (int half = 0; half < 2; ++half) {
            const size_t grow = arow0 + wm * 32 + mt * 16 + half * 8 + lane / 4;
            const float sc = g_scale[grow];
#pragma unroll
            for (int j = 0; j < 8; ++j) {
                const int col = (int)brow0 + wn * 64 + j * 8 + (lane & 3) * 2;
                const float2 xv = *(const float2*)(x + grow * C_ + col);
                const float z0 = sc * (acc[mt][j][half * 2 + 0] + g_c1[col]);
                const float z1 = sc * (acc[mt][j][half * 2 + 1] + g_c1[col + 1]);
                float y0 = z0 * g_kmul[col] + g_kadd[col];
                float y1 = z1 * g_kmul[col + 1] + g_kadd[col + 1];
                float2 o;
                o.x = fmaxf(y0, 0.f) + xv.x;
                o.y = fmaxf(y1, 0.f) + xv.y;
                *(float2*)(out + grow * C_ + col) = o;
            }
        }
    }
}

// ------------------------------- prep kernels --------------------------------
__global__ __launch_bounds__(512) void xsplit_kernel(const float* __restrict__ x)
{
    const size_t i4 = (size_t)blockIdx.x * 512 + threadIdx.x;
    const float4 v = *(const float4*)(x + i4 * 4);
    const float a[4] = {v.x, v.y, v.z, v.w};
#pragma unroll
    for (int j = 0; j < 4; ++j) {
        bf16 h = __float2bfloat16(a[j]);
        g_xh[i4 * 4 + j] = h;
        g_xl[i4 * 4 + j] = __float2bfloat16(a[j] - __bfloat162float(h));
    }
}

// D[i][l] = sum_j A[i*sa1+j*sa2] * Bm[l*sb1+j*sb2], 512x512 out, split store
__global__ __launch_bounds__(256) void wgemm_kernel(
    const float* __restrict__ A, int sa1, int sa2,
    const float* __restrict__ Bm, int sb1, int sb2,
    bf16* __restrict__ outH, bf16* __restrict__ outL)
{
    __shared__ float As[64][65], Bs[64][65];
    const int i0 = blockIdx.y * 64, l0 = blockIdx.x * 64;
    const int tid = threadIdx.x;
    const int ty = tid >> 4, tx = tid & 15;
    float acc[4][4] = {};
    for (int k0 = 0; k0 < C_; k0 += 64) {
        for (int v = tid; v < 4096; v += 256) {
            const int r = v >> 6, kk = v & 63;
            As[r][kk] = A[(size_t)(i0 + r) * sa1 + (size_t)(k0 + kk) * sa2];
            Bs[r][kk] = Bm[(size_t)(l0 + r) * sb1 + (size_t)(k0 + kk) * sb2];
        }
        __syncthreads();
#pragma unroll 8
        for (int kk = 0; kk < 64; ++kk) {
            float av[4], bv[4];
#pragma unroll
            for (int u = 0; u < 4; ++u) { av[u] = As[ty * 4 + u][kk]; bv[u] = Bs[tx * 4 + u][kk]; }
#pragma unroll
            for (int u = 0; u < 4; ++u)
#pragma unroll
                for (int q = 0; q < 4; ++q) acc[u][q] += av[u] * bv[q];
        }
        __syncthreads();
    }
#pragma unroll
    for (int u = 0; u < 4; ++u)
#pragma unroll
        for (int q = 0; q < 4; ++q) {
            const size_t o = (size_t)(i0 + ty * 4 + u) * C_ + l0 + tx * 4 + q;
            const float v = acc[u][q];
            const bf16 h = __float2bfloat16(v);
            outH[o] = h;
            outL[o] = __float2bfloat16(v - __bfloat162float(h));
        }
}

// outv[i] = sum_c W[i*C+c]*vec[c]   (grid 64 x 256: warp per row)
__global__ void gemv_w_kernel(const float* __restrict__ W, const float* __restrict__ vec,
                              float* __restrict__ outv)
{
    const int row = blockIdx.x * 8 + (threadIdx.x >> 5);
    const int lane = threadIdx.x & 31;
    float s = 0.f;
    for (int c = lane; c < C_; c += 32) s += W[(size_t)row * C_ + c] * vec[c];
#pragma unroll
    for (int off = 16; off > 0; off >>= 1) s += __shfl_xor_sync(0xffffffffu, s, off);
    if (lane == 0) outv[row] = s;
}

// g_bcol[t] = x[t,:]·g_v1   (grid 4096 x 256: warp per row)
__global__ void gemv_x_kernel(const float* __restrict__ x)
{
    __shared__ float v1s[C_];
    for (int c = threadIdx.x; c < C_; c += 256) v1s[c] = g_v1[c];
    __syncthreads();
    const int row = blockIdx.x * 8 + (threadIdx.x >> 5);
    const int lane = threadIdx.x & 31;
    float s = 0.f;
    for (int c = lane; c < C_; c += 32) s += x[(size_t)row * C_ + c] * v1s[c];
#pragma unroll
    for (int off = 16; off > 0; off >>= 1) s += __shfl_xor_sync(0xffffffffu, s, off);
    if (lane == 0) g_bcol[row] = s;
}

// g_c1[c] = sum_j bv[j]*Wo[j*C+c]   (grid 4 x 128)
__global__ void c1_kernel(const float* __restrict__ bv, const float* __restrict__ Wo)
{
    const int c = blockIdx.x * 128 + threadIdx.x;
    float s = 0.f;
    for (int j = 0; j < C_; ++j) s += bv[j] * Wo[(size_t)j * C_ + c];
    g_c1[c] = s;
}

__global__ void bnprep_kernel(const float* __restrict__ bo,
                              const float* __restrict__ bns, const float* __restrict__ bnb,
                              const float* __restrict__ bnm, const float* __restrict__ bnv)
{
    const int c = threadIdx.x;
    const float ka = bns[c] * rsqrtf(bnv[c] + BNEPS_);
    g_kmul[c] = ka;
    g_kadd[c] = (bo[c] - bnm[c]) * ka + bnb[c];
}

// rmax/rinv + per-(tile,m) colsum weights w = exp(pmax - rmax)/rsum
__global__ __launch_bounds__(256) void combine_kernel()
{
    const int t = blockIdx.x * 256 + threadIdx.x;     // b*2048 + m
    const int b = t >> 11, m = t & (N_ - 1);
    float pm[16];
#pragma unroll
    for (int j = 0; j < 16; ++j) pm[j] = g_pmax[((size_t)b * 16 + j) * N_ + m];
    float rmax = -FLT_MAX;
#pragma unroll
    for (int j = 0; j < 16; ++j) rmax = fmaxf(rmax, pm[j]);
    float rsum = 0.f;
#pragma unroll
    for (int j = 0; j < 16; ++j)
        rsum += g_psum[((size_t)b * 16 + j) * N_ + m] * __expf(pm[j] - rmax);
    const float rinv = 1.f / rsum;
#pragma unroll
    for (int j = 0; j < 16; ++j)
        g_w[((size_t)b * 16 + j) * N_ + m] = __expf(pm[j] - rmax) * rinv;
}

// col_n = sum_m E[m][n]*w[tile(n)][m] ; scale = col/(eps+col)
__global__ __launch_bounds__(256) void colsum_kernel()
{
    const int jt = blockIdx.x, b = blockIdx.y;
    const int t = threadIdx.x;
    const int c2 = t & 63;          // column pair within tile
    const int mh = t >> 6;          // 0..3, m-stripe of 512
    const int n0 = jt * 128 + c2 * 2;
    const bf16* Eb = g_E + (size_t)b * N_ * N_;
    const float* wv = g_w + ((size_t)b * 16 + jt) * N_;

    float a0 = 0.f, a1 = 0.f;
#pragma unroll 4
    for (int m = mh * 512; m < mh * 512 + 512; ++m) {
        const float wm = wv[m];
        const __nv_bfloat162 e2 = *(const __nv_bfloat162*)(Eb + (size_t)m * N_ + n0);
        a0 += wm * __bfloat162float(e2.x);
        a1 += wm * __bfloat162float(e2.y);
    }
    __shared__ float red[256][2];
    red[t][0] = a0;
    red[t][1] = a1;
    __syncthreads();
    if (mh == 0) {
        const float c0 = a0 + red[t + 64][0] + red[t + 128][0] + red[t + 192][0];
        const float c1v = a1 + red[t + 64][1] + red[t + 128][1] + red[t + 192][1];
        g_scale[(size_t)b * N_ + n0]     = c0 / (EPS_ + c0);
        g_scale[(size_t)b * N_ + n0 + 1] = c1v / (EPS_ + c1v);
    }
}

// --------------------------------- launch ------------------------------------
extern "C" void kernel_launch(void* const* d_in, const int* in_sizes, int n_in,
                              void* d_out, int out_size)
{
    const float* x   = (const float*)d_in[0];
    const float* Wq  = (const float*)d_in[1];
    const float* bq  = (const float*)d_in[2];
    const float* Wk  = (const float*)d_in[3];
    const float* bk  = (const float*)d_in[4];  // unused: a_m cancels in softmax
    const float* Wv  = (const float*)d_in[5];
    const float* bv  = (const float*)d_in[6];
    const float* Wo  = (const float*)d_in[7];
    const float* bo  = (const float*)d_in[8];
    const float* bns = (const float*)d_in[9];
    const float* bnb = (const float*)d_in[10];
    const float* bnm = (const float*)d_in[11];
    const float* bnv = (const float*)d_in[12];
    float* out = (float*)d_out;
    (void)bk;

    cudaFuncSetAttribute(gemm_t,   cudaFuncAttributeMaxDynamicSharedMemorySize, DYN_SMEM);
    cudaFuncSetAttribute(gemm_s,   cudaFuncAttributeMaxDynamicSharedMemorySize, DYN_SMEM);
    cudaFuncSetAttribute(gemm_out, cudaFuncAttributeMaxDynamicSharedMemorySize, DYN_SMEM);

    bf16 *mth, *mtl, *pth, *ptl;
    float *v1;
    cudaGetSymbolAddress((void**)&mth, g_mth);
    cudaGetSymbolAddress((void**)&mtl, g_mtl);
    cudaGetSymbolAddress((void**)&pth, g_pth);
    cudaGetSymbolAddress((void**)&ptl, g_ptl);
    cudaGetSymbolAddress((void**)&v1,  g_v1);

    // prep
    xsplit_kernel<<<(B_ * N_ * C_) / (512 * 4), 512>>>(x);
    // Mt[c][k] = (Wq Wk^T)[k][c] = sum_j Wk[c,j]*Wq[k,j]
    wgemm_kernel<<<dim3(8, 8), 256>>>(Wk, C_, 1, Wq, C_, 1, mth, mtl);
    // Pt[c][k] = (Wv Wo)[k][c] = sum_j Wo[j,c]*Wv[k,j]
    wgemm_kernel<<<dim3(8, 8), 256>>>(Wo, 1, C_, Wv, C_, 1, pth, ptl);
    // column bias: b_n = x_n · (Wk·bq)   (a_m cancels; const cancels)
    gemv_w_kernel<<<64, 256>>>(Wk, bq, v1);
    gemv_x_kernel<<<4096, 256>>>(x);
    c1_kernel<<<4, 128>>>(bv, Wo);
    bnprep_kernel<<<1, C_>>>(bo, bns, bnb, bnm, bnv);

    // t = x · M (split store)
    gemm_t<<<dim3(256, 4), 256, DYN_SMEM>>>(mth, mtl);

    // S-pass: per-tile softmax stats + bf16 exp store
    gemm_s<<<dim3(16, 16, 16), 256, DYN_SMEM>>>();

    // global stats + column sums -> scale
    combine_kernel<<<(B_ * N_) / 256, 256>>>();
    colsum_kernel<<<dim3(16, B_), 256>>>();

    // out = relu(BN(scale ⊙ (x·P) + c1 + bo)) + x
    gemm_out<<<dim3(256, 4), 256, DYN_SMEM>>>(pth, ptl, x, out);
}

// round 7
// speedup vs baseline: 4.7216x; 1.0298x over previous
#include <cuda_runtime.h>
#include <cuda_bf16.h>
#include <math.h>
#include <float.h>
#include <stdint.h>

#define B_ 16
#define N_ 2048
#define C_ 512
#define EPS_ 1e-9f
#define BNEPS_ 1e-5f

typedef __nv_bfloat16 bf16;

// ------------------------- device scratch ---------------------------------
__device__ bf16 g_xh[B_ * N_ * C_], g_xl[B_ * N_ * C_];
__device__ bf16 g_th[B_ * N_ * C_], g_tl[B_ * N_ * C_];
__device__ bf16 g_mth[C_ * C_], g_mtl[C_ * C_];   // (WqWk^T)^T split
__device__ bf16 g_pth[C_ * C_], g_ptl[C_ * C_];   // (WvWo)^T split
__device__ bf16 g_E[(size_t)B_ * N_ * N_];        // 128 MB: exp(s - rowmax)
__device__ float g_pmax[B_ * 16 * N_], g_psum[B_ * 16 * N_], g_w[B_ * 16 * N_];
__device__ float g_scale[B_ * N_], g_bcol[B_ * N_];
__device__ float g_v1[C_], g_c1k[C_], g_kmul[C_], g_kadd[C_];

// ------------------------------ helpers ------------------------------------
__device__ __forceinline__ uint32_t smem_u32(const void* p) {
    uint32_t a;
    asm("{ .reg .u64 t; cvta.to.shared.u64 t, %1; cvt.u32.u64 %0, t; }" : "=r"(a) : "l"(p));
    return a;
}
#define SWZ(o) ((o) ^ (((o) >> 3) & 0x70))

#define CPASYNC(s, g) asm volatile("cp.async.cg.shared.global [%0], [%1], 16;" :: "r"(s), "l"(g))
#define CPCOMMIT()    asm volatile("cp.async.commit_group;" ::: "memory")
#define CPWAIT1()     asm volatile("cp.async.wait_group 1;" ::: "memory")
#define CPWAIT0()     asm volatile("cp.async.wait_group 0;" ::: "memory")

__device__ __forceinline__ void ldsm4(uint32_t addr, uint32_t& r0, uint32_t& r1,
                                      uint32_t& r2, uint32_t& r3) {
    asm volatile("ldmatrix.sync.aligned.m8n8.x4.shared.b16 {%0,%1,%2,%3}, [%4];"
                 : "=r"(r0), "=r"(r1), "=r"(r2), "=r"(r3) : "r"(addr));
}

__device__ __forceinline__ void mma16816(float* c, uint32_t a0, uint32_t a1,
                                         uint32_t a2, uint32_t a3,
                                         uint32_t b0, uint32_t b1) {
    asm volatile(
        "mma.sync.aligned.m16n8k16.row.col.f32.bf16.bf16.f32 "
        "{%0,%1,%2,%3}, {%4,%5,%6,%7}, {%8,%9}, {%0,%1,%2,%3};"
        : "+f"(c[0]), "+f"(c[1]), "+f"(c[2]), "+f"(c[3])
        : "r"(a0), "r"(a1), "r"(a2), "r"(a3), "r"(b0), "r"(b1));
}

// ----------------------------- smem layout ----------------------------------
#define STAGE_STRIDE 65536
#define OFF_RED 131072
#define DYN_SMEM (131072 + 2048)

// ------------------------- cp.async stage loader (512 thr) -------------------
__device__ __forceinline__ void load_stage(uint32_t sb, int s, int tid,
        const bf16* __restrict__ Ah, const bf16* __restrict__ Al, size_t arow0,
        const bf16* __restrict__ Bh, const bf16* __restrict__ Bl, size_t brow0)
{
    const int k0 = s * 64;
    const uint32_t stb = sb + (uint32_t)(s & 1) * STAGE_STRIDE;
#pragma unroll
    for (int i = 0; i < 2; ++i) {
        const int idx = tid + i * 512;       // 0..1023
        const int row = idx >> 3;            // 0..127
        const int c = idx & 7;               // 16B chunk
        const uint32_t off = SWZ((uint32_t)(row * 128 + c * 16));
        const size_t ga = (arow0 + row) * C_ + k0 + c * 8;
        const size_t gb = (brow0 + row) * C_ + k0 + c * 8;
        CPASYNC(stb + off,         Ah + ga);
        CPASYNC(stb + 16384 + off, Al + ga);
        CPASYNC(stb + 32768 + off, Bh + gb);
        CPASYNC(stb + 49152 + off, Bl + gb);
    }
    CPCOMMIT();
}

// -------------- compute one 64-K stage into acc (warp tile 32x32) ------------
__device__ __forceinline__ void compute_stage(uint32_t sb, int s, int lane,
                                              int wm, int wn, float acc[2][4][4])
{
    const uint32_t stb = sb + (uint32_t)(s & 1) * STAGE_STRIDE;
#pragma unroll
    for (int k16 = 0; k16 < 4; ++k16) {
        uint32_t ah[2][4], al[2][4], bh[2][4], bl[2][4];
        const uint32_t akoff = (uint32_t)(k16 * 32 + (lane >> 4) * 16);
#pragma unroll
        for (int mt = 0; mt < 2; ++mt) {
            const int row = wm * 32 + mt * 16 + (lane & 15);
            const uint32_t a = SWZ((uint32_t)(row * 128) + akoff);
            ldsm4(stb + a,         ah[mt][0], ah[mt][1], ah[mt][2], ah[mt][3]);
            ldsm4(stb + 16384 + a, al[mt][0], al[mt][1], al[mt][2], al[mt][3]);
        }
        const int g = lane >> 3;
        const int nofs = (lane & 7) + (g >> 1) * 8;
        const uint32_t bk = (uint32_t)(k16 * 32 + (g & 1) * 16);
#pragma unroll
        for (int nt4 = 0; nt4 < 2; ++nt4) {
            const int n = wn * 32 + nt4 * 16 + nofs;
            const uint32_t a = SWZ((uint32_t)(n * 128) + bk);
            ldsm4(stb + 32768 + a, bh[nt4][0], bh[nt4][1], bh[nt4][2], bh[nt4][3]);
            ldsm4(stb + 49152 + a, bl[nt4][0], bl[nt4][1], bl[nt4][2], bl[nt4][3]);
        }
#pragma unroll
        for (int mt = 0; mt < 2; ++mt)
#pragma unroll
            for (int j = 0; j < 4; ++j) {
                const int p = j >> 1, hi = (j & 1) * 2;
                mma16816(acc[mt][j], ah[mt][0], ah[mt][1], ah[mt][2], ah[mt][3],
                         bh[p][hi], bh[p][hi + 1]);
            }
#pragma unroll
        for (int mt = 0; mt < 2; ++mt)
#pragma unroll
            for (int j = 0; j < 4; ++j) {
                const int p = j >> 1, hi = (j & 1) * 2;
                mma16816(acc[mt][j], ah[mt][0], ah[mt][1], ah[mt][2], ah[mt][3],
                         bl[p][hi], bl[p][hi + 1]);
            }
#pragma unroll
        for (int mt = 0; mt < 2; ++mt)
#pragma unroll
            for (int j = 0; j < 4; ++j) {
                const int p = j >> 1, hi = (j & 1) * 2;
                mma16816(acc[mt][j], al[mt][0], al[mt][1], al[mt][2], al[mt][3],
                         bh[p][hi], bh[p][hi + 1]);
            }
    }
}

// ------------------- full mainloop: D[128,128] = A·B^T (split) ---------------
__device__ __forceinline__ void mma_mainloop(uint32_t sb,
        const bf16* __restrict__ Ah, const bf16* __restrict__ Al, size_t arow0,
        const bf16* __restrict__ Bh, const bf16* __restrict__ Bl, size_t brow0,
        float acc[2][4][4])
{
    const int tid = threadIdx.x;
    const int lane = tid & 31;
    const int w = tid >> 5;
    const int wm = w & 3, wn = w >> 2;

#pragma unroll
    for (int mt = 0; mt < 2; ++mt)
#pragma unroll
        for (int j = 0; j < 4; ++j)
#pragma unroll
            for (int q = 0; q < 4; ++q) acc[mt][j][q] = 0.f;

    load_stage(sb, 0, tid, Ah, Al, arow0, Bh, Bl, brow0);
#pragma unroll 1
    for (int s = 0; s < 8; ++s) {
        if (s < 7) {
            load_stage(sb, s + 1, tid, Ah, Al, arow0, Bh, Bl, brow0);
            CPWAIT1();
        } else {
            CPWAIT0();
        }
        __syncthreads();
        compute_stage(sb, s, lane, wm, wn, acc);
        __syncthreads();
    }
}

// ------------------- t = x·M GEMM (split store, no bias) ---------------------
__global__ __launch_bounds__(512, 1)
void gemm_t(const bf16* __restrict__ Bh, const bf16* __restrict__ Bl)
{
    extern __shared__ __align__(128) char smem[];
    const uint32_t sb = smem_u32(smem);
    const size_t arow0 = (size_t)blockIdx.x * 128;
    const size_t brow0 = (size_t)blockIdx.y * 128;

    float acc[2][4][4];
    mma_mainloop(sb, g_xh, g_xl, arow0, Bh, Bl, brow0, acc);

    const int tid = threadIdx.x, lane = tid & 31, w = tid >> 5;
    const int wm = w & 3, wn = w >> 2;
#pragma unroll
    for (int mt = 0; mt < 2; ++mt) {
#pragma unroll
        for (int half = 0; half < 2; ++half) {
            const size_t grow = arow0 + wm * 32 + mt * 16 + half * 8 + lane / 4;
#pragma unroll
            for (int j = 0; j < 4; ++j) {
                const int col = (int)brow0 + wn * 32 + j * 8 + (lane & 3) * 2;
                const float v0 = acc[mt][j][half * 2 + 0];
                const float v1 = acc[mt][j][half * 2 + 1];
                const bf16 h0 = __float2bfloat16(v0);
                const bf16 h1 = __float2bfloat16(v1);
                __nv_bfloat162 hh; hh.x = h0; hh.y = h1;
                __nv_bfloat162 ll;
                ll.x = __float2bfloat16(v0 - __bfloat162float(h0));
                ll.y = __float2bfloat16(v1 - __bfloat162float(h1));
                *(__nv_bfloat162*)(g_th + grow * C_ + col) = hh;
                *(__nv_bfloat162*)(g_tl + grow * C_ + col) = ll;
            }
        }
    }
}

// -------------- S-pass: s = t·x^T + b_n ; stats + bf16 exp store -------------
__global__ __launch_bounds__(512, 1)
void gemm_s()
{
    extern __shared__ __align__(128) char smem[];
    const uint32_t sb = smem_u32(smem);
    float* red = (float*)(smem + OFF_RED);

    const int it = blockIdx.x, jt = blockIdx.y, bb = blockIdx.z;
    const size_t arow0 = (size_t)bb * N_ + (size_t)it * 128;
    const size_t brow0 = (size_t)bb * N_ + (size_t)jt * 128;

    float acc[2][4][4];
    mma_mainloop(sb, g_th, g_tl, arow0, g_xh, g_xl, brow0, acc);

    const int tid = threadIdx.x, lane = tid & 31, w = tid >> 5;
    const int wm = w & 3, wn = w >> 2;

    // column-bias values for this thread's 8 columns
    const int base_n = bb * N_ + jt * 128;
    float bc[4][2];
#pragma unroll
    for (int j = 0; j < 4; ++j) {
        const int col = wn * 32 + j * 8 + (lane & 3) * 2;
        bc[j][0] = __ldg(g_bcol + base_n + col);
        bc[j][1] = __ldg(g_bcol + base_n + col + 1);
    }

    // ---- row max over tile
    float rmx[4];
#pragma unroll
    for (int slot = 0; slot < 4; ++slot) {
        const int mt = slot >> 1, half = slot & 1;
        float m = -FLT_MAX;
#pragma unroll
        for (int j = 0; j < 4; ++j) {
            m = fmaxf(m, acc[mt][j][half * 2 + 0] + bc[j][0]);
            m = fmaxf(m, acc[mt][j][half * 2 + 1] + bc[j][1]);
        }
        m = fmaxf(m, __shfl_xor_sync(0xffffffffu, m, 1));
        m = fmaxf(m, __shfl_xor_sync(0xffffffffu, m, 2));
        rmx[slot] = m;
    }
    if ((lane & 3) == 0) {
#pragma unroll
        for (int slot = 0; slot < 4; ++slot) {
            const int row = wm * 32 + (slot >> 1) * 16 + (slot & 1) * 8 + lane / 4;
            red[row * 4 + wn] = rmx[slot];
        }
    }
    __syncthreads();
    float rowmax[4];
#pragma unroll
    for (int slot = 0; slot < 4; ++slot) {
        const int row = wm * 32 + (slot >> 1) * 16 + (slot & 1) * 8 + lane / 4;
        rowmax[slot] = fmaxf(fmaxf(red[row * 4 + 0], red[row * 4 + 1]),
                             fmaxf(red[row * 4 + 2], red[row * 4 + 3]));
    }
    __syncthreads();

    // ---- store e = exp(s - rowmax) in bf16, accumulate sumexp
    float rsm[4];
#pragma unroll
    for (int slot = 0; slot < 4; ++slot) {
        const int mt = slot >> 1, half = slot & 1;
        const int row = wm * 32 + mt * 16 + half * 8 + lane / 4;
        bf16* Erow = g_E + ((size_t)bb * N_ + it * 128 + row) * N_ + jt * 128;
        float s = 0.f;
#pragma unroll
        for (int j = 0; j < 4; ++j) {
            const int col = wn * 32 + j * 8 + (lane & 3) * 2;
            const float e0 = __expf(acc[mt][j][half * 2 + 0] + bc[j][0] - rowmax[slot]);
            const float e1 = __expf(acc[mt][j][half * 2 + 1] + bc[j][1] - rowmax[slot]);
            __nv_bfloat162 e2;
            e2.x = __float2bfloat16(e0);
            e2.y = __float2bfloat16(e1);
            *(__nv_bfloat162*)(Erow + col) = e2;
            s += e0 + e1;
        }
        s += __shfl_xor_sync(0xffffffffu, s, 1);
        s += __shfl_xor_sync(0xffffffffu, s, 2);
        rsm[slot] = s;
    }
    if ((lane & 3) == 0) {
#pragma unroll
        for (int slot = 0; slot < 4; ++slot) {
            const int row = wm * 32 + (slot >> 1) * 16 + (slot & 1) * 8 + lane / 4;
            red[row * 4 + wn] = rsm[slot];
        }
    }
    __syncthreads();
    if (wn == 0 && (lane & 3) == 0) {
#pragma unroll
        for (int slot = 0; slot < 4; ++slot) {
            const int row = wm * 32 + (slot >> 1) * 16 + (slot & 1) * 8 + lane / 4;
            const size_t p = ((size_t)bb * 16 + jt) * N_ + it * 128 + row;
            g_pmax[p] = rowmax[slot];
            g_psum[p] = red[row * 4] + red[row * 4 + 1] + red[row * 4 + 2] + red[row * 4 + 3];
        }
    }
}

// ---------- final GEMM: x·P with fused scale/bias/BN/ReLU/residual ----------
__global__ __launch_bounds__(512, 1)
void gemm_out(const bf16* __restrict__ Bh, const bf16* __restrict__ Bl,
              const float* __restrict__ x, float* __restrict__ out)
{
    extern __shared__ __align__(128) char smem[];
    const uint32_t sb = smem_u32(smem);
    const size_t arow0 = (size_t)blockIdx.x * 128;
    const size_t brow0 = (size_t)blockIdx.y * 128;

    float acc[2][4][4];
    mma_mainloop(sb, g_xh, g_xl, arow0, Bh, Bl, brow0, acc);

    const int tid = threadIdx.x, lane = tid & 31, w = tid >> 5;
    const int wm = w & 3, wn = w >> 2;

    // per-thread column constants (8 columns)
    float km[4][2], kd[4][2], ck[4][2];
#pragma unroll
    for (int j = 0; j < 4; ++j) {
        const int col = (int)brow0 + wn * 32 + j * 8 + (lane & 3) * 2;
        km[j][0] = __ldg(g_kmul + col);     km[j][1] = __ldg(g_kmul + col + 1);
        kd[j][0] = __ldg(g_kadd + col);     kd[j][1] = __ldg(g_kadd + col + 1);
        ck[j][0] = __ldg(g_c1k + col);      ck[j][1] = __ldg(g_c1k + col + 1);
    }

#pragma unroll
    for (int mt = 0; mt < 2; ++mt) {
#pragma unroll
        for (int half = 0; half < 2; ++half) {
            const size_t grow = arow0 + wm * 32 + mt * 16 + half * 8 + lane / 4;
            const float sc = g_scale[grow];
#pragma unroll
            for (int j = 0; j < 4; ++j) {
                const int col = (int)brow0 + wn * 32 + j * 8 + (lane & 3) * 2;
                const float2 xv = *(const float2*)(x + grow * C_ + col);
                float y0 = sc * (acc[mt][j][half * 2 + 0] * km[j][0] + ck[j][0]) + kd[j][0];
                float y1 = sc * (acc[mt][j][half * 2 + 1] * km[j][1] + ck[j][1]) + kd[j][1];
                float2 o;
                o.x = fmaxf(y0, 0.f) + xv.x;
                o.y = fmaxf(y1, 0.f) + xv.y;
                *(float2*)(out + grow * C_ + col) = o;
            }
        }
    }
}

// ------------------------------- prep kernels --------------------------------
__global__ __launch_bounds__(512) void xsplit_kernel(const float* __restrict__ x)
{
    const size_t i4 = (size_t)blockIdx.x * 512 + threadIdx.x;
    const float4 v = *(const float4*)(x + i4 * 4);
    const float a[4] = {v.x, v.y, v.z, v.w};
#pragma unroll
    for (int j = 0; j < 4; ++j) {
        bf16 h = __float2bfloat16(a[j]);
        g_xh[i4 * 4 + j] = h;
        g_xl[i4 * 4 + j] = __float2bfloat16(a[j] - __bfloat162float(h));
    }
}

// D[i][l] = sum_j A[i*sa1+j*sa2] * Bm[l*sb1+j*sb2], 512x512 out, split store
__global__ __launch_bounds__(256) void wgemm_kernel(
    const float* __restrict__ A, int sa1, int sa2,
    const float* __restrict__ Bm, int sb1, int sb2,
    bf16* __restrict__ outH, bf16* __restrict__ outL)
{
    __shared__ float As[64][65], Bs[64][65];
    const int i0 = blockIdx.y * 64, l0 = blockIdx.x * 64;
    const int tid = threadIdx.x;
    const int ty = tid >> 4, tx = tid & 15;
    float acc[4][4] = {};
    for (int k0 = 0; k0 < C_; k0 += 64) {
        for (int v = tid; v < 4096; v += 256) {
            const int r = v >> 6, kk = v & 63;
            As[r][kk] = A[(size_t)(i0 + r) * sa1 + (size_t)(k0 + kk) * sa2];
            Bs[r][kk] = Bm[(size_t)(l0 + r) * sb1 + (size_t)(k0 + kk) * sb2];
        }
        __syncthreads();
#pragma unroll 8
        for (int kk = 0; kk < 64; ++kk) {
            float av[4], bv[4];
#pragma unroll
            for (int u = 0; u < 4; ++u) { av[u] = As[ty * 4 + u][kk]; bv[u] = Bs[tx * 4 + u][kk]; }
#pragma unroll
            for (int u = 0; u < 4; ++u)
#pragma unroll
                for (int q = 0; q < 4; ++q) acc[u][q] += av[u] * bv[q];
        }
        __syncthreads();
    }
#pragma unroll
    for (int u = 0; u < 4; ++u)
#pragma unroll
        for (int q = 0; q < 4; ++q) {
            const size_t o = (size_t)(i0 + ty * 4 + u) * C_ + l0 + tx * 4 + q;
            const float v = acc[u][q];
            const bf16 h = __float2bfloat16(v);
            outH[o] = h;
            outL[o] = __float2bfloat16(v - __bfloat162float(h));
        }
}

// v1[i] = sum_c Wk[i*C+c]*bq[c]   grid 16 x 1024: warp per row, float4
__global__ __launch_bounds__(1024) void gemv_w_kernel(const float* __restrict__ W,
                                                      const float* __restrict__ vec,
                                                      float* __restrict__ outv)
{
    const int row = blockIdx.x * 32 + (threadIdx.x >> 5);
    const int lane = threadIdx.x & 31;
    float s = 0.f;
#pragma unroll
    for (int i = 0; i < 4; ++i) {
        const int c = lane * 4 + i * 128;
        const float4 wv = *(const float4*)(W + (size_t)row * C_ + c);
        const float4 vv = *(const float4*)(vec + c);
        s += wv.x * vv.x + wv.y * vv.y + wv.z * vv.z + wv.w * vv.w;
    }
#pragma unroll
    for (int off = 16; off > 0; off >>= 1) s += __shfl_xor_sync(0xffffffffu, s, off);
    if (lane == 0) outv[row] = s;
}

// g_bcol[t] = x[t,:]·g_v1   grid 4096 x 256: warp per row, float4
__global__ __launch_bounds__(256) void gemv_x_kernel(const float* __restrict__ x)
{
    __shared__ float v1s[C_];
    for (int c = threadIdx.x; c < C_; c += 256) v1s[c] = g_v1[c];
    __syncthreads();
    const int row = blockIdx.x * 8 + (threadIdx.x >> 5);
    const int lane = threadIdx.x & 31;
    float s = 0.f;
#pragma unroll
    for (int i = 0; i < 4; ++i) {
        const int c = lane * 4 + i * 128;
        const float4 xv = *(const float4*)(x + (size_t)row * C_ + c);
        s += xv.x * v1s[c] + xv.y * v1s[c + 1] + xv.z * v1s[c + 2] + xv.w * v1s[c + 3];
    }
#pragma unroll
    for (int off = 16; off > 0; off >>= 1) s += __shfl_xor_sync(0xffffffffu, s, off);
    if (lane == 0) g_bcol[row] = s;
}

// epiprep: c1[c] = sum_j bv[j]*Wo[j,c]; kmul/kadd; c1k = c1*kmul. grid 4 x (128,8)
__global__ void epiprep_kernel(const float* __restrict__ bv, const float* __restrict__ Wo,
                               const float* __restrict__ bo,
                               const float* __restrict__ bns, const float* __restrict__ bnb,
                               const float* __restrict__ bnm, const float* __restrict__ bnv)
{
    __shared__ float part[8][128];
    const int c = blockIdx.x * 128 + threadIdx.x;
    const int jy = threadIdx.y;
    float s = 0.f;
    for (int j = jy * 64; j < jy * 64 + 64; ++j)
        s += bv[j] * Wo[(size_t)j * C_ + c];
    part[jy][threadIdx.x] = s;
    __syncthreads();
    if (jy == 0) {
        float c1 = 0.f;
#pragma unroll
        for (int p = 0; p < 8; ++p) c1 += part[p][threadIdx.x];
        const float ka = bns[c] * rsqrtf(bnv[c] + BNEPS_);
        g_kmul[c] = ka;
        g_kadd[c] = (bo[c] - bnm[c]) * ka + bnb[c];
        g_c1k[c] = c1 * ka;
    }
}

// rmax/rinv + per-(tile,m) colsum weights w = exp(pmax - rmax)/rsum
__global__ __launch_bounds__(256) void combine_kernel()
{
    const int t = blockIdx.x * 256 + threadIdx.x;     // b*2048 + m
    const int b = t >> 11, m = t & (N_ - 1);
    float pm[16];
#pragma unroll
    for (int j = 0; j < 16; ++j) pm[j] = g_pmax[((size_t)b * 16 + j) * N_ + m];
    float rmax = -FLT_MAX;
#pragma unroll
    for (int j = 0; j < 16; ++j) rmax = fmaxf(rmax, pm[j]);
    float rsum = 0.f;
#pragma unroll
    for (int j = 0; j < 16; ++j)
        rsum += g_psum[((size_t)b * 16 + j) * N_ + m] * __expf(pm[j] - rmax);
    const float rinv = 1.f / rsum;
#pragma unroll
    for (int j = 0; j < 16; ++j)
        g_w[((size_t)b * 16 + j) * N_ + m] = __expf(pm[j] - rmax) * rinv;
}

// col_n = sum_m E[m][n]*w[m] ; scale = col/(eps+col).  block: 16 colgrp x 16 stripes
__global__ __launch_bounds__(256) void colsum_kernel()
{
    const int jt = blockIdx.x, b = blockIdx.y;
    const int t = threadIdx.x;
    const int c8 = t & 15;          // 16 groups of 8 cols
    const int mh = t >> 4;          // 16 m-stripes of 128
    const int n0 = jt * 128 + c8 * 8;
    const bf16* Eb = g_E + (size_t)b * N_ * N_;
    const float* wv = g_w + ((size_t)b * 16 + jt) * N_;

    float a[8] = {};
#pragma unroll 4
    for (int m = mh * 128; m < mh * 128 + 128; ++m) {
        const float wm = wv[m];
        const uint4 u = *(const uint4*)(Eb + (size_t)m * N_ + n0);
        const __nv_bfloat162* e2 = (const __nv_bfloat162*)&u;
#pragma unroll
        for (int q = 0; q < 4; ++q) {
            a[q * 2 + 0] += wm * __bfloat162float(e2[q].x);
            a[q * 2 + 1] += wm * __bfloat162float(e2[q].y);
        }
    }
    __shared__ float red[256][8];
#pragma unroll
    for (int q = 0; q < 8; ++q) red[t][q] = a[q];
    __syncthreads();
    if (mh == 0) {
#pragma unroll
        for (int q = 0; q < 8; ++q) {
            float c = a[q];
#pragma unroll 1
            for (int sp = 1; sp < 16; ++sp) c += red[sp * 16 + c8][q];
            g_scale[(size_t)b * N_ + n0 + q] = c / (EPS_ + c);
        }
    }
}

// --------------------------------- launch ------------------------------------
extern "C" void kernel_launch(void* const* d_in, const int* in_sizes, int n_in,
                              void* d_out, int out_size)
{
    const float* x   = (const float*)d_in[0];
    const float* Wq  = (const float*)d_in[1];
    const float* bq  = (const float*)d_in[2];
    const float* Wk  = (const float*)d_in[3];
    const float* bk  = (const float*)d_in[4];  // unused: row bias cancels in softmax
    const float* Wv  = (const float*)d_in[5];
    const float* bv  = (const float*)d_in[6];
    const float* Wo  = (const float*)d_in[7];
    const float* bo  = (const float*)d_in[8];
    const float* bns = (const float*)d_in[9];
    const float* bnb = (const float*)d_in[10];
    const float* bnm = (const float*)d_in[11];
    const float* bnv = (const float*)d_in[12];
    float* out = (float*)d_out;
    (void)bk;

    cudaFuncSetAttribute(gemm_t,   cudaFuncAttributeMaxDynamicSharedMemorySize, DYN_SMEM);
    cudaFuncSetAttribute(gemm_s,   cudaFuncAttributeMaxDynamicSharedMemorySize, DYN_SMEM);
    cudaFuncSetAttribute(gemm_out, cudaFuncAttributeMaxDynamicSharedMemorySize, DYN_SMEM);

    bf16 *mth, *mtl, *pth, *ptl;
    float *v1;
    cudaGetSymbolAddress((void**)&mth, g_mth);
    cudaGetSymbolAddress((void**)&mtl, g_mtl);
    cudaGetSymbolAddress((void**)&pth, g_pth);
    cudaGetSymbolAddress((void**)&ptl, g_ptl);
    cudaGetSymbolAddress((void**)&v1,  g_v1);

    // prep
    xsplit_kernel<<<(B_ * N_ * C_) / (512 * 4), 512>>>(x);
    // Mt[c][k] = (Wq Wk^T)[k][c] = sum_j Wk[c,j]*Wq[k,j]
    wgemm_kernel<<<dim3(8, 8), 256>>>(Wk, C_, 1, Wq, C_, 1, mth, mtl);
    // Pt[c][k] = (Wv Wo)[k][c] = sum_j Wo[j,c]*Wv[k,j]
    wgemm_kernel<<<dim3(8, 8), 256>>>(Wo, 1, C_, Wv, C_, 1, pth, ptl);
    // column bias: b_n = x_n · (Wk·bq)
    gemv_w_kernel<<<16, 1024>>>(Wk, bq, v1);
    gemv_x_kernel<<<4096, 256>>>(x);
    epiprep_kernel<<<4, dim3(128, 8)>>>(bv, Wo, bo, bns, bnb, bnm, bnv);

    // t = x · M (split store)
    gemm_t<<<dim3(256, 4), 512, DYN_SMEM>>>(mth, mtl);

    // S-pass: per-tile softmax stats + bf16 exp store
    gemm_s<<<dim3(16, 16, 16), 512, DYN_SMEM>>>();

    // global stats + column sums -> scale
    combine_kernel<<<(B_ * N_) / 256, 256>>>();
    colsum_kernel<<<dim3(16, B_), 256>>>();

    // out = relu(BN(scale ⊙ (x·P) + c1 + bo)) + x
    gemm_out<<<dim3(256, 4), 512, DYN_SMEM>>>(pth, ptl, x, out);
}

// round 8
// speedup vs baseline: 6.0129x; 1.2735x over previous
#include <cuda_runtime.h>
#include <cuda_fp16.h>
#include <math.h>
#include <float.h>
#include <stdint.h>

#define B_ 16
#define N_ 2048
#define C_ 512
#define EPS_ 1e-9f
#define BNEPS_ 1e-5f

typedef __half h16;

// ------------------------- device scratch ---------------------------------
__device__ h16 g_xh[B_ * N_ * C_], g_xl[B_ * N_ * C_];
__device__ h16 g_th[B_ * N_ * C_], g_tl[B_ * N_ * C_];
__device__ h16 g_mh[C_ * C_];                     // (WqWk^T)^T fp16
__device__ h16 g_ph[C_ * C_];                     // (WvWo)^T fp16
__device__ h16 g_E[(size_t)B_ * N_ * N_];         // 128 MB: exp(s - rowmax), fp16
__device__ float g_pmax[B_ * 16 * N_], g_psum[B_ * 16 * N_], g_w[B_ * 16 * N_];
__device__ float g_scale[B_ * N_], g_bcol[B_ * N_];
__device__ float g_v1[C_], g_c1k[C_], g_kmul[C_], g_kadd[C_];

// ------------------------------ helpers ------------------------------------
__device__ __forceinline__ uint32_t smem_u32(const void* p) {
    uint32_t a;
    asm("{ .reg .u64 t; cvta.to.shared.u64 t, %1; cvt.u32.u64 %0, t; }" : "=r"(a) : "l"(p));
    return a;
}
#define SWZ(o) ((o) ^ (((o) >> 3) & 0x70))

#define CPASYNC(s, g) asm volatile("cp.async.cg.shared.global [%0], [%1], 16;" :: "r"(s), "l"(g))
#define CPCOMMIT()    asm volatile("cp.async.commit_group;" ::: "memory")
#define CPWAIT2()     asm volatile("cp.async.wait_group 2;" ::: "memory")
#define CPWAIT1()     asm volatile("cp.async.wait_group 1;" ::: "memory")
#define CPWAIT0()     asm volatile("cp.async.wait_group 0;" ::: "memory")

__device__ __forceinline__ void ldsm4(uint32_t addr, uint32_t& r0, uint32_t& r1,
                                      uint32_t& r2, uint32_t& r3) {
    asm volatile("ldmatrix.sync.aligned.m8n8.x4.shared.b16 {%0,%1,%2,%3}, [%4];"
                 : "=r"(r0), "=r"(r1), "=r"(r2), "=r"(r3) : "r"(addr));
}

__device__ __forceinline__ void mma16816(float* c, uint32_t a0, uint32_t a1,
                                         uint32_t a2, uint32_t a3,
                                         uint32_t b0, uint32_t b1) {
    asm volatile(
        "mma.sync.aligned.m16n8k16.row.col.f32.f16.f16.f32 "
        "{%0,%1,%2,%3}, {%4,%5,%6,%7}, {%8,%9}, {%0,%1,%2,%3};"
        : "+f"(c[0]), "+f"(c[1]), "+f"(c[2]), "+f"(c[3])
        : "r"(a0), "r"(a1), "r"(a2), "r"(a3), "r"(b0), "r"(b1));
}

// ----------------------------- smem layout ----------------------------------
// per stage: Ah +0, Al +16384, Bh +32768 ; 3 stages of 49152 B
#define STAGE_STRIDE 49152
#define OFF_RED 147456
#define DYN_SMEM (147456 + 2048)

// ------------------------- cp.async stage loader (512 thr) -------------------
__device__ __forceinline__ void load_stage(uint32_t sb, int s, int tid,
        const h16* __restrict__ Ah, const h16* __restrict__ Al, size_t arow0,
        const h16* __restrict__ Bh, size_t brow0)
{
    const int k0 = s * 64;
    const uint32_t stb = sb + (uint32_t)(s % 3) * STAGE_STRIDE;
#pragma unroll
    for (int i = 0; i < 2; ++i) {
        const int idx = tid + i * 512;       // 0..1023
        const int row = idx >> 3;            // 0..127
        const int c = idx & 7;               // 16B chunk
        const uint32_t off = SWZ((uint32_t)(row * 128 + c * 16));
        const size_t ga = (arow0 + row) * C_ + k0 + c * 8;
        const size_t gb = (brow0 + row) * C_ + k0 + c * 8;
        CPASYNC(stb + off,         Ah + ga);
        CPASYNC(stb + 16384 + off, Al + ga);
        CPASYNC(stb + 32768 + off, Bh + gb);
    }
    CPCOMMIT();
}

// -------- compute one 64-K stage into acc (warp tile 32x32, 2-term) ----------
__device__ __forceinline__ void compute_stage(uint32_t sb, int s, int lane,
                                              int wm, int wn, float acc[2][4][4])
{
    const uint32_t stb = sb + (uint32_t)(s % 3) * STAGE_STRIDE;
#pragma unroll
    for (int k16 = 0; k16 < 4; ++k16) {
        uint32_t ah[2][4], al[2][4], bh[2][4];
        const uint32_t akoff = (uint32_t)(k16 * 32 + (lane >> 4) * 16);
#pragma unroll
        for (int mt = 0; mt < 2; ++mt) {
            const int row = wm * 32 + mt * 16 + (lane & 15);
            const uint32_t a = SWZ((uint32_t)(row * 128) + akoff);
            ldsm4(stb + a,         ah[mt][0], ah[mt][1], ah[mt][2], ah[mt][3]);
            ldsm4(stb + 16384 + a, al[mt][0], al[mt][1], al[mt][2], al[mt][3]);
        }
        const int g = lane >> 3;
        const int nofs = (lane & 7) + (g >> 1) * 8;
        const uint32_t bk = (uint32_t)(k16 * 32 + (g & 1) * 16);
#pragma unroll
        for (int nt4 = 0; nt4 < 2; ++nt4) {
            const int n = wn * 32 + nt4 * 16 + nofs;
            const uint32_t a = SWZ((uint32_t)(n * 128) + bk);
            ldsm4(stb + 32768 + a, bh[nt4][0], bh[nt4][1], bh[nt4][2], bh[nt4][3]);
        }
#pragma unroll
        for (int mt = 0; mt < 2; ++mt)
#pragma unroll
            for (int j = 0; j < 4; ++j) {
                const int p = j >> 1, hi = (j & 1) * 2;
                mma16816(acc[mt][j], ah[mt][0], ah[mt][1], ah[mt][2], ah[mt][3],
                         bh[p][hi], bh[p][hi + 1]);
            }
#pragma unroll
        for (int mt = 0; mt < 2; ++mt)
#pragma unroll
            for (int j = 0; j < 4; ++j) {
                const int p = j >> 1, hi = (j & 1) * 2;
                mma16816(acc[mt][j], al[mt][0], al[mt][1], al[mt][2], al[mt][3],
                         bh[p][hi], bh[p][hi + 1]);
            }
    }
}

// ------------- full mainloop: D[128,128] = (Ah+Al)·Bh^T, 3-stage -------------
__device__ __forceinline__ void mma_mainloop(uint32_t sb,
        const h16* __restrict__ Ah, const h16* __restrict__ Al, size_t arow0,
        const h16* __restrict__ Bh, size_t brow0,
        float acc[2][4][4])
{
    const int tid = threadIdx.x;
    const int lane = tid & 31;
    const int w = tid >> 5;
    const int wm = w & 3, wn = w >> 2;

#pragma unroll
    for (int mt = 0; mt < 2; ++mt)
#pragma unroll
        for (int j = 0; j < 4; ++j)
#pragma unroll
            for (int q = 0; q < 4; ++q) acc[mt][j][q] = 0.f;

    load_stage(sb, 0, tid, Ah, Al, arow0, Bh, brow0);
    load_stage(sb, 1, tid, Ah, Al, arow0, Bh, brow0);
#pragma unroll 1
    for (int s = 0; s < 8; ++s) {
        if (s < 6) {
            load_stage(sb, s + 2, tid, Ah, Al, arow0, Bh, brow0);
            CPWAIT2();
        } else if (s == 6) {
            CPWAIT1();
        } else {
            CPWAIT0();
        }
        __syncthreads();
        compute_stage(sb, s, lane, wm, wn, acc);
        __syncthreads();
    }
}

// ------------------- t = x·M GEMM (fp16 split store) -------------------------
__global__ __launch_bounds__(512, 1)
void gemm_t(const h16* __restrict__ Bh)
{
    extern __shared__ __align__(128) char smem[];
    const uint32_t sb = smem_u32(smem);
    const size_t arow0 = (size_t)blockIdx.x * 128;
    const size_t brow0 = (size_t)blockIdx.y * 128;

    float acc[2][4][4];
    mma_mainloop(sb, g_xh, g_xl, arow0, Bh, brow0, acc);

    const int tid = threadIdx.x, lane = tid & 31, w = tid >> 5;
    const int wm = w & 3, wn = w >> 2;
#pragma unroll
    for (int mt = 0; mt < 2; ++mt) {
#pragma unroll
        for (int half = 0; half < 2; ++half) {
            const size_t grow = arow0 + wm * 32 + mt * 16 + half * 8 + lane / 4;
#pragma unroll
            for (int j = 0; j < 4; ++j) {
                const int col = (int)brow0 + wn * 32 + j * 8 + (lane & 3) * 2;
                const float v0 = acc[mt][j][half * 2 + 0];
                const float v1 = acc[mt][j][half * 2 + 1];
                const h16 h0 = __float2half_rn(v0);
                const h16 h1 = __float2half_rn(v1);
                const h16 l0 = __float2half_rn(v0 - __half2float(h0));
                const h16 l1 = __float2half_rn(v1 - __half2float(h1));
                *(__half2*)(g_th + grow * C_ + col) = __halves2half2(h0, h1);
                *(__half2*)(g_tl + grow * C_ + col) = __halves2half2(l0, l1);
            }
        }
    }
}

// -------------- S-pass: s = t·x^T + b_n ; stats + fp16 exp store -------------
__global__ __launch_bounds__(512, 1)
void gemm_s()
{
    extern __shared__ __align__(128) char smem[];
    const uint32_t sb = smem_u32(smem);
    float* red = (float*)(smem + OFF_RED);

    const int it = blockIdx.x, jt = blockIdx.y, bb = blockIdx.z;
    const size_t arow0 = (size_t)bb * N_ + (size_t)it * 128;
    const size_t brow0 = (size_t)bb * N_ + (size_t)jt * 128;

    float acc[2][4][4];
    mma_mainloop(sb, g_th, g_tl, arow0, g_xh, brow0, acc);

    const int tid = threadIdx.x, lane = tid & 31, w = tid >> 5;
    const int wm = w & 3, wn = w >> 2;

    // column-bias values for this thread's 8 columns
    const int base_n = bb * N_ + jt * 128;
    float bc[4][2];
#pragma unroll
    for (int j = 0; j < 4; ++j) {
        const int col = wn * 32 + j * 8 + (lane & 3) * 2;
        bc[j][0] = __ldg(g_bcol + base_n + col);
        bc[j][1] = __ldg(g_bcol + base_n + col + 1);
    }

    // ---- row max over tile
    float rmx[4];
#pragma unroll
    for (int slot = 0; slot < 4; ++slot) {
        const int mt = slot >> 1, half = slot & 1;
        float m = -FLT_MAX;
#pragma unroll
        for (int j = 0; j < 4; ++j) {
            m = fmaxf(m, acc[mt][j][half * 2 + 0] + bc[j][0]);
            m = fmaxf(m, acc[mt][j][half * 2 + 1] + bc[j][1]);
        }
        m = fmaxf(m, __shfl_xor_sync(0xffffffffu, m, 1));
        m = fmaxf(m, __shfl_xor_sync(0xffffffffu, m, 2));
        rmx[slot] = m;
    }
    if ((lane & 3) == 0) {
#pragma unroll
        for (int slot = 0; slot < 4; ++slot) {
            const int row = wm * 32 + (slot >> 1) * 16 + (slot & 1) * 8 + lane / 4;
            red[row * 4 + wn] = rmx[slot];
        }
    }
    __syncthreads();
    float rowmax[4];
#pragma unroll
    for (int slot = 0; slot < 4; ++slot) {
        const int row = wm * 32 + (slot >> 1) * 16 + (slot & 1) * 8 + lane / 4;
        rowmax[slot] = fmaxf(fmaxf(red[row * 4 + 0], red[row * 4 + 1]),
                             fmaxf(red[row * 4 + 2], red[row * 4 + 3]));
    }
    __syncthreads();

    // ---- store e = exp(s - rowmax) in fp16, accumulate sumexp
    float rsm[4];
#pragma unroll
    for (int slot = 0; slot < 4; ++slot) {
        const int mt = slot >> 1, half = slot & 1;
        const int row = wm * 32 + mt * 16 + half * 8 + lane / 4;
        h16* Erow = g_E + ((size_t)bb * N_ + it * 128 + row) * N_ + jt * 128;
        float s = 0.f;
#pragma unroll
        for (int j = 0; j < 4; ++j) {
            const int col = wn * 32 + j * 8 + (lane & 3) * 2;
            const float e0 = __expf(acc[mt][j][half * 2 + 0] + bc[j][0] - rowmax[slot]);
            const float e1 = __expf(acc[mt][j][half * 2 + 1] + bc[j][1] - rowmax[slot]);
            *(__half2*)(Erow + col) = __halves2half2(__float2half_rn(e0), __float2half_rn(e1));
            s += e0 + e1;
        }
        s += __shfl_xor_sync(0xffffffffu, s, 1);
        s += __shfl_xor_sync(0xffffffffu, s, 2);
        rsm[slot] = s;
    }
    if ((lane & 3) == 0) {
#pragma unroll
        for (int slot = 0; slot < 4; ++slot) {
            const int row = wm * 32 + (slot >> 1) * 16 + (slot & 1) * 8 + lane / 4;
            red[row * 4 + wn] = rsm[slot];
        }
    }
    __syncthreads();
    if (wn == 0 && (lane & 3) == 0) {
#pragma unroll
        for (int slot = 0; slot < 4; ++slot) {
            const int row = wm * 32 + (slot >> 1) * 16 + (slot & 1) * 8 + lane / 4;
            const size_t p = ((size_t)bb * 16 + jt) * N_ + it * 128 + row;
            g_pmax[p] = rowmax[slot];
            g_psum[p] = red[row * 4] + red[row * 4 + 1] + red[row * 4 + 2] + red[row * 4 + 3];
        }
    }
}

// ---------- final GEMM: x·P with fused scale/bias/BN/ReLU/residual ----------
__global__ __launch_bounds__(512, 1)
void gemm_out(const h16* __restrict__ Bh,
              const float* __restrict__ x, float* __restrict__ out)
{
    extern __shared__ __align__(128) char smem[];
    const uint32_t sb = smem_u32(smem);
    const size_t arow0 = (size_t)blockIdx.x * 128;
    const size_t brow0 = (size_t)blockIdx.y * 128;

    float acc[2][4][4];
    mma_mainloop(sb, g_xh, g_xl, arow0, Bh, brow0, acc);

    const int tid = threadIdx.x, lane = tid & 31, w = tid >> 5;
    const int wm = w & 3, wn = w >> 2;

    // per-thread column constants (8 columns)
    float km[4][2], kd[4][2], ck[4][2];
#pragma unroll
    for (int j = 0; j < 4; ++j) {
        const int col = (int)brow0 + wn * 32 + j * 8 + (lane & 3) * 2;
        km[j][0] = __ldg(g_kmul + col);     km[j][1] = __ldg(g_kmul + col + 1);
        kd[j][0] = __ldg(g_kadd + col);     kd[j][1] = __ldg(g_kadd + col + 1);
        ck[j][0] = __ldg(g_c1k + col);      ck[j][1] = __ldg(g_c1k + col + 1);
    }

#pragma unroll
    for (int mt = 0; mt < 2; ++mt) {
#pragma unroll
        for (int half = 0; half < 2; ++half) {
            const size_t grow = arow0 + wm * 32 + mt * 16 + half * 8 + lane / 4;
            const float sc = g_scale[grow];
#pragma unroll
            for (int j = 0; j < 4; ++j) {
                const int col = (int)brow0 + wn * 32 + j * 8 + (lane & 3) * 2;
                const float2 xv = *(const float2*)(x + grow * C_ + col);
                float y0 = sc * (acc[mt][j][half * 2 + 0] * km[j][0] + ck[j][0]) + kd[j][0];
                float y1 = sc * (acc[mt][j][half * 2 + 1] * km[j][1] + ck[j][1]) + kd[j][1];
                float2 o;
                o.x = fmaxf(y0, 0.f) + xv.x;
                o.y = fmaxf(y1, 0.f) + xv.y;
                *(float2*)(out + grow * C_ + col) = o;
            }
        }
    }
}

// ------------------------------- prep kernels --------------------------------
__global__ __launch_bounds__(512) void xsplit_kernel(const float* __restrict__ x)
{
    const size_t i4 = (size_t)blockIdx.x * 512 + threadIdx.x;
    const float4 v = *(const float4*)(x + i4 * 4);
    const float a[4] = {v.x, v.y, v.z, v.w};
#pragma unroll
    for (int j = 0; j < 4; ++j) {
        const h16 h = __float2half_rn(a[j]);
        g_xh[i4 * 4 + j] = h;
        g_xl[i4 * 4 + j] = __float2half_rn(a[j] - __half2float(h));
    }
}

// D[i][l] = sum_j A[i*sa1+j*sa2] * Bm[l*sb1+j*sb2], 512x512 out, fp16 store
__global__ __launch_bounds__(256) void wgemm_kernel(
    const float* __restrict__ A, int sa1, int sa2,
    const float* __restrict__ Bm, int sb1, int sb2,
    h16* __restrict__ outH)
{
    __shared__ float As[64][65], Bs[64][65];
    const int i0 = blockIdx.y * 64, l0 = blockIdx.x * 64;
    const int tid = threadIdx.x;
    const int ty = tid >> 4, tx = tid & 15;
    float acc[4][4] = {};
    for (int k0 = 0; k0 < C_; k0 += 64) {
        for (int v = tid; v < 4096; v += 256) {
            const int r = v >> 6, kk = v & 63;
            As[r][kk] = A[(size_t)(i0 + r) * sa1 + (size_t)(k0 + kk) * sa2];
            Bs[r][kk] = Bm[(size_t)(l0 + r) * sb1 + (size_t)(k0 + kk) * sb2];
        }
        __syncthreads();
#pragma unroll 8
        for (int kk = 0; kk < 64; ++kk) {
            float av[4], bv[4];
#pragma unroll
            for (int u = 0; u < 4; ++u) { av[u] = As[ty * 4 + u][kk]; bv[u] = Bs[tx * 4 + u][kk]; }
#pragma unroll
            for (int u = 0; u < 4; ++u)
#pragma unroll
                for (int q = 0; q < 4; ++q) acc[u][q] += av[u] * bv[q];
        }
        __syncthreads();
    }
#pragma unroll
    for (int u = 0; u < 4; ++u)
#pragma unroll
        for (int q = 0; q < 4; ++q) {
            const size_t o = (size_t)(i0 + ty * 4 + u) * C_ + l0 + tx * 4 + q;
            outH[o] = __float2half_rn(acc[u][q]);
        }
}

// v1[i] = sum_c Wk[i*C+c]*bq[c]   grid 16 x 1024: warp per row, float4
__global__ __launch_bounds__(1024) void gemv_w_kernel(const float* __restrict__ W,
                                                      const float* __restrict__ vec,
                                                      float* __restrict__ outv)
{
    const int row = blockIdx.x * 32 + (threadIdx.x >> 5);
    const int lane = threadIdx.x & 31;
    float s = 0.f;
#pragma unroll
    for (int i = 0; i < 4; ++i) {
        const int c = lane * 4 + i * 128;
        const float4 wv = *(const float4*)(W + (size_t)row * C_ + c);
        const float4 vv = *(const float4*)(vec + c);
        s += wv.x * vv.x + wv.y * vv.y + wv.z * vv.z + wv.w * vv.w;
    }
#pragma unroll
    for (int off = 16; off > 0; off >>= 1) s += __shfl_xor_sync(0xffffffffu, s, off);
    if (lane == 0) outv[row] = s;
}

// g_bcol[t] = x[t,:]·g_v1   grid 4096 x 256: warp per row, float4
__global__ __launch_bounds__(256) void gemv_x_kernel(const float* __restrict__ x)
{
    __shared__ float v1s[C_];
    for (int c = threadIdx.x; c < C_; c += 256) v1s[c] = g_v1[c];
    __syncthreads();
    const int row = blockIdx.x * 8 + (threadIdx.x >> 5);
    const int lane = threadIdx.x & 31;
    float s = 0.f;
#pragma unroll
    for (int i = 0; i < 4; ++i) {
        const int c = lane * 4 + i * 128;
        const float4 xv = *(const float4*)(x + (size_t)row * C_ + c);
        s += xv.x * v1s[c] + xv.y * v1s[c + 1] + xv.z * v1s[c + 2] + xv.w * v1s[c + 3];
    }
#pragma unroll
    for (int off = 16; off > 0; off >>= 1) s += __shfl_xor_sync(0xffffffffu, s, off);
    if (lane == 0) g_bcol[row] = s;
}

// epiprep: c1[c] = sum_j bv[j]*Wo[j,c]; kmul/kadd; c1k = c1*kmul. grid 4 x (128,8)
__global__ void epiprep_kernel(const float* __restrict__ bv, const float* __restrict__ Wo,
                               const float* __restrict__ bo,
                               const float* __restrict__ bns, const float* __restrict__ bnb,
                               const float* __restrict__ bnm, const float* __restrict__ bnv)
{
    __shared__ float part[8][128];
    const int c = blockIdx.x * 128 + threadIdx.x;
    const int jy = threadIdx.y;
    float s = 0.f;
    for (int j = jy * 64; j < jy * 64 + 64; ++j)
        s += bv[j] * Wo[(size_t)j * C_ + c];
    part[jy][threadIdx.x] = s;
    __syncthreads();
    if (jy == 0) {
        float c1 = 0.f;
#pragma unroll
        for (int p = 0; p < 8; ++p) c1 += part[p][threadIdx.x];
        const float ka = bns[c] * rsqrtf(bnv[c] + BNEPS_);
        g_kmul[c] = ka;
        g_kadd[c] = (bo[c] - bnm[c]) * ka + bnb[c];
        g_c1k[c] = c1 * ka;
    }
}

// rmax/rinv + per-(tile,m) colsum weights w = exp(pmax - rmax)/rsum
__global__ __launch_bounds__(256) void combine_kernel()
{
    const int t = blockIdx.x * 256 + threadIdx.x;     // b*2048 + m
    const int b = t >> 11, m = t & (N_ - 1);
    float pm[16];
#pragma unroll
    for (int j = 0; j < 16; ++j) pm[j] = g_pmax[((size_t)b * 16 + j) * N_ + m];
    float rmax = -FLT_MAX;
#pragma unroll
    for (int j = 0; j < 16; ++j) rmax = fmaxf(rmax, pm[j]);
    float rsum = 0.f;
#pragma unroll
    for (int j = 0; j < 16; ++j)
        rsum += g_psum[((size_t)b * 16 + j) * N_ + m] * __expf(pm[j] - rmax);
    const float rinv = 1.f / rsum;
#pragma unroll
    for (int j = 0; j < 16; ++j)
        g_w[((size_t)b * 16 + j) * N_ + m] = __expf(pm[j] - rmax) * rinv;
}

// col_n = sum_m E[m][n]*w[m] ; scale = col/(eps+col).  block: 16 colgrp x 16 stripes
__global__ __launch_bounds__(256) void colsum_kernel()
{
    const int jt = blockIdx.x, b = blockIdx.y;
    const int t = threadIdx.x;
    const int c8 = t & 15;          // 16 groups of 8 cols
    const int mh = t >> 4;          // 16 m-stripes of 128
    const int n0 = jt * 128 + c8 * 8;
    const h16* Eb = g_E + (size_t)b * N_ * N_;
    const float* wv = g_w + ((size_t)b * 16 + jt) * N_;

    float a[8] = {};
#pragma unroll 4
    for (int m = mh * 128; m < mh * 128 + 128; ++m) {
        const float wm = wv[m];
        const uint4 u = *(const uint4*)(Eb + (size_t)m * N_ + n0);
        const __half2* e2 = (const __half2*)&u;
#pragma unroll
        for (int q = 0; q < 4; ++q) {
            const float2 f = __half22float2(e2[q]);
            a[q * 2 + 0] += wm * f.x;
            a[q * 2 + 1] += wm * f.y;
        }
    }
    __shared__ float red[256][8];
#pragma unroll
    for (int q = 0; q < 8; ++q) red[t][q] = a[q];
    __syncthreads();
    if (mh == 0) {
#pragma unroll
        for (int q = 0; q < 8; ++q) {
            float c = a[q];
#pragma unroll 1
            for (int sp = 1; sp < 16; ++sp) c += red[sp * 16 + c8][q];
            g_scale[(size_t)b * N_ + n0 + q] = c / (EPS_ + c);
        }
    }
}

// --------------------------------- launch ------------------------------------
extern "C" void kernel_launch(void* const* d_in, const int* in_sizes, int n_in,
                              void* d_out, int out_size)
{
    const float* x   = (const float*)d_in[0];
    const float* Wq  = (const float*)d_in[1];
    const float* bq  = (const float*)d_in[2];
    const float* Wk  = (const float*)d_in[3];
    const float* bk  = (const float*)d_in[4];  // unused: row bias cancels in softmax
    const float* Wv  = (const float*)d_in[5];
    const float* bv  = (const float*)d_in[6];
    const float* Wo  = (const float*)d_in[7];
    const float* bo  = (const float*)d_in[8];
    const float* bns = (const float*)d_in[9];
    const float* bnb = (const float*)d_in[10];
    const float* bnm = (const float*)d_in[11];
    const float* bnv = (const float*)d_in[12];
    float* out = (float*)d_out;
    (void)bk;

    cudaFuncSetAttribute(gemm_t,   cudaFuncAttributeMaxDynamicSharedMemorySize, DYN_SMEM);
    cudaFuncSetAttribute(gemm_s,   cudaFuncAttributeMaxDynamicSharedMemorySize, DYN_SMEM);
    cudaFuncSetAttribute(gemm_out, cudaFuncAttributeMaxDynamicSharedMemorySize, DYN_SMEM);

    h16 *mh, *ph;
    float *v1;
    cudaGetSymbolAddress((void**)&mh, g_mh);
    cudaGetSymbolAddress((void**)&ph, g_ph);
    cudaGetSymbolAddress((void**)&v1, g_v1);

    // prep
    xsplit_kernel<<<(B_ * N_ * C_) / (512 * 4), 512>>>(x);
    // Mt[c][k] = (Wq Wk^T)[k][c] = sum_j Wk[c,j]*Wq[k,j]
    wgemm_kernel<<<dim3(8, 8), 256>>>(Wk, C_, 1, Wq, C_, 1, mh);
    // Pt[c][k] = (Wv Wo)[k][c] = sum_j Wo[j,c]*Wv[k,j]
    wgemm_kernel<<<dim3(8, 8), 256>>>(Wo, 1, C_, Wv, C_, 1, ph);
    // column bias: b_n = x_n · (Wk·bq)
    gemv_w_kernel<<<16, 1024>>>(Wk, bq, v1);
    gemv_x_kernel<<<4096, 256>>>(x);
    epiprep_kernel<<<4, dim3(128, 8)>>>(bv, Wo, bo, bns, bnb, bnm, bnv);

    // t = x · M (fp16 split store)
    gemm_t<<<dim3(256, 4), 512, DYN_SMEM>>>(mh);

    // S-pass: per-tile softmax stats + fp16 exp store
    gemm_s<<<dim3(16, 16, 16), 512, DYN_SMEM>>>();

    // global stats + column sums -> scale
    combine_kernel<<<(B_ * N_) / 256, 256>>>();
    colsum_kernel<<<dim3(16, B_), 256>>>();

    // out = relu(BN(scale ⊙ (x·P) + c1 + bo)) + x
    gemm_out<<<dim3(256, 4), 512, DYN_SMEM>>>(ph, x, out);
}

// round 10
// speedup vs baseline: 6.3911x; 1.0629x over previous
#include <cuda_runtime.h>
#include <cuda_fp16.h>
#include <math.h>
#include <float.h>
#include <stdint.h>

#define B_ 16
#define N_ 2048
#define C_ 512
#define EPS_ 1e-9f
#define BNEPS_ 1e-5f
#define EBIAS_ 10.0f   // fp16-E exponent bias; cancels exactly in col = Σ E·w

typedef __half h16;

// ------------------------- device scratch ---------------------------------
__device__ h16 g_xh[B_ * N_ * C_], g_xl[B_ * N_ * C_];
__device__ h16 g_th[B_ * N_ * C_], g_tl[B_ * N_ * C_];
__device__ h16 g_mh[C_ * C_];                     // (WqWk^T)^T fp16
__device__ h16 g_ph[C_ * C_];                     // (WvWo)^T fp16
__device__ h16 g_E[(size_t)B_ * N_ * N_];         // 128 MB: exp(s - rowmax + EBIAS), fp16
__device__ float g_pmax[B_ * 16 * N_], g_psum[B_ * 16 * N_], g_w[B_ * 16 * N_];
__device__ float g_scale[B_ * N_], g_bcol[B_ * N_];
__device__ float g_v1[C_], g_c1k[C_], g_kmul[C_], g_kadd[C_];

// ------------------------------ helpers ------------------------------------
__device__ __forceinline__ uint32_t smem_u32(const void* p) {
    uint32_t a;
    asm("{ .reg .u64 t; cvta.to.shared.u64 t, %1; cvt.u32.u64 %0, t; }" : "=r"(a) : "l"(p));
    return a;
}
#define SWZ(o) ((o) ^ (((o) >> 3) & 0x70))

#define CPASYNC(s, g) asm volatile("cp.async.cg.shared.global [%0], [%1], 16;" :: "r"(s), "l"(g))
#define CPCOMMIT()    asm volatile("cp.async.commit_group;" ::: "memory")
#define CPWAIT2()     asm volatile("cp.async.wait_group 2;" ::: "memory")
#define CPWAIT1()     asm volatile("cp.async.wait_group 1;" ::: "memory")
#define CPWAIT0()     asm volatile("cp.async.wait_group 0;" ::: "memory")

__device__ __forceinline__ void ldsm4(uint32_t addr, uint32_t& r0, uint32_t& r1,
                                      uint32_t& r2, uint32_t& r3) {
    asm volatile("ldmatrix.sync.aligned.m8n8.x4.shared.b16 {%0,%1,%2,%3}, [%4];"
                 : "=r"(r0), "=r"(r1), "=r"(r2), "=r"(r3) : "r"(addr));
}

__device__ __forceinline__ void mma16816(float* c, uint32_t a0, uint32_t a1,
                                         uint32_t a2, uint32_t a3,
                                         uint32_t b0, uint32_t b1) {
    asm volatile(
        "mma.sync.aligned.m16n8k16.row.col.f32.f16.f16.f32 "
        "{%0,%1,%2,%3}, {%4,%5,%6,%7}, {%8,%9}, {%0,%1,%2,%3};"
        : "+f"(c[0]), "+f"(c[1]), "+f"(c[2]), "+f"(c[3])
        : "r"(a0), "r"(a1), "r"(a2), "r"(a3), "r"(b0), "r"(b1));
}

// ----------------------------- smem layout ----------------------------------
// per stage: Ah +0 (16K), Al +16384 (16K), Bh +32768 (32K: 256 rows) ; 3 stages
#define STAGE_STRIDE 65536
#define OFF_RED 196608
#define DYN_SMEM (196608 + 2048)

// ---------------- cp.async stage loader (512 thr, M=128/N=256) ---------------
__device__ __forceinline__ void load_stage(uint32_t sb, int s, int tid,
        const h16* __restrict__ Ah, const h16* __restrict__ Al, size_t arow0,
        const h16* __restrict__ Bh, size_t brow0)
{
    const int k0 = s * 64;
    const uint32_t stb = sb + (uint32_t)(s % 3) * STAGE_STRIDE;
    const int row = tid >> 3;            // 0..63
    const int c = tid & 7;               // 16B chunk
    const size_t gk = (size_t)(k0 + c * 8);
#pragma unroll
    for (int h = 0; h < 2; ++h) {
        const int r = row + h * 64;      // 0..127
        const uint32_t off = SWZ((uint32_t)(r * 128 + c * 16));
        const size_t ga = (arow0 + r) * C_ + gk;
        CPASYNC(stb + off,         Ah + ga);
        CPASYNC(stb + 16384 + off, Al + ga);
    }
#pragma unroll
    for (int h = 0; h < 4; ++h) {
        const int r = row + h * 64;      // 0..255
        const uint32_t off = SWZ((uint32_t)(r * 128 + c * 16));
        CPASYNC(stb + 32768 + off, Bh + (brow0 + r) * C_ + gk);
    }
    CPCOMMIT();
}

// -------- compute one 64-K stage into acc (warp tile 32x64, 2-term) ----------
__device__ __forceinline__ void compute_stage(uint32_t sb, int s, int lane,
                                              int wm, int wn, float acc[2][8][4])
{
    const uint32_t stb = sb + (uint32_t)(s % 3) * STAGE_STRIDE;
#pragma unroll
    for (int k16 = 0; k16 < 4; ++k16) {
        uint32_t ah[2][4], al[2][4], bh[4][4];
        const uint32_t akoff = (uint32_t)(k16 * 32 + (lane >> 4) * 16);
#pragma unroll
        for (int mt = 0; mt < 2; ++mt) {
            const int row = wm * 32 + mt * 16 + (lane & 15);
            const uint32_t a = SWZ((uint32_t)(row * 128) + akoff);
            ldsm4(stb + a,         ah[mt][0], ah[mt][1], ah[mt][2], ah[mt][3]);
            ldsm4(stb + 16384 + a, al[mt][0], al[mt][1], al[mt][2], al[mt][3]);
        }
        const int g = lane >> 3;
        const int nofs = (lane & 7) + (g >> 1) * 8;
        const uint32_t bk = (uint32_t)(k16 * 32 + (g & 1) * 16);
#pragma unroll
        for (int nt4 = 0; nt4 < 4; ++nt4) {
            const int n = wn * 64 + nt4 * 16 + nofs;
            const uint32_t a = SWZ((uint32_t)(n * 128) + bk);
            ldsm4(stb + 32768 + a, bh[nt4][0], bh[nt4][1], bh[nt4][2], bh[nt4][3]);
        }
#pragma unroll
        for (int mt = 0; mt < 2; ++mt)
#pragma unroll
            for (int j = 0; j < 8; ++j) {
                const int p = j >> 1, hi = (j & 1) * 2;
                mma16816(acc[mt][j], ah[mt][0], ah[mt][1], ah[mt][2], ah[mt][3],
                         bh[p][hi], bh[p][hi + 1]);
            }
#pragma unroll
        for (int mt = 0; mt < 2; ++mt)
#pragma unroll
            for (int j = 0; j < 8; ++j) {
                const int p = j >> 1, hi = (j & 1) * 2;
                mma16816(acc[mt][j], al[mt][0], al[mt][1], al[mt][2], al[mt][3],
                         bh[p][hi], bh[p][hi + 1]);
            }
    }
}

// ------------- full mainloop: D[128,256] = (Ah+Al)·Bh^T, 3-stage -------------
__device__ __forceinline__ void mma_mainloop(uint32_t sb,
        const h16* __restrict__ Ah, const h16* __restrict__ Al, size_t arow0,
        const h16* __restrict__ Bh, size_t brow0,
        float acc[2][8][4])
{
    const int tid = threadIdx.x;
    const int lane = tid & 31;
    const int w = tid >> 5;
    const int wm = w & 3, wn = w >> 2;

#pragma unroll
    for (int mt = 0; mt < 2; ++mt)
#pragma unroll
        for (int j = 0; j < 8; ++j)
#pragma unroll
            for (int q = 0; q < 4; ++q) acc[mt][j][q] = 0.f;

    load_stage(sb, 0, tid, Ah, Al, arow0, Bh, brow0);
    load_stage(sb, 1, tid, Ah, Al, arow0, Bh, brow0);
#pragma unroll 1
    for (int s = 0; s < 8; ++s) {
        if (s < 6) {
            load_stage(sb, s + 2, tid, Ah, Al, arow0, Bh, brow0);
            CPWAIT2();
        } else if (s == 6) {
            CPWAIT1();
        } else {
            CPWAIT0();
        }
        __syncthreads();
        compute_stage(sb, s, lane, wm, wn, acc);
        __syncthreads();
    }
}

// ------------------- t = x·M GEMM (fp16 split store) -------------------------
__global__ __launch_bounds__(512, 1)
void gemm_t(const h16* __restrict__ Bh)
{
    extern __shared__ __align__(128) char smem[];
    const uint32_t sb = smem_u32(smem);
    const size_t arow0 = (size_t)blockIdx.x * 128;
    const size_t brow0 = (size_t)blockIdx.y * 256;

    float acc[2][8][4];
    mma_mainloop(sb, g_xh, g_xl, arow0, Bh, brow0, acc);

    const int tid = threadIdx.x, lane = tid & 31, w = tid >> 5;
    const int wm = w & 3, wn = w >> 2;
#pragma unroll
    for (int mt = 0; mt < 2; ++mt) {
#pragma unroll
        for (int half = 0; half < 2; ++half) {
            const size_t grow = arow0 + wm * 32 + mt * 16 + half * 8 + lane / 4;
#pragma unroll
            for (int j = 0; j < 8; ++j) {
                const int col = (int)brow0 + wn * 64 + j * 8 + (lane & 3) * 2;
                const float v0 = acc[mt][j][half * 2 + 0];
                const float v1 = acc[mt][j][half * 2 + 1];
                const h16 h0 = __float2half_rn(v0);
                const h16 h1 = __float2half_rn(v1);
                const h16 l0 = __float2half_rn(v0 - __half2float(h0));
                const h16 l1 = __float2half_rn(v1 - __half2float(h1));
                *(__half2*)(g_th + grow * C_ + col) = __halves2half2(h0, h1);
                *(__half2*)(g_tl + grow * C_ + col) = __halves2half2(l0, l1);
            }
        }
    }
}

// -------------- S-pass: s = t·x^T + b_n ; stats + biased fp16 exp store ------
__global__ __launch_bounds__(512, 1)
void gemm_s()
{
    extern __shared__ __align__(128) char smem[];
    const uint32_t sb = smem_u32(smem);
    float* red = (float*)(smem + OFF_RED);

    const int it = blockIdx.x, jt = blockIdx.y, bb = blockIdx.z;
    const size_t arow0 = (size_t)bb * N_ + (size_t)it * 128;
    const size_t brow0 = (size_t)bb * N_ + (size_t)jt * 256;

    float acc[2][8][4];
    mma_mainloop(sb, g_th, g_tl, arow0, g_xh, brow0, acc);

    const int tid = threadIdx.x, lane = tid & 31, w = tid >> 5;
    const int wm = w & 3, wn = w >> 2;

    // column-bias values for this thread's 16 columns
    const int base_n = bb * N_ + jt * 256;
    float bc[8][2];
#pragma unroll
    for (int j = 0; j < 8; ++j) {
        const int col = wn * 64 + j * 8 + (lane & 3) * 2;
        bc[j][0] = __ldg(g_bcol + base_n + col);
        bc[j][1] = __ldg(g_bcol + base_n + col + 1);
    }

    // ---- row max over tile (256 cols: 4 wn warps)
    float rmx[4];
#pragma unroll
    for (int slot = 0; slot < 4; ++slot) {
        const int mt = slot >> 1, half = slot & 1;
        float m = -FLT_MAX;
#pragma unroll
        for (int j = 0; j < 8; ++j) {
            m = fmaxf(m, acc[mt][j][half * 2 + 0] + bc[j][0]);
            m = fmaxf(m, acc[mt][j][half * 2 + 1] + bc[j][1]);
        }
        m = fmaxf(m, __shfl_xor_sync(0xffffffffu, m, 1));
        m = fmaxf(m, __shfl_xor_sync(0xffffffffu, m, 2));
        rmx[slot] = m;
    }
    if ((lane & 3) == 0) {
#pragma unroll
        for (int slot = 0; slot < 4; ++slot) {
            const int row = wm * 32 + (slot >> 1) * 16 + (slot & 1) * 8 + lane / 4;
            red[row * 4 + wn] = rmx[slot];
        }
    }
    __syncthreads();
    float rowmax[4];
#pragma unroll
    for (int slot = 0; slot < 4; ++slot) {
        const int row = wm * 32 + (slot >> 1) * 16 + (slot & 1) * 8 + lane / 4;
        rowmax[slot] = fmaxf(fmaxf(red[row * 4 + 0], red[row * 4 + 1]),
                             fmaxf(red[row * 4 + 2], red[row * 4 + 3]));
    }
    __syncthreads();

    // ---- store E = exp(s - rowmax + EBIAS) in fp16; biased sumexp.
    // The e^EBIAS factor appears in every E term AND in psum -> cancels exactly
    // in w = exp(pmax-rmax)/rsum_biased and col = Σ E·w, so col stays the true
    // softmax column sum. Purpose: moves the fp16 flush threshold 10 nats down.
    float rsm[4];
#pragma unroll
    for (int slot = 0; slot < 4; ++slot) {
        const int mt = slot >> 1, half = slot & 1;
        const int row = wm * 32 + mt * 16 + half * 8 + lane / 4;
        h16* Erow = g_E + ((size_t)bb * N_ + it * 128 + row) * N_ + jt * 256;
        float s = 0.f;
#pragma unroll
        for (int j = 0; j < 8; ++j) {
            const int col = wn * 64 + j * 8 + (lane & 3) * 2;
            const float e0 = __expf(acc[mt][j][half * 2 + 0] + bc[j][0] - rowmax[slot] + EBIAS_);
            const float e1 = __expf(acc[mt][j][half * 2 + 1] + bc[j][1] - rowmax[slot] + EBIAS_);
            *(__half2*)(Erow + col) = __halves2half2(__float2half_rn(e0), __float2half_rn(e1));
            s += e0 + e1;
        }
        s += __shfl_xor_sync(0xffffffffu, s, 1);
        s += __shfl_xor_sync(0xffffffffu, s, 2);
        rsm[slot] = s;
    }
    if ((lane & 3) == 0) {
#pragma unroll
        for (int slot = 0; slot < 4; ++slot) {
            const int row = wm * 32 + (slot >> 1) * 16 + (slot & 1) * 8 + lane / 4;
            red[row * 4 + wn] = rsm[slot];
        }
    }
    __syncthreads();
    if (wn == 0 && (lane & 3) == 0) {
#pragma unroll
        for (int slot = 0; slot < 4; ++slot) {
            const int row = wm * 32 + (slot >> 1) * 16 + (slot & 1) * 8 + lane / 4;
            const size_t p = ((size_t)bb * 8 + jt) * N_ + it * 128 + row;
            g_pmax[p] = rowmax[slot];
            g_psum[p] = red[row * 4] + red[row * 4 + 1] + red[row * 4 + 2] + red[row * 4 + 3];
        }
    }
}

// ---------- final GEMM: x·P with fused scale/bias/BN/ReLU/residual ----------
__global__ __launch_bounds__(512, 1)
void gemm_out(const h16* __restrict__ Bh,
              const float* __restrict__ x, float* __restrict__ out)
{
    extern __shared__ __align__(128) char smem[];
    const uint32_t sb = smem_u32(smem);
    const size_t arow0 = (size_t)blockIdx.x * 128;
    const size_t brow0 = (size_t)blockIdx.y * 256;

    float acc[2][8][4];
    mma_mainloop(sb, g_xh, g_xl, arow0, Bh, brow0, acc);

    const int tid = threadIdx.x, lane = tid & 31, w = tid >> 5;
    const int wm = w & 3, wn = w >> 2;

#pragma unroll
    for (int mt = 0; mt < 2; ++mt) {
#pragma unroll
        for (int half = 0; half < 2; ++half) {
            const size_t grow = arow0 + wm * 32 + mt * 16 + half * 8 + lane / 4;
            const float sc = g_scale[grow];
#pragma unroll
            for (int j = 0; j < 8; ++j) {
                const int col = (int)brow0 + wn * 64 + j * 8 + (lane & 3) * 2;
                const float2 xv = *(const float2*)(x + grow * C_ + col);
                const float km0 = __ldg(g_kmul + col), km1 = __ldg(g_kmul + col + 1);
                const float kd0 = __ldg(g_kadd + col), kd1 = __ldg(g_kadd + col + 1);
                const float ck0 = __ldg(g_c1k + col),  ck1 = __ldg(g_c1k + col + 1);
                float y0 = sc * (acc[mt][j][half * 2 + 0] * km0 + ck0) + kd0;
                float y1 = sc * (acc[mt][j][half * 2 + 1] * km1 + ck1) + kd1;
                float2 o;
                o.x = fmaxf(y0, 0.f) + xv.x;
                o.y = fmaxf(y1, 0.f) + xv.y;
                *(float2*)(out + grow * C_ + col) = o;
            }
        }
    }
}

// ------------------------------- prep kernels --------------------------------
__global__ __launch_bounds__(512) void xsplit_kernel(const float* __restrict__ x)
{
    const size_t i4 = (size_t)blockIdx.x * 512 + threadIdx.x;
    const float4 v = *(const float4*)(x + i4 * 4);
    const float a[4] = {v.x, v.y, v.z, v.w};
#pragma unroll
    for (int j = 0; j < 4; ++j) {
        const h16 h = __float2half_rn(a[j]);
        g_xh[i4 * 4 + j] = h;
        g_xl[i4 * 4 + j] = __float2half_rn(a[j] - __half2float(h));
    }
}

// D[i][l] = sum_j A[i*sa1+j*sa2] * Bm[l*sb1+j*sb2], 512x512 out, fp16 store
__global__ __launch_bounds__(256) void wgemm_kernel(
    const float* __restrict__ A, int sa1, int sa2,
    const float* __restrict__ Bm, int sb1, int sb2,
    h16* __restrict__ outH)
{
    __shared__ float As[64][65], Bs[64][65];
    const int i0 = blockIdx.y * 64, l0 = blockIdx.x * 64;
    const int tid = threadIdx.x;
    const int ty = tid >> 4, tx = tid & 15;
    float acc[4][4] = {};
    for (int k0 = 0; k0 < C_; k0 += 64) {
        for (int v = tid; v < 4096; v += 256) {
            const int r = v >> 6, kk = v & 63;
            As[r][kk] = A[(size_t)(i0 + r) * sa1 + (size_t)(k0 + kk) * sa2];
            Bs[r][kk] = Bm[(size_t)(l0 + r) * sb1 + (size_t)(k0 + kk) * sb2];
        }
        __syncthreads();
#pragma unroll 8
        for (int kk = 0; kk < 64; ++kk) {
            float av[4], bv[4];
#pragma unroll
            for (int u = 0; u < 4; ++u) { av[u] = As[ty * 4 + u][kk]; bv[u] = Bs[tx * 4 + u][kk]; }
#pragma unroll
            for (int u = 0; u < 4; ++u)
#pragma unroll
                for (int q = 0; q < 4; ++q) acc[u][q] += av[u] * bv[q];
        }
        __syncthreads();
    }
#pragma unroll
    for (int u = 0; u < 4; ++u)
#pragma unroll
        for (int q = 0; q < 4; ++q) {
            const size_t o = (size_t)(i0 + ty * 4 + u) * C_ + l0 + tx * 4 + q;
            outH[o] = __float2half_rn(acc[u][q]);
        }
}

// v1[i] = sum_c Wk[i*C+c]*bq[c]   grid 16 x 1024: warp per row, float4
__global__ __launch_bounds__(1024) void gemv_w_kernel(const float* __restrict__ W,
                                                      const float* __restrict__ vec,
                                                      float* __restrict__ outv)
{
    const int row = blockIdx.x * 32 + (threadIdx.x >> 5);
    const int lane = threadIdx.x & 31;
    float s = 0.f;
#pragma unroll
    for (int i = 0; i < 4; ++i) {
        const int c = lane * 4 + i * 128;
        const float4 wv = *(const float4*)(W + (size_t)row * C_ + c);
        const float4 vv = *(const float4*)(vec + c);
        s += wv.x * vv.x + wv.y * vv.y + wv.z * vv.z + wv.w * vv.w;
    }
#pragma unroll
    for (int off = 16; off > 0; off >>= 1) s += __shfl_xor_sync(0xffffffffu, s, off);
    if (lane == 0) outv[row] = s;
}

// g_bcol[t] = x[t,:]·g_v1   grid 4096 x 256: warp per row, float4
__global__ __launch_bounds__(256) void gemv_x_kernel(const float* __restrict__ x)
{
    __shared__ float v1s[C_];
    for (int c = threadIdx.x; c < C_; c += 256) v1s[c] = g_v1[c];
    __syncthreads();
    const int row = blockIdx.x * 8 + (threadIdx.x >> 5);
    const int lane = threadIdx.x & 31;
    float s = 0.f;
#pragma unroll
    for (int i = 0; i < 4; ++i) {
        const int c = lane * 4 + i * 128;
        const float4 xv = *(const float4*)(x + (size_t)row * C_ + c);
        s += xv.x * v1s[c] + xv.y * v1s[c + 1] + xv.z * v1s[c + 2] + xv.w * v1s[c + 3];
    }
#pragma unroll
    for (int off = 16; off > 0; off >>= 1) s += __shfl_xor_sync(0xffffffffu, s, off);
    if (lane == 0) g_bcol[row] = s;
}

// epiprep: c1[c] = sum_j bv[j]*Wo[j,c]; kmul/kadd; c1k = c1*kmul. grid 4 x (128,8)
__global__ void epiprep_kernel(const float* __restrict__ bv, const float* __restrict__ Wo,
                               const float* __restrict__ bo,
                               const float* __restrict__ bns, const float* __restrict__ bnb,
                               const float* __restrict__ bnm, const float* __restrict__ bnv)
{
    __shared__ float part[8][128];
    const int c = blockIdx.x * 128 + threadIdx.x;
    const int jy = threadIdx.y;
    float s = 0.f;
    for (int j = jy * 64; j < jy * 64 + 64; ++j)
        s += bv[j] * Wo[(size_t)j * C_ + c];
    part[jy][threadIdx.x] = s;
    __syncthreads();
    if (jy == 0) {
        float c1 = 0.f;
#pragma unroll
        for (int p = 0; p < 8; ++p) c1 += part[p][threadIdx.x];
        const float ka = bns[c] * rsqrtf(bnv[c] + BNEPS_);
        g_kmul[c] = ka;
        g_kadd[c] = (bo[c] - bnm[c]) * ka + bnb[c];
        g_c1k[c] = c1 * ka;
    }
}

// rmax + per-(tile,m) colsum weights w = exp(pmax-rmax)/rsum_biased  (8 tiles)
// (EBIAS cancels: rsum is biased by e^EBIAS and so is every E it divides.)
__global__ __launch_bounds__(256) void combine_kernel()
{
    const int t = blockIdx.x * 256 + threadIdx.x;     // b*2048 + m
    const int b = t >> 11, m = t & (N_ - 1);
    float pm[8];
#pragma unroll
    for (int j = 0; j < 8; ++j) pm[j] = g_pmax[((size_t)b * 8 + j) * N_ + m];
    float rmax = -FLT_MAX;
#pragma unroll
    for (int j = 0; j < 8; ++j) rmax = fmaxf(rmax, pm[j]);
    float rsum = 0.f;
#pragma unroll
    for (int j = 0; j < 8; ++j)
        rsum += g_psum[((size_t)b * 8 + j) * N_ + m] * __expf(pm[j] - rmax);
    const float rinv = 1.f / rsum;
#pragma unroll
    for (int j = 0; j < 8; ++j)
        g_w[((size_t)b * 8 + j) * N_ + m] = __expf(pm[j] - rmax) * rinv;
}

// col_n = sum_m E[m][n]*w[m] ; scale = col/(eps+col).  block: 16 colgrp x 16 stripes
__global__ __launch_bounds__(256) void colsum_kernel()
{
    const int jt = blockIdx.x, b = blockIdx.y;        // jt: 128-col groups (16)
    const int t = threadIdx.x;
    const int c8 = t & 15;          // 16 groups of 8 cols
    const int mh = t >> 4;          // 16 m-stripes of 128
    const int n0 = jt * 128 + c8 * 8;
    const h16* Eb = g_E + (size_t)b * N_ * N_;
    const float* wv = g_w + ((size_t)b * 8 + (jt >> 1)) * N_;   // tile = jt/2 (256-wide)

    float a[8] = {};
#pragma unroll 4
    for (int m = mh * 128; m < mh * 128 + 128; ++m) {
        const float wm = wv[m];
        const uint4 u = *(const uint4*)(Eb + (size_t)m * N_ + n0);
        const __half2* e2 = (const __half2*)&u;
#pragma unroll
        for (int q = 0; q < 4; ++q) {
            const float2 f = __half22float2(e2[q]);
            a[q * 2 + 0] += wm * f.x;
            a[q * 2 + 1] += wm * f.y;
        }
    }
    __shared__ float red[256][8];
#pragma unroll
    for (int q = 0; q < 8; ++q) red[t][q] = a[q];
    __syncthreads();
    if (mh == 0) {
#pragma unroll
        for (int q = 0; q < 8; ++q) {
            float c = a[q];
#pragma unroll 1
            for (int sp = 1; sp < 16; ++sp) c += red[sp * 16 + c8][q];
            g_scale[(size_t)b * N_ + n0 + q] = c / (EPS_ + c);
        }
    }
}

// --------------------------------- launch ------------------------------------
extern "C" void kernel_launch(void* const* d_in, const int* in_sizes, int n_in,
                              void* d_out, int out_size)
{
    const float* x   = (const float*)d_in[0];
    const float* Wq  = (const float*)d_in[1];
    const float* bq  = (const float*)d_in[2];
    const float* Wk  = (const float*)d_in[3];
    const float* bk  = (const float*)d_in[4];  // unused: row bias cancels in softmax
    const float* Wv  = (const float*)d_in[5];
    const float* bv  = (const float*)d_in[6];
    const float* Wo  = (const float*)d_in[7];
    const float* bo  = (const float*)d_in[8];
    const float* bns = (const float*)d_in[9];
    const float* bnb = (const float*)d_in[10];
    const float* bnm = (const float*)d_in[11];
    const float* bnv = (const float*)d_in[12];
    float* out = (float*)d_out;
    (void)bk;

    cudaFuncSetAttribute(gemm_t,   cudaFuncAttributeMaxDynamicSharedMemorySize, DYN_SMEM);
    cudaFuncSetAttribute(gemm_s,   cudaFuncAttributeMaxDynamicSharedMemorySize, DYN_SMEM);
    cudaFuncSetAttribute(gemm_out, cudaFuncAttributeMaxDynamicSharedMemorySize, DYN_SMEM);

    h16 *mh, *ph;
    float *v1;
    cudaGetSymbolAddress((void**)&mh, g_mh);
    cudaGetSymbolAddress((void**)&ph, g_ph);
    cudaGetSymbolAddress((void**)&v1, g_v1);

    // prep
    xsplit_kernel<<<(B_ * N_ * C_) / (512 * 4), 512>>>(x);
    // Mt[c][k] = (Wq Wk^T)[k][c] = sum_j Wk[c,j]*Wq[k,j]
    wgemm_kernel<<<dim3(8, 8), 256>>>(Wk, C_, 1, Wq, C_, 1, mh);
    // Pt[c][k] = (Wv Wo)[k][c] = sum_j Wo[j,c]*Wv[k,j]
    wgemm_kernel<<<dim3(8, 8), 256>>>(Wo, 1, C_, Wv, C_, 1, ph);
    // column bias: b_n = x_n · (Wk·bq)
    gemv_w_kernel<<<16, 1024>>>(Wk, bq, v1);
    gemv_x_kernel<<<4096, 256>>>(x);
    epiprep_kernel<<<4, dim3(128, 8)>>>(bv, Wo, bo, bns, bnb, bnm, bnv);

    // t = x · M (fp16 split store)
    gemm_t<<<dim3(256, 2), 512, DYN_SMEM>>>(mh);

    // S-pass: per-tile softmax stats + biased fp16 exp store
    gemm_s<<<dim3(16, 8, 16), 512, DYN_SMEM>>>();

    // global stats + column sums -> scale
    combine_kernel<<<(B_ * N_) / 256, 256>>>();
    colsum_kernel<<<dim3(16, B_), 256>>>();

    // out = relu(BN(scale ⊙ (x·P) + c1 + bo)) + x
    gemm_out<<<dim3(256, 2), 512, DYN_SMEM>>>(ph, x, out);
}

// round 11
// speedup vs baseline: 7.8076x; 1.2216x over previous
#include <cuda_runtime.h>
#include <cuda_fp16.h>
#include <math.h>
#include <float.h>
#include <stdint.h>

#define B_ 16
#define N_ 2048
#define C_ 512
#define EPS_ 1e-9f
#define BNEPS_ 1e-5f
#define EBIAS_ 10.0f   // fp16-E exponent bias; cancels exactly in col = Σ E·w

typedef __half h16;

// ------------------------- device scratch ---------------------------------
__device__ h16 g_xh[B_ * N_ * C_], g_xl[B_ * N_ * C_];
__device__ h16 g_th[B_ * N_ * C_];                // t = x·M rounded to fp16
__device__ h16 g_mh[C_ * C_];                     // (WqWk^T)^T fp16
__device__ h16 g_ph[C_ * C_];                     // (WvWo)^T fp16
__device__ h16 g_E[(size_t)B_ * N_ * N_];         // 128 MB: exp(s - rowmax + EBIAS), fp16
__device__ float g_pmax[B_ * 16 * N_], g_psum[B_ * 16 * N_], g_w[B_ * 16 * N_];
__device__ float g_scale[B_ * N_], g_bcol[B_ * N_];
__device__ float g_v1[C_], g_c1k[C_], g_kmul[C_], g_kadd[C_];

// ------------------------------ helpers ------------------------------------
__device__ __forceinline__ uint32_t smem_u32(const void* p) {
    uint32_t a;
    asm("{ .reg .u64 t; cvta.to.shared.u64 t, %1; cvt.u32.u64 %0, t; }" : "=r"(a) : "l"(p));
    return a;
}
#define SWZ(o) ((o) ^ (((o) >> 3) & 0x70))

#define CPASYNC(s, g) asm volatile("cp.async.cg.shared.global [%0], [%1], 16;" :: "r"(s), "l"(g))
#define CPCOMMIT()    asm volatile("cp.async.commit_group;" ::: "memory")
#define CPWAIT2()     asm volatile("cp.async.wait_group 2;" ::: "memory")
#define CPWAIT1()     asm volatile("cp.async.wait_group 1;" ::: "memory")
#define CPWAIT0()     asm volatile("cp.async.wait_group 0;" ::: "memory")

__device__ __forceinline__ void ldsm4(uint32_t addr, uint32_t& r0, uint32_t& r1,
                                      uint32_t& r2, uint32_t& r3) {
    asm volatile("ldmatrix.sync.aligned.m8n8.x4.shared.b16 {%0,%1,%2,%3}, [%4];"
                 : "=r"(r0), "=r"(r1), "=r"(r2), "=r"(r3) : "r"(addr));
}

__device__ __forceinline__ void mma16816(float* c, uint32_t a0, uint32_t a1,
                                         uint32_t a2, uint32_t a3,
                                         uint32_t b0, uint32_t b1) {
    asm volatile(
        "mma.sync.aligned.m16n8k16.row.col.f32.f16.f16.f32 "
        "{%0,%1,%2,%3}, {%4,%5,%6,%7}, {%8,%9}, {%0,%1,%2,%3};"
        : "+f"(c[0]), "+f"(c[1]), "+f"(c[2]), "+f"(c[3])
        : "r"(a0), "r"(a1), "r"(a2), "r"(a3), "r"(b0), "r"(b1));
}

// ----------------------------- smem layout ----------------------------------
// per stage: Ah +0 (16K), Al +16384 (16K), Bh +32768 (32K: 256 rows) ; 3 stages
#define STAGE_STRIDE 65536
#define OFF_RED 196608
#define DYN_SMEM (196608 + 2048)

// ---------------- cp.async stage loader (512 thr, M=128/N=256) ---------------
template<bool AL>
__device__ __forceinline__ void load_stage(uint32_t sb, int s, int tid,
        const h16* __restrict__ Ah, const h16* __restrict__ Al, size_t arow0,
        const h16* __restrict__ Bh, size_t brow0)
{
    const int k0 = s * 64;
    const uint32_t stb = sb + (uint32_t)(s % 3) * STAGE_STRIDE;
    const int row = tid >> 3;            // 0..63
    const int c = tid & 7;               // 16B chunk
    const size_t gk = (size_t)(k0 + c * 8);
#pragma unroll
    for (int h = 0; h < 2; ++h) {
        const int r = row + h * 64;      // 0..127
        const uint32_t off = SWZ((uint32_t)(r * 128 + c * 16));
        const size_t ga = (arow0 + r) * C_ + gk;
        CPASYNC(stb + off, Ah + ga);
        if (AL) CPASYNC(stb + 16384 + off, Al + ga);
    }
#pragma unroll
    for (int h = 0; h < 4; ++h) {
        const int r = row + h * 64;      // 0..255
        const uint32_t off = SWZ((uint32_t)(r * 128 + c * 16));
        CPASYNC(stb + 32768 + off, Bh + (brow0 + r) * C_ + gk);
    }
    CPCOMMIT();
}

// -------- compute one 64-K stage into acc (warp tile 32x64) ------------------
template<bool AL>
__device__ __forceinline__ void compute_stage(uint32_t sb, int s, int lane,
                                              int wm, int wn, float acc[2][8][4])
{
    const uint32_t stb = sb + (uint32_t)(s % 3) * STAGE_STRIDE;
#pragma unroll
    for (int k16 = 0; k16 < 4; ++k16) {
        uint32_t ah[2][4], al[2][4], bh[4][4];
        const uint32_t akoff = (uint32_t)(k16 * 32 + (lane >> 4) * 16);
#pragma unroll
        for (int mt = 0; mt < 2; ++mt) {
            const int row = wm * 32 + mt * 16 + (lane & 15);
            const uint32_t a = SWZ((uint32_t)(row * 128) + akoff);
            ldsm4(stb + a, ah[mt][0], ah[mt][1], ah[mt][2], ah[mt][3]);
            if (AL) ldsm4(stb + 16384 + a, al[mt][0], al[mt][1], al[mt][2], al[mt][3]);
        }
        const int g = lane >> 3;
        const int nofs = (lane & 7) + (g >> 1) * 8;
        const uint32_t bk = (uint32_t)(k16 * 32 + (g & 1) * 16);
#pragma unroll
        for (int nt4 = 0; nt4 < 4; ++nt4) {
            const int n = wn * 64 + nt4 * 16 + nofs;
            const uint32_t a = SWZ((uint32_t)(n * 128) + bk);
            ldsm4(stb + 32768 + a, bh[nt4][0], bh[nt4][1], bh[nt4][2], bh[nt4][3]);
        }
#pragma unroll
        for (int mt = 0; mt < 2; ++mt)
#pragma unroll
            for (int j = 0; j < 8; ++j) {
                const int p = j >> 1, hi = (j & 1) * 2;
                mma16816(acc[mt][j], ah[mt][0], ah[mt][1], ah[mt][2], ah[mt][3],
                         bh[p][hi], bh[p][hi + 1]);
            }
        if (AL) {
#pragma unroll
            for (int mt = 0; mt < 2; ++mt)
#pragma unroll
                for (int j = 0; j < 8; ++j) {
                    const int p = j >> 1, hi = (j & 1) * 2;
                    mma16816(acc[mt][j], al[mt][0], al[mt][1], al[mt][2], al[mt][3],
                             bh[p][hi], bh[p][hi + 1]);
                }
        }
    }
}

// ------------- full mainloop: D[128,256], 3-stage pipeline -------------------
template<bool AL>
__device__ __forceinline__ void mma_mainloop(uint32_t sb,
        const h16* __restrict__ Ah, const h16* __restrict__ Al, size_t arow0,
        const h16* __restrict__ Bh, size_t brow0,
        float acc[2][8][4])
{
    const int tid = threadIdx.x;
    const int lane = tid & 31;
    const int w = tid >> 5;
    const int wm = w & 3, wn = w >> 2;

#pragma unroll
    for (int mt = 0; mt < 2; ++mt)
#pragma unroll
        for (int j = 0; j < 8; ++j)
#pragma unroll
            for (int q = 0; q < 4; ++q) acc[mt][j][q] = 0.f;

    load_stage<AL>(sb, 0, tid, Ah, Al, arow0, Bh, brow0);
    load_stage<AL>(sb, 1, tid, Ah, Al, arow0, Bh, brow0);
#pragma unroll 1
    for (int s = 0; s < 8; ++s) {
        if (s < 6) {
            load_stage<AL>(sb, s + 2, tid, Ah, Al, arow0, Bh, brow0);
            CPWAIT2();
        } else if (s == 6) {
            CPWAIT1();
        } else {
            CPWAIT0();
        }
        __syncthreads();
        compute_stage<AL>(sb, s, lane, wm, wn, acc);
        __syncthreads();
    }
}

// ------------------- t = x·M GEMM (plain fp16 store) -------------------------
__global__ __launch_bounds__(512, 1)
void gemm_t(const h16* __restrict__ Bh)
{
    extern __shared__ __align__(128) char smem[];
    const uint32_t sb = smem_u32(smem);
    const size_t arow0 = (size_t)blockIdx.x * 128;
    const size_t brow0 = (size_t)blockIdx.y * 256;

    float acc[2][8][4];
    mma_mainloop<true>(sb, g_xh, g_xl, arow0, Bh, brow0, acc);

    const int tid = threadIdx.x, lane = tid & 31, w = tid >> 5;
    const int wm = w & 3, wn = w >> 2;
#pragma unroll
    for (int mt = 0; mt < 2; ++mt) {
#pragma unroll
        for (int half = 0; half < 2; ++half) {
            const size_t grow = arow0 + wm * 32 + mt * 16 + half * 8 + lane / 4;
#pragma unroll
            for (int j = 0; j < 8; ++j) {
                const int col = (int)brow0 + wn * 64 + j * 8 + (lane & 3) * 2;
                *(__half2*)(g_th + grow * C_ + col) =
                    __halves2half2(__float2half_rn(acc[mt][j][half * 2 + 0]),
                                   __float2half_rn(acc[mt][j][half * 2 + 1]));
            }
        }
    }
}

// -------- S-pass: s = th·xh^T + b_n ; stats + biased fp16 exp store ----------
__global__ __launch_bounds__(512, 1)
void gemm_s()
{
    extern __shared__ __align__(128) char smem[];
    const uint32_t sb = smem_u32(smem);
    float* red = (float*)(smem + OFF_RED);

    const int it = blockIdx.x, jt = blockIdx.y, bb = blockIdx.z;
    const size_t arow0 = (size_t)bb * N_ + (size_t)it * 128;
    const size_t brow0 = (size_t)bb * N_ + (size_t)jt * 256;

    float acc[2][8][4];
    mma_mainloop<false>(sb, g_th, (const h16*)nullptr, arow0, g_xh, brow0, acc);

    const int tid = threadIdx.x, lane = tid & 31, w = tid >> 5;
    const int wm = w & 3, wn = w >> 2;

    // column-bias values for this thread's 16 columns
    const int base_n = bb * N_ + jt * 256;
    float bc[8][2];
#pragma unroll
    for (int j = 0; j < 8; ++j) {
        const int col = wn * 64 + j * 8 + (lane & 3) * 2;
        bc[j][0] = __ldg(g_bcol + base_n + col);
        bc[j][1] = __ldg(g_bcol + base_n + col + 1);
    }

    // ---- row max over tile (256 cols: 4 wn warps)
    float rmx[4];
#pragma unroll
    for (int slot = 0; slot < 4; ++slot) {
        const int mt = slot >> 1, half = slot & 1;
        float m = -FLT_MAX;
#pragma unroll
        for (int j = 0; j < 8; ++j) {
            m = fmaxf(m, acc[mt][j][half * 2 + 0] + bc[j][0]);
            m = fmaxf(m, acc[mt][j][half * 2 + 1] + bc[j][1]);
        }
        m = fmaxf(m, __shfl_xor_sync(0xffffffffu, m, 1));
        m = fmaxf(m, __shfl_xor_sync(0xffffffffu, m, 2));
        rmx[slot] = m;
    }
    if ((lane & 3) == 0) {
#pragma unroll
        for (int slot = 0; slot < 4; ++slot) {
            const int row = wm * 32 + (slot >> 1) * 16 + (slot & 1) * 8 + lane / 4;
            red[row * 4 + wn] = rmx[slot];
        }
    }
    __syncthreads();
    float rowmax[4];
#pragma unroll
    for (int slot = 0; slot < 4; ++slot) {
        const int row = wm * 32 + (slot >> 1) * 16 + (slot & 1) * 8 + lane / 4;
        rowmax[slot] = fmaxf(fmaxf(red[row * 4 + 0], red[row * 4 + 1]),
                             fmaxf(red[row * 4 + 2], red[row * 4 + 3]));
    }
    __syncthreads();

    // ---- store E = exp(s - rowmax + EBIAS) in fp16; biased sumexp.
    // e^EBIAS appears in every E AND in psum -> cancels exactly in
    // w = exp(pmax-rmax)/rsum_biased and col = Σ E·w. It only moves the fp16
    // flush threshold 10 nats further below the tile max.
    float rsm[4];
#pragma unroll
    for (int slot = 0; slot < 4; ++slot) {
        const int mt = slot >> 1, half = slot & 1;
        const int row = wm * 32 + mt * 16 + half * 8 + lane / 4;
        h16* Erow = g_E + ((size_t)bb * N_ + it * 128 + row) * N_ + jt * 256;
        float s = 0.f;
#pragma unroll
        for (int j = 0; j < 8; ++j) {
            const int col = wn * 64 + j * 8 + (lane & 3) * 2;
            const float e0 = __expf(acc[mt][j][half * 2 + 0] + bc[j][0] - rowmax[slot] + EBIAS_);
            const float e1 = __expf(acc[mt][j][half * 2 + 1] + bc[j][1] - rowmax[slot] + EBIAS_);
            *(__half2*)(Erow + col) = __halves2half2(__float2half_rn(e0), __float2half_rn(e1));
            s += e0 + e1;
        }
        s += __shfl_xor_sync(0xffffffffu, s, 1);
        s += __shfl_xor_sync(0xffffffffu, s, 2);
        rsm[slot] = s;
    }
    if ((lane & 3) == 0) {
#pragma unroll
        for (int slot = 0; slot < 4; ++slot) {
            const int row = wm * 32 + (slot >> 1) * 16 + (slot & 1) * 8 + lane / 4;
            red[row * 4 + wn] = rsm[slot];
        }
    }
    __syncthreads();
    if (wn == 0 && (lane & 3) == 0) {
#pragma unroll
        for (int slot = 0; slot < 4; ++slot) {
            const int row = wm * 32 + (slot >> 1) * 16 + (slot & 1) * 8 + lane / 4;
            const size_t p = ((size_t)bb * 8 + jt) * N_ + it * 128 + row;
            g_pmax[p] = rowmax[slot];
            g_psum[p] = red[row * 4] + red[row * 4 + 1] + red[row * 4 + 2] + red[row * 4 + 3];
        }
    }
}

// ---------- final GEMM: x·P with fused scale/bias/BN/ReLU/residual ----------
__global__ __launch_bounds__(512, 1)
void gemm_out(const h16* __restrict__ Bh,
              const float* __restrict__ x, float* __restrict__ out)
{
    extern __shared__ __align__(128) char smem[];
    const uint32_t sb = smem_u32(smem);
    const size_t arow0 = (size_t)blockIdx.x * 128;
    const size_t brow0 = (size_t)blockIdx.y * 256;

    float acc[2][8][4];
    mma_mainloop<true>(sb, g_xh, g_xl, arow0, Bh, brow0, acc);

    const int tid = threadIdx.x, lane = tid & 31, w = tid >> 5;
    const int wm = w & 3, wn = w >> 2;

#pragma unroll
    for (int mt = 0; mt < 2; ++mt) {
#pragma unroll
        for (int half = 0; half < 2; ++half) {
            const size_t grow = arow0 + wm * 32 + mt * 16 + half * 8 + lane / 4;
            const float sc = g_scale[grow];
#pragma unroll
            for (int j = 0; j < 8; ++j) {
                const int col = (int)brow0 + wn * 64 + j * 8 + (lane & 3) * 2;
                const float2 xv = *(const float2*)(x + grow * C_ + col);
                const float km0 = __ldg(g_kmul + col), km1 = __ldg(g_kmul + col + 1);
                const float kd0 = __ldg(g_kadd + col), kd1 = __ldg(g_kadd + col + 1);
                const float ck0 = __ldg(g_c1k + col),  ck1 = __ldg(g_c1k + col + 1);
                float y0 = sc * (acc[mt][j][half * 2 + 0] * km0 + ck0) + kd0;
                float y1 = sc * (acc[mt][j][half * 2 + 1] * km1 + ck1) + kd1;
                float2 o;
                o.x = fmaxf(y0, 0.f) + xv.x;
                o.y = fmaxf(y1, 0.f) + xv.y;
                *(float2*)(out + grow * C_ + col) = o;
            }
        }
    }
}

// ------------------------------- prep kernels --------------------------------
__global__ __launch_bounds__(512) void xsplit_kernel(const float* __restrict__ x)
{
    const size_t i4 = (size_t)blockIdx.x * 512 + threadIdx.x;
    const float4 v = *(const float4*)(x + i4 * 4);
    const float a[4] = {v.x, v.y, v.z, v.w};
#pragma unroll
    for (int j = 0; j < 4; ++j) {
        const h16 h = __float2half_rn(a[j]);
        g_xh[i4 * 4 + j] = h;
        g_xl[i4 * 4 + j] = __float2half_rn(a[j] - __half2float(h));
    }
}

// D[i][l] = sum_j A[i*sa1+j*sa2] * Bm[l*sb1+j*sb2], 512x512 out, fp16 store
__global__ __launch_bounds__(256) void wgemm_kernel(
    const float* __restrict__ A, int sa1, int sa2,
    const float* __restrict__ Bm, int sb1, int sb2,
    h16* __restrict__ outH)
{
    __shared__ float As[64][65], Bs[64][65];
    const int i0 = blockIdx.y * 64, l0 = blockIdx.x * 64;
    const int tid = threadIdx.x;
    const int ty = tid >> 4, tx = tid & 15;
    float acc[4][4] = {};
    for (int k0 = 0; k0 < C_; k0 += 64) {
        for (int v = tid; v < 4096; v += 256) {
            const int r = v >> 6, kk = v & 63;
            As[r][kk] = A[(size_t)(i0 + r) * sa1 + (size_t)(k0 + kk) * sa2];
            Bs[r][kk] = Bm[(size_t)(l0 + r) * sb1 + (size_t)(k0 + kk) * sb2];
        }
        __syncthreads();
#pragma unroll 8
        for (int kk = 0; kk < 64; ++kk) {
            float av[4], bv[4];
#pragma unroll
            for (int u = 0; u < 4; ++u) { av[u] = As[ty * 4 + u][kk]; bv[u] = Bs[tx * 4 + u][kk]; }
#pragma unroll
            for (int u = 0; u < 4; ++u)
#pragma unroll
                for (int q = 0; q < 4; ++q) acc[u][q] += av[u] * bv[q];
        }
        __syncthreads();
    }
#pragma unroll
    for (int u = 0; u < 4; ++u)
#pragma unroll
        for (int q = 0; q < 4; ++q) {
            const size_t o = (size_t)(i0 + ty * 4 + u) * C_ + l0 + tx * 4 + q;
            outH[o] = __float2half_rn(acc[u][q]);
        }
}

// v1[i] = sum_c Wk[i*C+c]*bq[c]   grid 16 x 1024: warp per row, float4
__global__ __launch_bounds__(1024) void gemv_w_kernel(const float* __restrict__ W,
                                                      const float* __restrict__ vec,
                                                      float* __restrict__ outv)
{
    const int row = blockIdx.x * 32 + (threadIdx.x >> 5);
    const int lane = threadIdx.x & 31;
    float s = 0.f;
#pragma unroll
    for (int i = 0; i < 4; ++i) {
        const int c = lane * 4 + i * 128;
        const float4 wv = *(const float4*)(W + (size_t)row * C_ + c);
        const float4 vv = *(const float4*)(vec + c);
        s += wv.x * vv.x + wv.y * vv.y + wv.z * vv.z + wv.w * vv.w;
    }
#pragma unroll
    for (int off = 16; off > 0; off >>= 1) s += __shfl_xor_sync(0xffffffffu, s, off);
    if (lane == 0) outv[row] = s;
}

// g_bcol[t] = x[t,:]·g_v1   grid 4096 x 256: warp per row, float4
__global__ __launch_bounds__(256) void gemv_x_kernel(const float* __restrict__ x)
{
    __shared__ float v1s[C_];
    for (int c = threadIdx.x; c < C_; c += 256) v1s[c] = g_v1[c];
    __syncthreads();
    const int row = blockIdx.x * 8 + (threadIdx.x >> 5);
    const int lane = threadIdx.x & 31;
    float s = 0.f;
#pragma unroll
    for (int i = 0; i < 4; ++i) {
        const int c = lane * 4 + i * 128;
        const float4 xv = *(const float4*)(x + (size_t)row * C_ + c);
        s += xv.x * v1s[c] + xv.y * v1s[c + 1] + xv.z * v1s[c + 2] + xv.w * v1s[c + 3];
    }
#pragma unroll
    for (int off = 16; off > 0; off >>= 1) s += __shfl_xor_sync(0xffffffffu, s, off);
    if (lane == 0) g_bcol[row] = s;
}

// epiprep: c1[c] = sum_j bv[j]*Wo[j,c]; kmul/kadd; c1k = c1*kmul. grid 4 x (128,8)
__global__ void epiprep_kernel(const float* __restrict__ bv, const float* __restrict__ Wo,
                               const float* __restrict__ bo,
                               const float* __restrict__ bns, const float* __restrict__ bnb,
                               const float* __restrict__ bnm, const float* __restrict__ bnv)
{
    __shared__ float part[8][128];
    const int c = blockIdx.x * 128 + threadIdx.x;
    const int jy = threadIdx.y;
    float s = 0.f;
    for (int j = jy * 64; j < jy * 64 + 64; ++j)
        s += bv[j] * Wo[(size_t)j * C_ + c];
    part[jy][threadIdx.x] = s;
    __syncthreads();
    if (jy == 0) {
        float c1 = 0.f;
#pragma unroll
        for (int p = 0; p < 8; ++p) c1 += part[p][threadIdx.x];
        const float ka = bns[c] * rsqrtf(bnv[c] + BNEPS_);
        g_kmul[c] = ka;
        g_kadd[c] = (bo[c] - bnm[c]) * ka + bnb[c];
        g_c1k[c] = c1 * ka;
    }
}

// rmax + per-(tile,m) colsum weights w = exp(pmax-rmax)/rsum_biased  (8 tiles)
__global__ __launch_bounds__(256) void combine_kernel()
{
    const int t = blockIdx.x * 256 + threadIdx.x;     // b*2048 + m
    const int b = t >> 11, m = t & (N_ - 1);
    float pm[8];
#pragma unroll
    for (int j = 0; j < 8; ++j) pm[j] = g_pmax[((size_t)b * 8 + j) * N_ + m];
    float rmax = -FLT_MAX;
#pragma unroll
    for (int j = 0; j < 8; ++j) rmax = fmaxf(rmax, pm[j]);
    float rsum = 0.f;
#pragma unroll
    for (int j = 0; j < 8; ++j)
        rsum += g_psum[((size_t)b * 8 + j) * N_ + m] * __expf(pm[j] - rmax);
    const float rinv = 1.f / rsum;
#pragma unroll
    for (int j = 0; j < 8; ++j)
        g_w[((size_t)b * 8 + j) * N_ + m] = __expf(pm[j] - rmax) * rinv;
}

// col_n = sum_m E[m][n]*w[m] ; scale = col/(eps+col).  block: 16 colgrp x 16 stripes
__global__ __launch_bounds__(256) void colsum_kernel()
{
    const int jt = blockIdx.x, b = blockIdx.y;        // jt: 128-col groups (16)
    const int t = threadIdx.x;
    const int c8 = t & 15;          // 16 groups of 8 cols
    const int mh = t >> 4;          // 16 m-stripes of 128
    const int n0 = jt * 128 + c8 * 8;
    const h16* Eb = g_E + (size_t)b * N_ * N_;
    const float* wv = g_w + ((size_t)b * 8 + (jt >> 1)) * N_;   // tile = jt/2 (256-wide)

    float a[8] = {};
#pragma unroll 4
    for (int m = mh * 128; m < mh * 128 + 128; ++m) {
        const float wm = wv[m];
        const uint4 u = *(const uint4*)(Eb + (size_t)m * N_ + n0);
        const __half2* e2 = (const __half2*)&u;
#pragma unroll
        for (int q = 0; q < 4; ++q) {
            const float2 f = __half22float2(e2[q]);
            a[q * 2 + 0] += wm * f.x;
            a[q * 2 + 1] += wm * f.y;
        }
    }
    __shared__ float red[256][8];
#pragma unroll
    for (int q = 0; q < 8; ++q) red[t][q] = a[q];
    __syncthreads();
    if (mh == 0) {
#pragma unroll
        for (int q = 0; q < 8; ++q) {
            float c = a[q];
#pragma unroll 1
            for (int sp = 1; sp < 16; ++sp) c += red[sp * 16 + c8][q];
            g_scale[(size_t)b * N_ + n0 + q] = c / (EPS_ + c);
        }
    }
}

// --------------------------------- launch ------------------------------------
extern "C" void kernel_launch(void* const* d_in, const int* in_sizes, int n_in,
                              void* d_out, int out_size)
{
    const float* x   = (const float*)d_in[0];
    const float* Wq  = (const float*)d_in[1];
    const float* bq  = (const float*)d_in[2];
    const float* Wk  = (const float*)d_in[3];
    const float* bk  = (const float*)d_in[4];  // unused: row bias cancels in softmax
    const float* Wv  = (const float*)d_in[5];
    const float* bv  = (const float*)d_in[6];
    const float* Wo  = (const float*)d_in[7];
    const float* bo  = (const float*)d_in[8];
    const float* bns = (const float*)d_in[9];
    const float* bnb = (const float*)d_in[10];
    const float* bnm = (const float*)d_in[11];
    const float* bnv = (const float*)d_in[12];
    float* out = (float*)d_out;
    (void)bk;

    cudaFuncSetAttribute(gemm_t,   cudaFuncAttributeMaxDynamicSharedMemorySize, DYN_SMEM);
    cudaFuncSetAttribute(gemm_s,   cudaFuncAttributeMaxDynamicSharedMemorySize, DYN_SMEM);
    cudaFuncSetAttribute(gemm_out, cudaFuncAttributeMaxDynamicSharedMemorySize, DYN_SMEM);

    h16 *mh, *ph;
    float *v1;
    cudaGetSymbolAddress((void**)&mh, g_mh);
    cudaGetSymbolAddress((void**)&ph, g_ph);
    cudaGetSymbolAddress((void**)&v1, g_v1);

    // prep
    xsplit_kernel<<<(B_ * N_ * C_) / (512 * 4), 512>>>(x);
    // Mt[c][k] = (Wq Wk^T)[k][c] = sum_j Wk[c,j]*Wq[k,j]
    wgemm_kernel<<<dim3(8, 8), 256>>>(Wk, C_, 1, Wq, C_, 1, mh);
    // Pt[c][k] = (Wv Wo)[k][c] = sum_j Wo[j,c]*Wv[k,j]
    wgemm_kernel<<<dim3(8, 8), 256>>>(Wo, 1, C_, Wv, C_, 1, ph);
    // column bias: b_n = x_n · (Wk·bq)
    gemv_w_kernel<<<16, 1024>>>(Wk, bq, v1);
    gemv_x_kernel<<<4096, 256>>>(x);
    epiprep_kernel<<<4, dim3(128, 8)>>>(bv, Wo, bo, bns, bnb, bnm, bnv);

    // t = x · M (fp16 store, 2-term A split)
    gemm_t<<<dim3(256, 2), 512, DYN_SMEM>>>(mh);

    // S-pass: single-term th·xh + per-tile softmax stats + biased fp16 exp store
    gemm_s<<<dim3(16, 8, 16), 512, DYN_SMEM>>>();

    // global stats + column sums -> scale
    combine_kernel<<<(B_ * N_) / 256, 256>>>();
    colsum_kernel<<<dim3(16, B_), 256>>>();

    // out = relu(BN(scale ⊙ (x·P) + c1 + bo)) + x
    gemm_out<<<dim3(256, 2), 512, DYN_SMEM>>>(ph, x, out);
}

// round 12
// speedup vs baseline: 9.3191x; 1.1936x over previous
#include <cuda_runtime.h>
#include <cuda_fp16.h>
#include <math.h>
#include <float.h>
#include <stdint.h>

#define B_ 16
#define N_ 2048
#define C_ 512
#define EPS_ 1e-9f
#define BNEPS_ 1e-5f
#define EBIAS_ 10.0f   // fp16-E exponent bias; cancels exactly in col = Σ E·w

typedef __half h16;

// ------------------------- device scratch ---------------------------------
__device__ h16 g_xh[B_ * N_ * C_];                // x rounded to fp16
__device__ h16 g_th[B_ * N_ * C_];                // t = x·M rounded to fp16
__device__ h16 g_mh[C_ * C_];                     // (WqWk^T)^T fp16
__device__ h16 g_ph[C_ * C_];                     // (WvWo)^T fp16
__device__ h16 g_E[(size_t)B_ * N_ * N_];         // 128 MB: exp(s - rowmax + EBIAS), fp16
__device__ float g_pmax[B_ * 16 * N_], g_psum[B_ * 16 * N_], g_w[B_ * 16 * N_];
__device__ float g_scale[B_ * N_], g_bcol[B_ * N_];
__device__ float g_v1[C_], g_c1k[C_], g_kmul[C_], g_kadd[C_];

// ------------------------------ helpers ------------------------------------
__device__ __forceinline__ uint32_t smem_u32(const void* p) {
    uint32_t a;
    asm("{ .reg .u64 t; cvta.to.shared.u64 t, %1; cvt.u32.u64 %0, t; }" : "=r"(a) : "l"(p));
    return a;
}
#define SWZ(o) ((o) ^ (((o) >> 3) & 0x70))

#define CPASYNC(s, g) asm volatile("cp.async.cg.shared.global [%0], [%1], 16;" :: "r"(s), "l"(g))
#define CPCOMMIT()    asm volatile("cp.async.commit_group;" ::: "memory")
#define CPWAIT2()     asm volatile("cp.async.wait_group 2;" ::: "memory")
#define CPWAIT1()     asm volatile("cp.async.wait_group 1;" ::: "memory")
#define CPWAIT0()     asm volatile("cp.async.wait_group 0;" ::: "memory")

__device__ __forceinline__ void ldsm4(uint32_t addr, uint32_t& r0, uint32_t& r1,
                                      uint32_t& r2, uint32_t& r3) {
    asm volatile("ldmatrix.sync.aligned.m8n8.x4.shared.b16 {%0,%1,%2,%3}, [%4];"
                 : "=r"(r0), "=r"(r1), "=r"(r2), "=r"(r3) : "r"(addr));
}

__device__ __forceinline__ void mma16816(float* c, uint32_t a0, uint32_t a1,
                                         uint32_t a2, uint32_t a3,
                                         uint32_t b0, uint32_t b1) {
    asm volatile(
        "mma.sync.aligned.m16n8k16.row.col.f32.f16.f16.f32 "
        "{%0,%1,%2,%3}, {%4,%5,%6,%7}, {%8,%9}, {%0,%1,%2,%3};"
        : "+f"(c[0]), "+f"(c[1]), "+f"(c[2]), "+f"(c[3])
        : "r"(a0), "r"(a1), "r"(a2), "r"(a3), "r"(b0), "r"(b1));
}

// ----------------------------- smem layout ----------------------------------
// per stage: A +0 (16K), B +16384 (32K: 256 rows) ; 3 stages of 48K
#define STAGE_STRIDE 49152
#define OFF_RED 147456
#define DYN_SMEM (147456 + 2048)

// ---------------- cp.async stage loader (512 thr, M=128/N=256) ---------------
__device__ __forceinline__ void load_stage(uint32_t sb, int s, int tid,
        const h16* __restrict__ A, size_t arow0,
        const h16* __restrict__ Bh, size_t brow0)
{
    const int k0 = s * 64;
    const uint32_t stb = sb + (uint32_t)(s % 3) * STAGE_STRIDE;
    const int row = tid >> 3;            // 0..63
    const int c = tid & 7;               // 16B chunk
    const size_t gk = (size_t)(k0 + c * 8);
#pragma unroll
    for (int h = 0; h < 2; ++h) {
        const int r = row + h * 64;      // 0..127
        const uint32_t off = SWZ((uint32_t)(r * 128 + c * 16));
        CPASYNC(stb + off, A + (arow0 + r) * C_ + gk);
    }
#pragma unroll
    for (int h = 0; h < 4; ++h) {
        const int r = row + h * 64;      // 0..255
        const uint32_t off = SWZ((uint32_t)(r * 128 + c * 16));
        CPASYNC(stb + 16384 + off, Bh + (brow0 + r) * C_ + gk);
    }
    CPCOMMIT();
}

// -------- compute one 64-K stage into acc (warp tile 32x64, 1-term) ----------
__device__ __forceinline__ void compute_stage(uint32_t sb, int s, int lane,
                                              int wm, int wn, float acc[2][8][4])
{
    const uint32_t stb = sb + (uint32_t)(s % 3) * STAGE_STRIDE;
#pragma unroll
    for (int k16 = 0; k16 < 4; ++k16) {
        uint32_t ah[2][4], bh[4][4];
        const uint32_t akoff = (uint32_t)(k16 * 32 + (lane >> 4) * 16);
#pragma unroll
        for (int mt = 0; mt < 2; ++mt) {
            const int row = wm * 32 + mt * 16 + (lane & 15);
            const uint32_t a = SWZ((uint32_t)(row * 128) + akoff);
            ldsm4(stb + a, ah[mt][0], ah[mt][1], ah[mt][2], ah[mt][3]);
        }
        const int g = lane >> 3;
        const int nofs = (lane & 7) + (g >> 1) * 8;
        const uint32_t bk = (uint32_t)(k16 * 32 + (g & 1) * 16);
#pragma unroll
        for (int nt4 = 0; nt4 < 4; ++nt4) {
            const int n = wn * 64 + nt4 * 16 + nofs;
            const uint32_t a = SWZ((uint32_t)(n * 128) + bk);
            ldsm4(stb + 16384 + a, bh[nt4][0], bh[nt4][1], bh[nt4][2], bh[nt4][3]);
        }
#pragma unroll
        for (int mt = 0; mt < 2; ++mt)
#pragma unroll
            for (int j = 0; j < 8; ++j) {
                const int p = j >> 1, hi = (j & 1) * 2;
                mma16816(acc[mt][j], ah[mt][0], ah[mt][1], ah[mt][2], ah[mt][3],
                         bh[p][hi], bh[p][hi + 1]);
            }
    }
}

// ------------- full mainloop: D[128,256] = A·B^T, 3-stage --------------------
__device__ __forceinline__ void mma_mainloop(uint32_t sb,
        const h16* __restrict__ A, size_t arow0,
        const h16* __restrict__ Bh, size_t brow0,
        float acc[2][8][4])
{
    const int tid = threadIdx.x;
    const int lane = tid & 31;
    const int w = tid >> 5;
    const int wm = w & 3, wn = w >> 2;

#pragma unroll
    for (int mt = 0; mt < 2; ++mt)
#pragma unroll
        for (int j = 0; j < 8; ++j)
#pragma unroll
            for (int q = 0; q < 4; ++q) acc[mt][j][q] = 0.f;

    load_stage(sb, 0, tid, A, arow0, Bh, brow0);
    load_stage(sb, 1, tid, A, arow0, Bh, brow0);
#pragma unroll 1
    for (int s = 0; s < 8; ++s) {
        if (s < 6) {
            load_stage(sb, s + 2, tid, A, arow0, Bh, brow0);
            CPWAIT2();
        } else if (s == 6) {
            CPWAIT1();
        } else {
            CPWAIT0();
        }
        __syncthreads();
        compute_stage(sb, s, lane, wm, wn, acc);
        __syncthreads();
    }
}

// ------------------- t = x·M GEMM (fp16 store) -------------------------------
__global__ __launch_bounds__(512, 1)
void gemm_t(const h16* __restrict__ Bh)
{
    extern __shared__ __align__(128) char smem[];
    const uint32_t sb = smem_u32(smem);
    const size_t arow0 = (size_t)blockIdx.x * 128;
    const size_t brow0 = (size_t)blockIdx.y * 256;

    float acc[2][8][4];
    mma_mainloop(sb, g_xh, arow0, Bh, brow0, acc);

    const int tid = threadIdx.x, lane = tid & 31, w = tid >> 5;
    const int wm = w & 3, wn = w >> 2;
#pragma unroll
    for (int mt = 0; mt < 2; ++mt) {
#pragma unroll
        for (int half = 0; half < 2; ++half) {
            const size_t grow = arow0 + wm * 32 + mt * 16 + half * 8 + lane / 4;
#pragma unroll
            for (int j = 0; j < 8; ++j) {
                const int col = (int)brow0 + wn * 64 + j * 8 + (lane & 3) * 2;
                *(__half2*)(g_th + grow * C_ + col) =
                    __halves2half2(__float2half_rn(acc[mt][j][half * 2 + 0]),
                                   __float2half_rn(acc[mt][j][half * 2 + 1]));
            }
        }
    }
}

// -------- S-pass: s = th·xh^T + b_n ; stats + biased fp16 exp store ----------
__global__ __launch_bounds__(512, 1)
void gemm_s()
{
    extern __shared__ __align__(128) char smem[];
    const uint32_t sb = smem_u32(smem);
    float* red = (float*)(smem + OFF_RED);

    const int it = blockIdx.x, jt = blockIdx.y, bb = blockIdx.z;
    const size_t arow0 = (size_t)bb * N_ + (size_t)it * 128;
    const size_t brow0 = (size_t)bb * N_ + (size_t)jt * 256;

    float acc[2][8][4];
    mma_mainloop(sb, g_th, arow0, g_xh, brow0, acc);

    const int tid = threadIdx.x, lane = tid & 31, w = tid >> 5;
    const int wm = w & 3, wn = w >> 2;

    // column-bias values for this thread's 16 columns
    const int base_n = bb * N_ + jt * 256;
    float bc[8][2];
#pragma unroll
    for (int j = 0; j < 8; ++j) {
        const int col = wn * 64 + j * 8 + (lane & 3) * 2;
        bc[j][0] = __ldg(g_bcol + base_n + col);
        bc[j][1] = __ldg(g_bcol + base_n + col + 1);
    }

    // ---- row max over tile (256 cols: 4 wn warps)
    float rmx[4];
#pragma unroll
    for (int slot = 0; slot < 4; ++slot) {
        const int mt = slot >> 1, half = slot & 1;
        float m = -FLT_MAX;
#pragma unroll
        for (int j = 0; j < 8; ++j) {
            m = fmaxf(m, acc[mt][j][half * 2 + 0] + bc[j][0]);
            m = fmaxf(m, acc[mt][j][half * 2 + 1] + bc[j][1]);
        }
        m = fmaxf(m, __shfl_xor_sync(0xffffffffu, m, 1));
        m = fmaxf(m, __shfl_xor_sync(0xffffffffu, m, 2));
        rmx[slot] = m;
    }
    if ((lane & 3) == 0) {
#pragma unroll
        for (int slot = 0; slot < 4; ++slot) {
            const int row = wm * 32 + (slot >> 1) * 16 + (slot & 1) * 8 + lane / 4;
            red[row * 4 + wn] = rmx[slot];
        }
    }
    __syncthreads();
    float rowmax[4];
#pragma unroll
    for (int slot = 0; slot < 4; ++slot) {
        const int row = wm * 32 + (slot >> 1) * 16 + (slot & 1) * 8 + lane / 4;
        rowmax[slot] = fmaxf(fmaxf(red[row * 4 + 0], red[row * 4 + 1]),
                             fmaxf(red[row * 4 + 2], red[row * 4 + 3]));
    }
    __syncthreads();

    // ---- store E = exp(s - rowmax + EBIAS) in fp16; biased sumexp.
    // e^EBIAS appears in every E AND in psum -> cancels exactly in
    // w = exp(pmax-rmax)/rsum_biased and col = Σ E·w. It only moves the fp16
    // flush threshold 10 nats further below the tile max.
    float rsm[4];
#pragma unroll
    for (int slot = 0; slot < 4; ++slot) {
        const int mt = slot >> 1, half = slot & 1;
        const int row = wm * 32 + mt * 16 + half * 8 + lane / 4;
        h16* Erow = g_E + ((size_t)bb * N_ + it * 128 + row) * N_ + jt * 256;
        float s = 0.f;
#pragma unroll
        for (int j = 0; j < 8; ++j) {
            const int col = wn * 64 + j * 8 + (lane & 3) * 2;
            const float e0 = __expf(acc[mt][j][half * 2 + 0] + bc[j][0] - rowmax[slot] + EBIAS_);
            const float e1 = __expf(acc[mt][j][half * 2 + 1] + bc[j][1] - rowmax[slot] + EBIAS_);
            *(__half2*)(Erow + col) = __halves2half2(__float2half_rn(e0), __float2half_rn(e1));
            s += e0 + e1;
        }
        s += __shfl_xor_sync(0xffffffffu, s, 1);
        s += __shfl_xor_sync(0xffffffffu, s, 2);
        rsm[slot] = s;
    }
    if ((lane & 3) == 0) {
#pragma unroll
        for (int slot = 0; slot < 4; ++slot) {
            const int row = wm * 32 + (slot >> 1) * 16 + (slot & 1) * 8 + lane / 4;
            red[row * 4 + wn] = rsm[slot];
        }
    }
    __syncthreads();
    if (wn == 0 && (lane & 3) == 0) {
#pragma unroll
        for (int slot = 0; slot < 4; ++slot) {
            const int row = wm * 32 + (slot >> 1) * 16 + (slot & 1) * 8 + lane / 4;
            const size_t p = ((size_t)bb * 8 + jt) * N_ + it * 128 + row;
            g_pmax[p] = rowmax[slot];
            g_psum[p] = red[row * 4] + red[row * 4 + 1] + red[row * 4 + 2] + red[row * 4 + 3];
        }
    }
}

// ---------- final GEMM: x·P with fused scale/bias/BN/ReLU/residual ----------
__global__ __launch_bounds__(512, 1)
void gemm_out(const h16* __restrict__ Bh,
              const float* __restrict__ x, float* __restrict__ out)
{
    extern __shared__ __align__(128) char smem[];
    const uint32_t sb = smem_u32(smem);
    const size_t arow0 = (size_t)blockIdx.x * 128;
    const size_t brow0 = (size_t)blockIdx.y * 256;

    float acc[2][8][4];
    mma_mainloop(sb, g_xh, arow0, Bh, brow0, acc);

    const int tid = threadIdx.x, lane = tid & 31, w = tid >> 5;
    const int wm = w & 3, wn = w >> 2;

#pragma unroll
    for (int mt = 0; mt < 2; ++mt) {
#pragma unroll
        for (int half = 0; half < 2; ++half) {
            const size_t grow = arow0 + wm * 32 + mt * 16 + half * 8 + lane / 4;
            const float sc = g_scale[grow];
#pragma unroll
            for (int j = 0; j < 8; ++j) {
                const int col = (int)brow0 + wn * 64 + j * 8 + (lane & 3) * 2;
                const float2 xv = *(const float2*)(x + grow * C_ + col);
                const float km0 = __ldg(g_kmul + col), km1 = __ldg(g_kmul + col + 1);
                const float kd0 = __ldg(g_kadd + col), kd1 = __ldg(g_kadd + col + 1);
                const float ck0 = __ldg(g_c1k + col),  ck1 = __ldg(g_c1k + col + 1);
                float y0 = sc * (acc[mt][j][half * 2 + 0] * km0 + ck0) + kd0;
                float y1 = sc * (acc[mt][j][half * 2 + 1] * km1 + ck1) + kd1;
                float2 o;
                o.x = fmaxf(y0, 0.f) + xv.x;
                o.y = fmaxf(y1, 0.f) + xv.y;
                *(float2*)(out + grow * C_ + col) = o;
            }
        }
    }
}

// ------------------------------- prep kernels --------------------------------
__global__ __launch_bounds__(512) void xconv_kernel(const float* __restrict__ x)
{
    const size_t i4 = (size_t)blockIdx.x * 512 + threadIdx.x;
    const float4 v = *(const float4*)(x + i4 * 4);
    __half2 a, b;
    a = __halves2half2(__float2half_rn(v.x), __float2half_rn(v.y));
    b = __halves2half2(__float2half_rn(v.z), __float2half_rn(v.w));
    *(__half2*)(g_xh + i4 * 4)     = a;
    *(__half2*)(g_xh + i4 * 4 + 2) = b;
}

// D[i][l] = sum_j A[i*sa1+j*sa2] * Bm[l*sb1+j*sb2], 512x512 out, fp16 store
__global__ __launch_bounds__(256) void wgemm_kernel(
    const float* __restrict__ A, int sa1, int sa2,
    const float* __restrict__ Bm, int sb1, int sb2,
    h16* __restrict__ outH)
{
    __shared__ float As[64][65], Bs[64][65];
    const int i0 = blockIdx.y * 64, l0 = blockIdx.x * 64;
    const int tid = threadIdx.x;
    const int ty = tid >> 4, tx = tid & 15;
    float acc[4][4] = {};
    for (int k0 = 0; k0 < C_; k0 += 64) {
        for (int v = tid; v < 4096; v += 256) {
            const int r = v >> 6, kk = v & 63;
            As[r][kk] = A[(size_t)(i0 + r) * sa1 + (size_t)(k0 + kk) * sa2];
            Bs[r][kk] = Bm[(size_t)(l0 + r) * sb1 + (size_t)(k0 + kk) * sb2];
        }
        __syncthreads();
#pragma unroll 8
        for (int kk = 0; kk < 64; ++kk) {
            float av[4], bv[4];
#pragma unroll
            for (int u = 0; u < 4; ++u) { av[u] = As[ty * 4 + u][kk]; bv[u] = Bs[tx * 4 + u][kk]; }
#pragma unroll
            for (int u = 0; u < 4; ++u)
#pragma unroll
                for (int q = 0; q < 4; ++q) acc[u][q] += av[u] * bv[q];
        }
        __syncthreads();
    }
#pragma unroll
    for (int u = 0; u < 4; ++u)
#pragma unroll
        for (int q = 0; q < 4; ++q) {
            const size_t o = (size_t)(i0 + ty * 4 + u) * C_ + l0 + tx * 4 + q;
            outH[o] = __float2half_rn(acc[u][q]);
        }
}

// v1[i] = sum_c Wk[i*C+c]*bq[c]   grid 16 x 1024: warp per row, float4
__global__ __launch_bounds__(1024) void gemv_w_kernel(const float* __restrict__ W,
                                                      const float* __restrict__ vec,
                                                      float* __restrict__ outv)
{
    const int row = blockIdx.x * 32 + (threadIdx.x >> 5);
    const int lane = threadIdx.x & 31;
    float s = 0.f;
#pragma unroll
    for (int i = 0; i < 4; ++i) {
        const int c = lane * 4 + i * 128;
        const float4 wv = *(const float4*)(W + (size_t)row * C_ + c);
        const float4 vv = *(const float4*)(vec + c);
        s += wv.x * vv.x + wv.y * vv.y + wv.z * vv.z + wv.w * vv.w;
    }
#pragma unroll
    for (int off = 16; off > 0; off >>= 1) s += __shfl_xor_sync(0xffffffffu, s, off);
    if (lane == 0) outv[row] = s;
}

// g_bcol[t] = x[t,:]·g_v1   grid 4096 x 256: warp per row, float4
__global__ __launch_bounds__(256) void gemv_x_kernel(const float* __restrict__ x)
{
    __shared__ float v1s[C_];
    for (int c = threadIdx.x; c < C_; c += 256) v1s[c] = g_v1[c];
    __syncthreads();
    const int row = blockIdx.x * 8 + (threadIdx.x >> 5);
    const int lane = threadIdx.x & 31;
    float s = 0.f;
#pragma unroll
    for (int i = 0; i < 4; ++i) {
        const int c = lane * 4 + i * 128;
        const float4 xv = *(const float4*)(x + (size_t)row * C_ + c);
        s += xv.x * v1s[c] + xv.y * v1s[c + 1] + xv.z * v1s[c + 2] + xv.w * v1s[c + 3];
    }
#pragma unroll
    for (int off = 16; off > 0; off >>= 1) s += __shfl_xor_sync(0xffffffffu, s, off);
    if (lane == 0) g_bcol[row] = s;
}

// epiprep: c1[c] = sum_j bv[j]*Wo[j,c]; kmul/kadd; c1k = c1*kmul. grid 4 x (128,8)
__global__ void epiprep_kernel(const float* __restrict__ bv, const float* __restrict__ Wo,
                               const float* __restrict__ bo,
                               const float* __restrict__ bns, const float* __restrict__ bnb,
                               const float* __restrict__ bnm, const float* __restrict__ bnv)
{
    __shared__ float part[8][128];
    const int c = blockIdx.x * 128 + threadIdx.x;
    const int jy = threadIdx.y;
    float s = 0.f;
    for (int j = jy * 64; j < jy * 64 + 64; ++j)
        s += bv[j] * Wo[(size_t)j * C_ + c];
    part[jy][threadIdx.x] = s;
    __syncthreads();
    if (jy == 0) {
        float c1 = 0.f;
#pragma unroll
        for (int p = 0; p < 8; ++p) c1 += part[p][threadIdx.x];
        const float ka = bns[c] * rsqrtf(bnv[c] + BNEPS_);
        g_kmul[c] = ka;
        g_kadd[c] = (bo[c] - bnm[c]) * ka + bnb[c];
        g_c1k[c] = c1 * ka;
    }
}

// rmax + per-(tile,m) colsum weights w = exp(pmax-rmax)/rsum_biased  (8 tiles)
__global__ __launch_bounds__(256) void combine_kernel()
{
    const int t = blockIdx.x * 256 + threadIdx.x;     // b*2048 + m
    const int b = t >> 11, m = t & (N_ - 1);
    float pm[8];
#pragma unroll
    for (int j = 0; j < 8; ++j) pm[j] = g_pmax[((size_t)b * 8 + j) * N_ + m];
    float rmax = -FLT_MAX;
#pragma unroll
    for (int j = 0; j < 8; ++j) rmax = fmaxf(rmax, pm[j]);
    float rsum = 0.f;
#pragma unroll
    for (int j = 0; j < 8; ++j)
        rsum += g_psum[((size_t)b * 8 + j) * N_ + m] * __expf(pm[j] - rmax);
    const float rinv = 1.f / rsum;
#pragma unroll
    for (int j = 0; j < 8; ++j)
        g_w[((size_t)b * 8 + j) * N_ + m] = __expf(pm[j] - rmax) * rinv;
}

// col_n = sum_m E[m][n]*w[m] ; scale = col/(eps+col).  block: 16 colgrp x 16 stripes
__global__ __launch_bounds__(256) void colsum_kernel()
{
    const int jt = blockIdx.x, b = blockIdx.y;        // jt: 128-col groups (16)
    const int t = threadIdx.x;
    const int c8 = t & 15;          // 16 groups of 8 cols
    const int mh = t >> 4;          // 16 m-stripes of 128
    const int n0 = jt * 128 + c8 * 8;
    const h16* Eb = g_E + (size_t)b * N_ * N_;
    const float* wv = g_w + ((size_t)b * 8 + (jt >> 1)) * N_;   // tile = jt/2 (256-wide)

    float a[8] = {};
#pragma unroll 4
    for (int m = mh * 128; m < mh * 128 + 128; ++m) {
        const float wm = wv[m];
        const uint4 u = *(const uint4*)(Eb + (size_t)m * N_ + n0);
        const __half2* e2 = (const __half2*)&u;
#pragma unroll
        for (int q = 0; q < 4; ++q) {
            const float2 f = __half22float2(e2[q]);
            a[q * 2 + 0] += wm * f.x;
            a[q * 2 + 1] += wm * f.y;
        }
    }
    __shared__ float red[256][8];
#pragma unroll
    for (int q = 0; q < 8; ++q) red[t][q] = a[q];
    __syncthreads();
    if (mh == 0) {
#pragma unroll
        for (int q = 0; q < 8; ++q) {
            float c = a[q];
#pragma unroll 1
            for (int sp = 1; sp < 16; ++sp) c += red[sp * 16 + c8][q];
            g_scale[(size_t)b * N_ + n0 + q] = c / (EPS_ + c);
        }
    }
}

// --------------------------------- launch ------------------------------------
extern "C" void kernel_launch(void* const* d_in, const int* in_sizes, int n_in,
                              void* d_out, int out_size)
{
    const float* x   = (const float*)d_in[0];
    const float* Wq  = (const float*)d_in[1];
    const float* bq  = (const float*)d_in[2];
    const float* Wk  = (const float*)d_in[3];
    const float* bk  = (const float*)d_in[4];  // unused: row bias cancels in softmax
    const float* Wv  = (const float*)d_in[5];
    const float* bv  = (const float*)d_in[6];
    const float* Wo  = (const float*)d_in[7];
    const float* bo  = (const float*)d_in[8];
    const float* bns = (const float*)d_in[9];
    const float* bnb = (const float*)d_in[10];
    const float* bnm = (const float*)d_in[11];
    const float* bnv = (const float*)d_in[12];
    float* out = (float*)d_out;
    (void)bk;

    cudaFuncSetAttribute(gemm_t,   cudaFuncAttributeMaxDynamicSharedMemorySize, DYN_SMEM);
    cudaFuncSetAttribute(gemm_s,   cudaFuncAttributeMaxDynamicSharedMemorySize, DYN_SMEM);
    cudaFuncSetAttribute(gemm_out, cudaFuncAttributeMaxDynamicSharedMemorySize, DYN_SMEM);

    h16 *mh, *ph;
    float *v1;
    cudaGetSymbolAddress((void**)&mh, g_mh);
    cudaGetSymbolAddress((void**)&ph, g_ph);
    cudaGetSymbolAddress((void**)&v1, g_v1);

    // prep
    xconv_kernel<<<(B_ * N_ * C_) / (512 * 4), 512>>>(x);
    // Mt[c][k] = (Wq Wk^T)[k][c] = sum_j Wk[c,j]*Wq[k,j]
    wgemm_kernel<<<dim3(8, 8), 256>>>(Wk, C_, 1, Wq, C_, 1, mh);
    // Pt[c][k] = (Wv Wo)[k][c] = sum_j Wo[j,c]*Wv[k,j]
    wgemm_kernel<<<dim3(8, 8), 256>>>(Wo, 1, C_, Wv, C_, 1, ph);
    // column bias: b_n = x_n · (Wk·bq)
    gemv_w_kernel<<<16, 1024>>>(Wk, bq, v1);
    gemv_x_kernel<<<4096, 256>>>(x);
    epiprep_kernel<<<4, dim3(128, 8)>>>(bv, Wo, bo, bns, bnb, bnm, bnv);

    // t = x · M (fp16 store, single-term)
    gemm_t<<<dim3(256, 2), 512, DYN_SMEM>>>(mh);

    // S-pass: th·xh + per-tile softmax stats + biased fp16 exp store
    gemm_s<<<dim3(16, 8, 16), 512, DYN_SMEM>>>();

    // global stats + column sums -> scale
    combine_kernel<<<(B_ * N_) / 256, 256>>>();
    colsum_kernel<<<dim3(16, B_), 256>>>();

    // out = relu(BN(scale ⊙ (x·P) + c1 + bo)) + x
    gemm_out<<<dim3(256, 2), 512, DYN_SMEM>>>(ph, x, out);
}

// round 13
// speedup vs baseline: 10.0794x; 1.0816x over previous
#include <cuda_runtime.h>
#include <cuda_fp16.h>
#include <math.h>
#include <float.h>
#include <stdint.h>

#define B_ 16
#define N_ 2048
#define C_ 512
#define EPS_ 1e-9f
#define BNEPS_ 1e-5f
#define EBIAS_ 10.0f   // fp16-E exponent bias; cancels exactly in col = Σ E·w

typedef __half h16;

__device__ h16 g_xh[B_ * N_ * C_];
__device__ h16 g_th[B_ * N_ * C_];
__device__ h16 g_mh[C_ * C_];
__device__ h16 g_ph[C_ * C_];
__device__ h16 g_E[(size_t)B_ * N_ * N_];
__device__ float g_pmax[B_ * 8 * N_], g_psum[B_ * 8 * N_];
__device__ float g_scale[B_ * N_], g_bcol[B_ * N_];
__device__ float g_v1[C_], g_c1k[C_], g_kmul[C_], g_kadd[C_];

__device__ __forceinline__ uint32_t smem_u32(const void* p) {
    uint32_t a;
    asm("{ .reg .u64 t; cvta.to.shared.u64 t, %1; cvt.u32.u64 %0, t; }" : "=r"(a) : "l"(p));
    return a;
}
#define SWZ(o) ((o) ^ (((o) >> 3) & 0x70))

#define CPASYNC(s, g) asm volatile("cp.async.cg.shared.global [%0], [%1], 16;" :: "r"(s), "l"(g))
#define CPCOMMIT()    asm volatile("cp.async.commit_group;" ::: "memory")
#define CPWAIT2()     asm volatile("cp.async.wait_group 2;" ::: "memory")
#define CPWAIT1()     asm volatile("cp.async.wait_group 1;" ::: "memory")
#define CPWAIT0()     asm volatile("cp.async.wait_group 0;" ::: "memory")

__device__ __forceinline__ void ldsm4(uint32_t addr, uint32_t& r0, uint32_t& r1,
                                      uint32_t& r2, uint32_t& r3) {
    asm volatile("ldmatrix.sync.aligned.m8n8.x4.shared.b16 {%0,%1,%2,%3}, [%4];"
                 : "=r"(r0), "=r"(r1), "=r"(r2), "=r"(r3) : "r"(addr));
}

__device__ __forceinline__ void mma16816(float* c, uint32_t a0, uint32_t a1,
                                         uint32_t a2, uint32_t a3,
                                         uint32_t b0, uint32_t b1) {
    asm volatile(
        "mma.sync.aligned.m16n8k16.row.col.f32.f16.f16.f32 "
        "{%0,%1,%2,%3}, {%4,%5,%6,%7}, {%8,%9}, {%0,%1,%2,%3};"
        : "+f"(c[0]), "+f"(c[1]), "+f"(c[2]), "+f"(c[3])
        : "r"(a0), "r"(a1), "r"(a2), "r"(a3), "r"(b0), "r"(b1));
}

#define STAGE_STRIDE 49152
#define OFF_RED 196608
#define DYN_SMEM (196608 + 2048)
#define STG_STRIDE 528

__device__ __forceinline__ void load_stage(uint32_t sb, int s, int tid,
        const h16* __restrict__ A, size_t arow0,
        const h16* __restrict__ Bh, size_t brow0)
{
    const int k0 = s * 64;
    const uint32_t stb = sb + (uint32_t)(s & 3) * STAGE_STRIDE;
    const int row = tid >> 3;
    const int c = tid & 7;
    const size_t gk = (size_t)(k0 + c * 8);
#pragma unroll
    for (int h = 0; h < 2; ++h) {
        const int r = row + h * 64;
        const uint32_t off = SWZ((uint32_t)(r * 128 + c * 16));
        CPASYNC(stb + off, A + (arow0 + r) * C_ + gk);
    }
#pragma unroll
    for (int h = 0; h < 4; ++h) {
        const int r = row + h * 64;
        const uint32_t off = SWZ((uint32_t)(r * 128 + c * 16));
        CPASYNC(stb + 16384 + off, Bh + (brow0 + r) * C_ + gk);
    }
    CPCOMMIT();
}

__device__ __forceinline__ void compute_stage(uint32_t sb, int s, int lane,
                                              int wm, int wn, float acc[2][8][4])
{
    const uint32_t stb = sb + (uint32_t)(s & 3) * STAGE_STRIDE;
#pragma unroll
    for (int k16 = 0; k16 < 4; ++k16) {
        uint32_t ah[2][4], bh[4][4];
        const uint32_t akoff = (uint32_t)(k16 * 32 + (lane >> 4) * 16);
#pragma unroll
        for (int mt = 0; mt < 2; ++mt) {
            const int row = wm * 32 + mt * 16 + (lane & 15);
            const uint32_t a = SWZ((uint32_t)(row * 128) + akoff);
            ldsm4(stb + a, ah[mt][0], ah[mt][1], ah[mt][2], ah[mt][3]);
        }
        const int g = lane >> 3;
        const int nofs = (lane & 7) + (g >> 1) * 8;
        const uint32_t bk = (uint32_t)(k16 * 32 + (g & 1) * 16);
#pragma unroll
        for (int nt4 = 0; nt4 < 4; ++nt4) {
            const int n = wn * 64 + nt4 * 16 + nofs;
            const uint32_t a = SWZ((uint32_t)(n * 128) + bk);
            ldsm4(stb + 16384 + a, bh[nt4][0], bh[nt4][1], bh[nt4][2], bh[nt4][3]);
        }
#pragma unroll
        for (int mt = 0; mt < 2; ++mt)
#pragma unroll
            for (int j = 0; j < 8; ++j) {
                const int p = j >> 1, hi = (j & 1) * 2;
                mma16816(acc[mt][j], ah[mt][0], ah[mt][1], ah[mt][2], ah[mt][3],
                         bh[p][hi], bh[p][hi + 1]);
            }
    }
}

__device__ __forceinline__ void mma_mainloop(uint32_t sb,
        const h16* __restrict__ A, size_t arow0,
        const h16* __restrict__ Bh, size_t brow0,
        float acc[2][8][4])
{
    const int tid = threadIdx.x;
    const int lane = tid & 31;
    const int w = tid >> 5;
    const int wm = w & 3, wn = w >> 2;

#pragma unroll
    for (int mt = 0; mt < 2; ++mt)
#pragma unroll
        for (int j = 0; j < 8; ++j)
#pragma unroll
            for (int q = 0; q < 4; ++q) acc[mt][j][q] = 0.f;

    load_stage(sb, 0, tid, A, arow0, Bh, brow0);
    load_stage(sb, 1, tid, A, arow0, Bh, brow0);
    load_stage(sb, 2, tid, A, arow0, Bh, brow0);
#pragma unroll 1
    for (int s = 0; s < 8; ++s) {
        if (s <= 5) CPWAIT2();
        else if (s == 6) CPWAIT1();
        else CPWAIT0();
        __syncthreads();
        if (s < 5) load_stage(sb, s + 3, tid, A, arow0, Bh, brow0);
        compute_stage(sb, s, lane, wm, wn, acc);
    }
}

__global__ __launch_bounds__(512, 1)
void gemm_t(const h16* __restrict__ Bh)
{
    extern __shared__ __align__(128) char smem[];
    const uint32_t sb = smem_u32(smem);
    const size_t arow0 = (size_t)blockIdx.x * 128;
    const size_t brow0 = (size_t)blockIdx.y * 256;

    float acc[2][8][4];
    mma_mainloop(sb, g_xh, arow0, Bh, brow0, acc);

    const int tid = threadIdx.x, lane = tid & 31, w = tid >> 5;
    const int wm = w & 3, wn = w >> 2;
#pragma unroll
    for (int mt = 0; mt < 2; ++mt)
#pragma unroll
        for (int half = 0; half < 2; ++half) {
            const int r = wm * 32 + mt * 16 + half * 8 + lane / 4;
#pragma unroll
            for (int j = 0; j < 8; ++j) {
                const int col = wn * 64 + j * 8 + (lane & 3) * 2;
                *(__half2*)(smem + r * STG_STRIDE + col * 2) =
                    __halves2half2(__float2half_rn(acc[mt][j][half * 2 + 0]),
                                   __float2half_rn(acc[mt][j][half * 2 + 1]));
            }
        }
    __syncthreads();
#pragma unroll
    for (int pass = 0; pass < 8; ++pass) {
        const int r = pass * 16 + (tid >> 5);
        const int c16 = tid & 31;
        const uint4 v = *(const uint4*)(smem + r * STG_STRIDE + c16 * 16);
        *(uint4*)(g_th + (arow0 + r) * C_ + brow0 + c16 * 8) = v;
    }
}

__global__ __launch_bounds__(512, 1)
void gemm_s()
{
    extern __shared__ __align__(128) char smem[];
    const uint32_t sb = smem_u32(smem);
    float* red = (float*)(smem + OFF_RED);

    const int it = blockIdx.x, jt = blockIdx.y, bb = blockIdx.z;
    const size_t arow0 = (size_t)bb * N_ + (size_t)it * 128;
    const size_t brow0 = (size_t)bb * N_ + (size_t)jt * 256;

    float acc[2][8][4];
    mma_mainloop(sb, g_th, arow0, g_xh, brow0, acc);

    const int tid = threadIdx.x, lane = tid & 31, w = tid >> 5;
    const int wm = w & 3, wn = w >> 2;

    const int base_n = bb * N_ + jt * 256;
    float bc[8][2];
#pragma unroll
    for (int j = 0; j < 8; ++j) {
        const int col = wn * 64 + j * 8 + (lane & 3) * 2;
        bc[j][0] = __ldg(g_bcol + base_n + col);
        bc[j][1] = __ldg(g_bcol + base_n + col + 1);
    }

    float rmx[4];
#pragma unroll
    for (int slot = 0; slot < 4; ++slot) {
        const int mt = slot >> 1, half = slot & 1;
        float m = -FLT_MAX;
#pragma unroll
        for (int j = 0; j < 8; ++j) {
            m = fmaxf(m, acc[mt][j][half * 2 + 0] + bc[j][0]);
            m = fmaxf(m, acc[mt][j][half * 2 + 1] + bc[j][1]);
        }
        m = fmaxf(m, __shfl_xor_sync(0xffffffffu, m, 1));
        m = fmaxf(m, __shfl_xor_sync(0xffffffffu, m, 2));
        rmx[slot] = m;
    }
    if ((lane & 3) == 0) {
#pragma unroll
        for (int slot = 0; slot < 4; ++slot) {
            const int row = wm * 32 + (slot >> 1) * 16 + (slot & 1) * 8 + lane / 4;
            red[row * 4 + wn] = rmx[slot];
        }
    }
    __syncthreads();
    float rowmax[4];
#pragma unroll
    for (int slot = 0; slot < 4; ++slot) {
        const int row = wm * 32 + (slot >> 1) * 16 + (slot & 1) * 8 + lane / 4;
        rowmax[slot] = fmaxf(fmaxf(red[row * 4 + 0], red[row * 4 + 1]),
                             fmaxf(red[row * 4 + 2], red[row * 4 + 3]));
    }
    __syncthreads();

    float rsm[4];
#pragma unroll
    for (int slot = 0; slot < 4; ++slot) {
        const int mt = slot >> 1, half = slot & 1;
        const int r = wm * 32 + mt * 16 + half * 8 + lane / 4;
        float s = 0.f;
#pragma unroll
        for (int j = 0; j < 8; ++j) {
            const int col = wn * 64 + j * 8 + (lane & 3) * 2;
            const float e0 = __expf(acc[mt][j][half * 2 + 0] + bc[j][0] - rowmax[slot] + EBIAS_);
            const float e1 = __expf(acc[mt][j][half * 2 + 1] + bc[j][1] - rowmax[slot] + EBIAS_);
            *(__half2*)(smem + r * STG_STRIDE + col * 2) =
                __halves2half2(__float2half_rn(e0), __float2half_rn(e1));
            s += e0 + e1;
        }
        s += __shfl_xor_sync(0xffffffffu, s, 1);
        s += __shfl_xor_sync(0xffffffffu, s, 2);
        rsm[slot] = s;
    }
    if ((lane & 3) == 0) {
#pragma unroll
        for (int slot = 0; slot < 4; ++slot) {
            const int row = wm * 32 + (slot >> 1) * 16 + (slot & 1) * 8 + lane / 4;
            red[row * 4 + wn] = rsm[slot];
        }
    }
    __syncthreads();
    if (wn == 0 && (lane & 3) == 0) {
#pragma unroll
        for (int slot = 0; slot < 4; ++slot) {
            const int row = wm * 32 + (slot >> 1) * 16 + (slot & 1) * 8 + lane / 4;
            const size_t p = ((size_t)bb * 8 + jt) * N_ + it * 128 + row;
            g_pmax[p] = rowmax[slot];
            g_psum[p] = red[row * 4] + red[row * 4 + 1] + red[row * 4 + 2] + red[row * 4 + 3];
        }
    }
    // coalesced E copy-out (row stride N_)
    h16* Ebase = g_E + ((size_t)bb * N_ + it * 128) * N_ + jt * 256;
#pragma unroll
    for (int pass = 0; pass < 8; ++pass) {
        const int r = pass * 16 + (tid >> 5);
        const int c16 = tid & 31;
        const uint4 v = *(const uint4*)(smem + r * STG_STRIDE + c16 * 16);
        *(uint4*)(Ebase + (size_t)r * N_ + c16 * 8) = v;
    }
}

__global__ __launch_bounds__(512, 1)
void gemm_out(const h16* __restrict__ Bh,
              const float* __restrict__ x, float* __restrict__ out)
{
    extern __shared__ __align__(128) char smem[];
    const uint32_t sb = smem_u32(smem);
    const size_t arow0 = (size_t)blockIdx.x * 128;
    const size_t brow0 = (size_t)blockIdx.y * 256;

    float acc[2][8][4];
    mma_mainloop(sb, g_xh, arow0, Bh, brow0, acc);

    const int tid = threadIdx.x, lane = tid & 31, w = tid >> 5;
    const int wm = w & 3, wn = w >> 2;

#pragma unroll
    for (int mt = 0; mt < 2; ++mt) {
#pragma unroll
        for (int half = 0; half < 2; ++half) {
            const size_t grow = arow0 + wm * 32 + mt * 16 + half * 8 + lane / 4;
            const float sc = g_scale[grow];
#pragma unroll
            for (int j = 0; j < 8; ++j) {
                const int col = (int)brow0 + wn * 64 + j * 8 + (lane & 3) * 2;
                const float2 xv = *(const float2*)(x + grow * C_ + col);
                const float km0 = __ldg(g_kmul + col), km1 = __ldg(g_kmul + col + 1);
                const float kd0 = __ldg(g_kadd + col), kd1 = __ldg(g_kadd + col + 1);
                const float ck0 = __ldg(g_c1k + col),  ck1 = __ldg(g_c1k + col + 1);
                float y0 = sc * (acc[mt][j][half * 2 + 0] * km0 + ck0) + kd0;
                float y1 = sc * (acc[mt][j][half * 2 + 1] * km1 + ck1) + kd1;
                float2 o;
                o.x = fmaxf(y0, 0.f) + xv.x;
                o.y = fmaxf(y1, 0.f) + xv.y;
                *(float2*)(out + grow * C_ + col) = o;
            }
        }
    }
}

__global__ __launch_bounds__(256) void xprep_kernel(const float* __restrict__ x)
{
    __shared__ float v1s[C_];
    for (int c = threadIdx.x; c < C_; c += 256) v1s[c] = g_v1[c];
    __syncthreads();
    const int row = blockIdx.x * 8 + (threadIdx.x >> 5);
    const int lane = threadIdx.x & 31;
    float s = 0.f;
#pragma unroll
    for (int i = 0; i < 4; ++i) {
        const int c = lane * 4 + i * 128;
        const float4 xv = *(const float4*)(x + (size_t)row * C_ + c);
        s += xv.x * v1s[c] + xv.y * v1s[c + 1] + xv.z * v1s[c + 2] + xv.w * v1s[c + 3];
        *(__half2*)(g_xh + (size_t)row * C_ + c) =
            __halves2half2(__float2half_rn(xv.x), __float2half_rn(xv.y));
        *(__half2*)(g_xh + (size_t)row * C_ + c + 2) =
            __halves2half2(__float2half_rn(xv.z), __float2half_rn(xv.w));
    }
#pragma unroll
    for (int off = 16; off > 0; off >>= 1) s += __shfl_xor_sync(0xffffffffu, s, off);
    if (lane == 0) g_bcol[row] = s;
}

__global__ __launch_bounds__(256) void wgemm_kernel(
    const float* __restrict__ Wk, const float* __restrict__ Wq,
    const float* __restrict__ Wo, const float* __restrict__ Wv)
{
    __shared__ float As[64][65], Bs[64][65];
    const int i0 = blockIdx.y * 64, l0 = blockIdx.x * 64;
    const int z = blockIdx.z;
    const float* A  = z ? Wo : Wk;
    const float* Bm = z ? Wv : Wq;
    const int sa1 = z ? 1 : C_, sa2 = z ? C_ : 1;
    h16* outH = z ? g_ph : g_mh;

    const int tid = threadIdx.x;
    const int ty = tid >> 4, tx = tid & 15;
    float acc[4][4] = {};
    for (int k0 = 0; k0 < C_; k0 += 64) {
        for (int v = tid; v < 4096; v += 256) {
            const int r = v >> 6, kk = v & 63;
            As[r][kk] = A[(size_t)(i0 + r) * sa1 + (size_t)(k0 + kk) * sa2];
            Bs[r][kk] = Bm[(size_t)(l0 + r) * C_ + (k0 + kk)];
        }
        __syncthreads();
#pragma unroll 8
        for (int kk = 0; kk < 64; ++kk) {
            float av[4], bv[4];
#pragma unroll
            for (int u = 0; u < 4; ++u) { av[u] = As[ty * 4 + u][kk]; bv[u] = Bs[tx * 4 + u][kk]; }
#pragma unroll
            for (int u = 0; u < 4; ++u)
#pragma unroll
                for (int q = 0; q < 4; ++q) acc[u][q] += av[u] * bv[q];
        }
        __syncthreads();
    }
#pragma unroll
    for (int u = 0; u < 4; ++u)
#pragma unroll
        for (int q = 0; q < 4; ++q) {
            const size_t o = (size_t)(i0 + ty * 4 + u) * C_ + l0 + tx * 4 + q;
            outH[o] = __float2half_rn(acc[u][q]);
        }
}

__global__ __launch_bounds__(1024) void gemv_w_kernel(const float* __restrict__ W,
                                                      const float* __restrict__ vec,
                                                      float* __restrict__ outv)
{
    const int row = blockIdx.x * 32 + (threadIdx.x >> 5);
    const int lane = threadIdx.x & 31;
    float s = 0.f;
#pragma unroll
    for (int i = 0; i < 4; ++i) {
        const int c = lane * 4 + i * 128;
        const float4 wv = *(const float4*)(W + (size_t)row * C_ + c);
        const float4 vv = *(const float4*)(vec + c);
        s += wv.x * vv.x + wv.y * vv.y + wv.z * vv.z + wv.w * vv.w;
    }
#pragma unroll
    for (int off = 16; off > 0; off >>= 1) s += __shfl_xor_sync(0xffffffffu, s, off);
    if (lane == 0) outv[row] = s;
}

__global__ void epiprep_kernel(const float* __restrict__ bv, const float* __restrict__ Wo,
                               const float* __restrict__ bo,
                               const float* __restrict__ bns, const float* __restrict__ bnb,
                               const float* __restrict__ bnm, const float* __restrict__ bnv)
{
    __shared__ float part[8][128];
    const int c = blockIdx.x * 128 + threadIdx.x;
    const int jy = threadIdx.y;
    float s = 0.f;
    for (int j = jy * 64; j < jy * 64 + 64; ++j)
        s += bv[j] * Wo[(size_t)j * C_ + c];
    part[jy][threadIdx.x] = s;
    __syncthreads();
    if (jy == 0) {
        float c1 = 0.f;
#pragma unroll
        for (int p = 0; p < 8; ++p) c1 += part[p][threadIdx.x];
        const float ka = bns[c] * rsqrtf(bnv[c] + BNEPS_);
        g_kmul[c] = ka;
        g_kadd[c] = (bo[c] - bnm[c]) * ka + bnb[c];
        g_c1k[c] = c1 * ka;
    }
}

__global__ __launch_bounds__(256) void colsum_kernel()
{
    __shared__ float sw[N_];
    __shared__ float red[256][8];

    const int jt = blockIdx.x, b = blockIdx.y;
    const int tile = jt >> 1;
    const int t = threadIdx.x;

    for (int m = t; m < N_; m += 256) {
        float pm[8];
#pragma unroll
        for (int j = 0; j < 8; ++j) pm[j] = g_pmax[((size_t)b * 8 + j) * N_ + m];
        float rmax = -FLT_MAX;
#pragma unroll
        for (int j = 0; j < 8; ++j) rmax = fmaxf(rmax, pm[j]);
        float rsum = 0.f;
#pragma unroll
        for (int j = 0; j < 8; ++j)
            rsum += g_psum[((size_t)b * 8 + j) * N_ + m] * __expf(pm[j] - rmax);
        sw[m] = __expf(pm[tile] - rmax) / rsum;
    }
    __syncthreads();

    const int c8 = t & 15;
    const int mh = t >> 4;
    const int n0 = jt * 128 + c8 * 8;
    const h16* Eb = g_E + (size_t)b * N_ * N_;

    float a[8] = {};
#pragma unroll 4
    for (int m = mh * 128; m < mh * 128 + 128; ++m) {
        const float wm = sw[m];
        const uint4 u = *(const uint4*)(Eb + (size_t)m * N_ + n0);
        const __half2* e2 = (const __half2*)&u;
#pragma unroll
        for (int q = 0; q < 4; ++q) {
            const float2 f = __half22float2(e2[q]);
            a[q * 2 + 0] += wm * f.x;
            a[q * 2 + 1] += wm * f.y;
        }
    }
#pragma unroll
    for (int q = 0; q < 8; ++q) red[t][q] = a[q];
    __syncthreads();
    if (mh == 0) {
#pragma unroll
        for (int q = 0; q < 8; ++q) {
            float c = a[q];
#pragma unroll 1
            for (int sp = 1; sp < 16; ++sp) c += red[sp * 16 + c8][q];
            g_scale[(size_t)b * N_ + n0 + q] = c / (EPS_ + c);
        }
    }
}

extern "C" void kernel_launch(void* const* d_in, const int* in_sizes, int n_in,
                              void* d_out, int out_size)
{
    const float* x   = (const float*)d_in[0];
    const float* Wq  = (const float*)d_in[1];
    const float* bq  = (const float*)d_in[2];
    const float* Wk  = (const float*)d_in[3];
    const float* bk  = (const float*)d_in[4];  // unused: row bias cancels in softmax
    const float* Wv  = (const float*)d_in[5];
    const float* bv  = (const float*)d_in[6];
    const float* Wo  = (const float*)d_in[7];
    const float* bo  = (const float*)d_in[8];
    const float* bns = (const float*)d_in[9];
    const float* bnb = (const float*)d_in[10];
    const float* bnm = (const float*)d_in[11];
    const float* bnv = (const float*)d_in[12];
    float* out = (float*)d_out;
    (void)bk;

    cudaFuncSetAttribute(gemm_t,   cudaFuncAttributeMaxDynamicSharedMemorySize, DYN_SMEM);
    cudaFuncSetAttribute(gemm_s,   cudaFuncAttributeMaxDynamicSharedMemorySize, DYN_SMEM);
    cudaFuncSetAttribute(gemm_out, cudaFuncAttributeMaxDynamicSharedMemorySize, DYN_SMEM);

    h16 *mh, *ph;
    float *v1;
    cudaGetSymbolAddress((void**)&mh, g_mh);
    cudaGetSymbolAddress((void**)&ph, g_ph);
    cudaGetSymbolAddress((void**)&v1, g_v1);

    wgemm_kernel<<<dim3(8, 8, 2), 256>>>(Wk, Wq, Wo, Wv);
    gemv_w_kernel<<<16, 1024>>>(Wk, bq, v1);
    xprep_kernel<<<4096, 256>>>(x);
    epiprep_kernel<<<4, dim3(128, 8)>>>(bv, Wo, bo, bns, bnb, bnm, bnv);

    gemm_t<<<dim3(256, 2), 512, DYN_SMEM>>>(mh);
    gemm_s<<<dim3(16, 8, 16), 512, DYN_SMEM>>>();
    colsum_kernel<<<dim3(16, B_), 256>>>();
    gemm_out<<<dim3(256, 2), 512, DYN_SMEM>>>(ph, x, out);
}

// round 15
// speedup vs baseline: 10.7033x; 1.0619x over previous
#include <cuda_runtime.h>
#include <cuda_fp16.h>
#include <math.h>
#include <float.h>
#include <stdint.h>

#define B_ 16
#define N_ 2048
#define C_ 512
#define EPS_ 1e-9f
#define BNEPS_ 1e-5f
#define EBIAS_ 10.0f   // fp16-E exponent bias; cancels exactly in col = Σ E·w

typedef __half h16;

__device__ h16 g_xh[B_ * N_ * C_];
__device__ h16 g_th[B_ * N_ * C_];
__device__ h16 g_mh[C_ * C_];
__device__ h16 g_ph[C_ * C_];
__device__ h16 g_E[(size_t)B_ * N_ * N_];
__device__ float g_pmax[B_ * 8 * N_], g_psum[B_ * 8 * N_];
__device__ float g_scale[B_ * N_], g_bcol[B_ * N_];
__device__ float g_v1[C_], g_c1k[C_], g_kmul[C_], g_kadd[C_];

__device__ __forceinline__ uint32_t smem_u32(const void* p) {
    uint32_t a;
    asm("{ .reg .u64 t; cvta.to.shared.u64 t, %1; cvt.u32.u64 %0, t; }" : "=r"(a) : "l"(p));
    return a;
}
#define SWZ(o) ((o) ^ (((o) >> 3) & 0x70))

#define CPASYNC(s, g) asm volatile("cp.async.cg.shared.global [%0], [%1], 16;" :: "r"(s), "l"(g))
#define CPCOMMIT()    asm volatile("cp.async.commit_group;" ::: "memory")
#define CPWAIT2()     asm volatile("cp.async.wait_group 2;" ::: "memory")
#define CPWAIT1()     asm volatile("cp.async.wait_group 1;" ::: "memory")
#define CPWAIT0()     asm volatile("cp.async.wait_group 0;" ::: "memory")

__device__ __forceinline__ void ldsm4(uint32_t addr, uint32_t& r0, uint32_t& r1,
                                      uint32_t& r2, uint32_t& r3) {
    asm volatile("ldmatrix.sync.aligned.m8n8.x4.shared.b16 {%0,%1,%2,%3}, [%4];"
                 : "=r"(r0), "=r"(r1), "=r"(r2), "=r"(r3) : "r"(addr));
}

__device__ __forceinline__ void mma16816(float* c, uint32_t a0, uint32_t a1,
                                         uint32_t a2, uint32_t a3,
                                         uint32_t b0, uint32_t b1) {
    asm volatile(
        "mma.sync.aligned.m16n8k16.row.col.f32.f16.f16.f32 "
        "{%0,%1,%2,%3}, {%4,%5,%6,%7}, {%8,%9}, {%0,%1,%2,%3};"
        : "+f"(c[0]), "+f"(c[1]), "+f"(c[2]), "+f"(c[3])
        : "r"(a0), "r"(a1), "r"(a2), "r"(a3), "r"(b0), "r"(b1));
}

#define STAGE_STRIDE 49152
#define OFF_RED 196608
#define DYN_SMEM (196608 + 2048)
#define STG_STRIDE 528

__device__ __forceinline__ void load_stage(uint32_t sb, int s, int tid,
        const h16* __restrict__ A, size_t arow0,
        const h16* __restrict__ Bh, size_t brow0)
{
    const int k0 = s * 64;
    const uint32_t stb = sb + (uint32_t)(s & 3) * STAGE_STRIDE;
    const int row = tid >> 3;
    const int c = tid & 7;
    const size_t gk = (size_t)(k0 + c * 8);
#pragma unroll
    for (int h = 0; h < 2; ++h) {
        const int r = row + h * 64;
        const uint32_t off = SWZ((uint32_t)(r * 128 + c * 16));
        CPASYNC(stb + off, A + (arow0 + r) * C_ + gk);
    }
#pragma unroll
    for (int h = 0; h < 4; ++h) {
        const int r = row + h * 64;
        const uint32_t off = SWZ((uint32_t)(r * 128 + c * 16));
        CPASYNC(stb + 16384 + off, Bh + (brow0 + r) * C_ + gk);
    }
    CPCOMMIT();
}

__device__ __forceinline__ void compute_stage(uint32_t sb, int s, int lane,
                                              int wm, int wn, float acc[2][8][4])
{
    const uint32_t stb = sb + (uint32_t)(s & 3) * STAGE_STRIDE;
#pragma unroll
    for (int k16 = 0; k16 < 4; ++k16) {
        uint32_t ah[2][4], bh[4][4];
        const uint32_t akoff = (uint32_t)(k16 * 32 + (lane >> 4) * 16);
#pragma unroll
        for (int mt = 0; mt < 2; ++mt) {
            const int row = wm * 32 + mt * 16 + (lane & 15);
            const uint32_t a = SWZ((uint32_t)(row * 128) + akoff);
            ldsm4(stb + a, ah[mt][0], ah[mt][1], ah[mt][2], ah[mt][3]);
        }
        const int g = lane >> 3;
        const int nofs = (lane & 7) + (g >> 1) * 8;
        const uint32_t bk = (uint32_t)(k16 * 32 + (g & 1) * 16);
#pragma unroll
        for (int nt4 = 0; nt4 < 4; ++nt4) {
            const int n = wn * 64 + nt4 * 16 + nofs;
            const uint32_t a = SWZ((uint32_t)(n * 128) + bk);
            ldsm4(stb + 16384 + a, bh[nt4][0], bh[nt4][1], bh[nt4][2], bh[nt4][3]);
        }
#pragma unroll
        for (int mt = 0; mt < 2; ++mt)
#pragma unroll
            for (int j = 0; j < 8; ++j) {
                const int p = j >> 1, hi = (j & 1) * 2;
                mma16816(acc[mt][j], ah[mt][0], ah[mt][1], ah[mt][2], ah[mt][3],
                         bh[p][hi], bh[p][hi + 1]);
            }
    }
}

__device__ __forceinline__ void mma_mainloop(uint32_t sb,
        const h16* __restrict__ A, size_t arow0,
        const h16* __restrict__ Bh, size_t brow0,
        float acc[2][8][4])
{
    const int tid = threadIdx.x;
    const int lane = tid & 31;
    const int w = tid >> 5;
    const int wm = w & 3, wn = w >> 2;

#pragma unroll
    for (int mt = 0; mt < 2; ++mt)
#pragma unroll
        for (int j = 0; j < 8; ++j)
#pragma unroll
            for (int q = 0; q < 4; ++q) acc[mt][j][q] = 0.f;

    load_stage(sb, 0, tid, A, arow0, Bh, brow0);
    load_stage(sb, 1, tid, A, arow0, Bh, brow0);
    load_stage(sb, 2, tid, A, arow0, Bh, brow0);
#pragma unroll 1
    for (int s = 0; s < 8; ++s) {
        if (s <= 5) CPWAIT2();
        else if (s == 6) CPWAIT1();
        else CPWAIT0();
        __syncthreads();
        if (s < 5) load_stage(sb, s + 3, tid, A, arow0, Bh, brow0);
        compute_stage(sb, s, lane, wm, wn, acc);
    }
}

__global__ __launch_bounds__(512, 1)
void gemm_t(const h16* __restrict__ Bh)
{
    extern __shared__ __align__(128) char smem[];
    const uint32_t sb = smem_u32(smem);
    const size_t arow0 = (size_t)blockIdx.x * 128;
    const size_t brow0 = (size_t)blockIdx.y * 256;

    float acc[2][8][4];
    mma_mainloop(sb, g_xh, arow0, Bh, brow0, acc);

    const int tid = threadIdx.x, lane = tid & 31, w = tid >> 5;
    const int wm = w & 3, wn = w >> 2;
#pragma unroll
    for (int mt = 0; mt < 2; ++mt)
#pragma unroll
        for (int half = 0; half < 2; ++half) {
            const int r = wm * 32 + mt * 16 + half * 8 + lane / 4;
#pragma unroll
            for (int j = 0; j < 8; ++j) {
                const int col = wn * 64 + j * 8 + (lane & 3) * 2;
                *(__half2*)(smem + r * STG_STRIDE + col * 2) =
                    __halves2half2(__float2half_rn(acc[mt][j][half * 2 + 0]),
                                   __float2half_rn(acc[mt][j][half * 2 + 1]));
            }
        }
    __syncthreads();
#pragma unroll
    for (int pass = 0; pass < 8; ++pass) {
        const int r = pass * 16 + (tid >> 5);
        const int c16 = tid & 31;
        const uint4 v = *(const uint4*)(smem + r * STG_STRIDE + c16 * 16);
        *(uint4*)(g_th + (arow0 + r) * C_ + brow0 + c16 * 8) = v;
    }
}

__global__ __launch_bounds__(512, 1)
void gemm_s()
{
    extern __shared__ __align__(128) char smem[];
    const uint32_t sb = smem_u32(smem);
    float* red = (float*)(smem + OFF_RED);

    const int it = blockIdx.x, jt = blockIdx.y, bb = blockIdx.z;
    const size_t arow0 = (size_t)bb * N_ + (size_t)it * 128;
    const size_t brow0 = (size_t)bb * N_ + (size_t)jt * 256;

    float acc[2][8][4];
    mma_mainloop(sb, g_th, arow0, g_xh, brow0, acc);

    const int tid = threadIdx.x, lane = tid & 31, w = tid >> 5;
    const int wm = w & 3, wn = w >> 2;

    const int base_n = bb * N_ + jt * 256;
    float bc[8][2];
#pragma unroll
    for (int j = 0; j < 8; ++j) {
        const int col = wn * 64 + j * 8 + (lane & 3) * 2;
        bc[j][0] = __ldg(g_bcol + base_n + col);
        bc[j][1] = __ldg(g_bcol + base_n + col + 1);
    }

    float rmx[4];
#pragma unroll
    for (int slot = 0; slot < 4; ++slot) {
        const int mt = slot >> 1, half = slot & 1;
        float m = -FLT_MAX;
#pragma unroll
        for (int j = 0; j < 8; ++j) {
            m = fmaxf(m, acc[mt][j][half * 2 + 0] + bc[j][0]);
            m = fmaxf(m, acc[mt][j][half * 2 + 1] + bc[j][1]);
        }
        m = fmaxf(m, __shfl_xor_sync(0xffffffffu, m, 1));
        m = fmaxf(m, __shfl_xor_sync(0xffffffffu, m, 2));
        rmx[slot] = m;
    }
    if ((lane & 3) == 0) {
#pragma unroll
        for (int slot = 0; slot < 4; ++slot) {
            const int row = wm * 32 + (slot >> 1) * 16 + (slot & 1) * 8 + lane / 4;
            red[row * 4 + wn] = rmx[slot];
        }
    }
    __syncthreads();
    float rowmax[4];
#pragma unroll
    for (int slot = 0; slot < 4; ++slot) {
        const int row = wm * 32 + (slot >> 1) * 16 + (slot & 1) * 8 + lane / 4;
        rowmax[slot] = fmaxf(fmaxf(red[row * 4 + 0], red[row * 4 + 1]),
                             fmaxf(red[row * 4 + 2], red[row * 4 + 3]));
    }
    __syncthreads();

    float rsm[4];
#pragma unroll
    for (int slot = 0; slot < 4; ++slot) {
        const int mt = slot >> 1, half = slot & 1;
        const int r = wm * 32 + mt * 16 + half * 8 + lane / 4;
        float s = 0.f;
#pragma unroll
        for (int j = 0; j < 8; ++j) {
            const int col = wn * 64 + j * 8 + (lane & 3) * 2;
            const float e0 = __expf(acc[mt][j][half * 2 + 0] + bc[j][0] - rowmax[slot] + EBIAS_);
            const float e1 = __expf(acc[mt][j][half * 2 + 1] + bc[j][1] - rowmax[slot] + EBIAS_);
            *(__half2*)(smem + r * STG_STRIDE + col * 2) =
                __halves2half2(__float2half_rn(e0), __float2half_rn(e1));
            s += e0 + e1;
        }
        s += __shfl_xor_sync(0xffffffffu, s, 1);
        s += __shfl_xor_sync(0xffffffffu, s, 2);
        rsm[slot] = s;
    }
    if ((lane & 3) == 0) {
#pragma unroll
        for (int slot = 0; slot < 4; ++slot) {
            const int row = wm * 32 + (slot >> 1) * 16 + (slot & 1) * 8 + lane / 4;
            red[row * 4 + wn] = rsm[slot];
        }
    }
    __syncthreads();
    if (wn == 0 && (lane & 3) == 0) {
#pragma unroll
        for (int slot = 0; slot < 4; ++slot) {
            const int row = wm * 32 + (slot >> 1) * 16 + (slot & 1) * 8 + lane / 4;
            const size_t p = ((size_t)bb * 8 + jt) * N_ + it * 128 + row;
            g_pmax[p] = rowmax[slot];
            g_psum[p] = red[row * 4] + red[row * 4 + 1] + red[row * 4 + 2] + red[row * 4 + 3];
        }
    }
    h16* Ebase = g_E + ((size_t)bb * N_ + it * 128) * N_ + jt * 256;
#pragma unroll
    for (int pass = 0; pass < 8; ++pass) {
        const int r = pass * 16 + (tid >> 5);
        const int c16 = tid & 31;
        const uint4 v = *(const uint4*)(smem + r * STG_STRIDE + c16 * 16);
        *(uint4*)(Ebase + (size_t)r * N_ + c16 * 8) = v;
    }
}

__global__ __launch_bounds__(512, 1)
void gemm_out(const h16* __restrict__ Bh,
              const float* __restrict__ x, float* __restrict__ out)
{
    extern __shared__ __align__(128) char smem[];
    const uint32_t sb = smem_u32(smem);
    const size_t arow0 = (size_t)blockIdx.x * 128;
    const size_t brow0 = (size_t)blockIdx.y * 256;

    float acc[2][8][4];
    mma_mainloop(sb, g_xh, arow0, Bh, brow0, acc);

    const int tid = threadIdx.x, lane = tid & 31, w = tid >> 5;
    const int wm = w & 3, wn = w >> 2;

#pragma unroll
    for (int mt = 0; mt < 2; ++mt) {
#pragma unroll
        for (int half = 0; half < 2; ++half) {
            const size_t grow = arow0 + wm * 32 + mt * 16 + half * 8 + lane / 4;
            const float sc = g_scale[grow];
#pragma unroll
            for (int j = 0; j < 8; ++j) {
                const int col = (int)brow0 + wn * 64 + j * 8 + (lane & 3) * 2;
                const float2 xv = *(const float2*)(x + grow * C_ + col);
                const float km0 = __ldg(g_kmul + col), km1 = __ldg(g_kmul + col + 1);
                const float kd0 = __ldg(g_kadd + col), kd1 = __ldg(g_kadd + col + 1);
                const float ck0 = __ldg(g_c1k + col),  ck1 = __ldg(g_c1k + col + 1);
                float y0 = sc * (acc[mt][j][half * 2 + 0] * km0 + ck0) + kd0;
                float y1 = sc * (acc[mt][j][half * 2 + 1] * km1 + ck1) + kd1;
                float2 o;
                o.x = fmaxf(y0, 0.f) + xv.x;
                o.y = fmaxf(y1, 0.f) + xv.y;
                *(float2*)(out + grow * C_ + col) = o;
            }
        }
    }
}

// --------- merged prep: wgemm (128 blocks) + epiprep (16) + xprep (4096) -----
// All parts are independent given g_v1 (computed by gemv_w beforehand).
__global__ __launch_bounds__(256) void prep_kernel(
    const float* __restrict__ Wk, const float* __restrict__ Wq,
    const float* __restrict__ Wo, const float* __restrict__ Wv,
    const float* __restrict__ x,  const float* __restrict__ bv,
    const float* __restrict__ bo,
    const float* __restrict__ bns, const float* __restrict__ bnb,
    const float* __restrict__ bnm, const float* __restrict__ bnv)
{
    __shared__ __align__(16) char sh[2 * 64 * 65 * 4];   // 33.3 KB union
    const int bid = blockIdx.x;
    const int tid = threadIdx.x;

    if (bid < 128) {
        // ---- weight-product GEMMs: z=0 -> Mt, z=1 -> Pt
        float (*As)[65] = (float(*)[65])sh;
        float (*Bs)[65] = (float(*)[65])(sh + 64 * 65 * 4);
        const int bx = bid & 7, by = (bid >> 3) & 7, z = bid >> 6;
        const float* A  = z ? Wo : Wk;
        const float* Bm = z ? Wv : Wq;
        const int sa1 = z ? 1 : C_, sa2 = z ? C_ : 1;
        h16* outH = z ? g_ph : g_mh;
        const int i0 = by * 64, l0 = bx * 64;
        const int ty = tid >> 4, tx = tid & 15;
        float acc[4][4] = {};
        for (int k0 = 0; k0 < C_; k0 += 64) {
            for (int v = tid; v < 4096; v += 256) {
                const int r = v >> 6, kk = v & 63;
                As[r][kk] = A[(size_t)(i0 + r) * sa1 + (size_t)(k0 + kk) * sa2];
                Bs[r][kk] = Bm[(size_t)(l0 + r) * C_ + (k0 + kk)];
            }
            __syncthreads();
#pragma unroll 8
            for (int kk = 0; kk < 64; ++kk) {
                float av[4], bvv[4];
#pragma unroll
                for (int u = 0; u < 4; ++u) { av[u] = As[ty * 4 + u][kk]; bvv[u] = Bs[tx * 4 + u][kk]; }
#pragma unroll
                for (int u = 0; u < 4; ++u)
#pragma unroll
                    for (int q = 0; q < 4; ++q) acc[u][q] += av[u] * bvv[q];
            }
            __syncthreads();
        }
#pragma unroll
        for (int u = 0; u < 4; ++u)
#pragma unroll
            for (int q = 0; q < 4; ++q) {
                const size_t o = (size_t)(i0 + ty * 4 + u) * C_ + l0 + tx * 4 + q;
                outH[o] = __float2half_rn(acc[u][q]);
            }
    } else if (bid < 144) {
        // ---- epiprep: 32 columns per block (16 blocks)
        float (*part)[32] = (float(*)[32])sh;
        const int cl = tid & 31, jg = tid >> 5;          // 32 cols x 8 j-groups
        const int c = (bid - 128) * 32 + cl;
        float s = 0.f;
        for (int j = jg * 64; j < jg * 64 + 64; ++j)
            s += bv[j] * Wo[(size_t)j * C_ + c];
        part[jg][cl] = s;
        __syncthreads();
        if (jg == 0) {
            float c1 = 0.f;
#pragma unroll
            for (int p = 0; p < 8; ++p) c1 += part[p][cl];
            const float ka = bns[c] * rsqrtf(bnv[c] + BNEPS_);
            g_kmul[c] = ka;
            g_kadd[c] = (bo[c] - bnm[c]) * ka + bnb[c];
            g_c1k[c] = c1 * ka;
        }
    } else {
        // ---- xprep: 8 rows per block (4096 blocks): fp16 convert + bcol gemv
        float* v1s = (float*)sh;
        for (int c = tid; c < C_; c += 256) v1s[c] = g_v1[c];
        __syncthreads();
        const int row = (bid - 144) * 8 + (tid >> 5);
        const int lane = tid & 31;
        float s = 0.f;
#pragma unroll
        for (int i = 0; i < 4; ++i) {
            const int c = lane * 4 + i * 128;
            const float4 xv = *(const float4*)(x + (size_t)row * C_ + c);
            s += xv.x * v1s[c] + xv.y * v1s[c + 1] + xv.z * v1s[c + 2] + xv.w * v1s[c + 3];
            *(__half2*)(g_xh + (size_t)row * C_ + c) =
                __halves2half2(__float2half_rn(xv.x), __float2half_rn(xv.y));
            *(__half2*)(g_xh + (size_t)row * C_ + c + 2) =
                __halves2half2(__float2half_rn(xv.z), __float2half_rn(xv.w));
        }
#pragma unroll
        for (int off = 16; off > 0; off >>= 1) s += __shfl_xor_sync(0xffffffffu, s, off);
        if (lane == 0) g_bcol[row] = s;
    }
}

__global__ __launch_bounds__(1024) void gemv_w_kernel(const float* __restrict__ W,
                                                      const float* __restrict__ vec,
                                                      float* __restrict__ outv)
{
    const int row = blockIdx.x * 32 + (threadIdx.x >> 5);
    const int lane = threadIdx.x & 31;
    float s = 0.f;
#pragma unroll
    for (int i = 0; i < 4; ++i) {
        const int c = lane * 4 + i * 128;
        const float4 wv = *(const float4*)(W + (size_t)row * C_ + c);
        const float4 vv = *(const float4*)(vec + c);
        s += wv.x * vv.x + wv.y * vv.y + wv.z * vv.z + wv.w * vv.w;
    }
#pragma unroll
    for (int off = 16; off > 0; off >>= 1) s += __shfl_xor_sync(0xffffffffu, s, off);
    if (lane == 0) outv[row] = s;
}

__global__ __launch_bounds__(256) void colsum_kernel()
{
    __shared__ float sw[N_];
    __shared__ float red[256][8];

    const int jt = blockIdx.x, b = blockIdx.y;
    const int tile = jt >> 1;
    const int t = threadIdx.x;

    for (int m = t; m < N_; m += 256) {
        float pm[8];
#pragma unroll
        for (int j = 0; j < 8; ++j) pm[j] = g_pmax[((size_t)b * 8 + j) * N_ + m];
        float rmax = -FLT_MAX;
#pragma unroll
        for (int j = 0; j < 8; ++j) rmax = fmaxf(rmax, pm[j]);
        float rsum = 0.f;
#pragma unroll
        for (int j = 0; j < 8; ++j)
            rsum += g_psum[((size_t)b * 8 + j) * N_ + m] * __expf(pm[j] - rmax);
        sw[m] = __expf(pm[tile] - rmax) / rsum;
    }
    __syncthreads();

    const int c8 = t & 15;
    const int mh = t >> 4;
    const int n0 = jt * 128 + c8 * 8;
    const h16* Eb = g_E + (size_t)b * N_ * N_;

    float a[8] = {};
#pragma unroll 4
    for (int m = mh * 128; m < mh * 128 + 128; ++m) {
        const float wm = sw[m];
        const uint4 u = *(const uint4*)(Eb + (size_t)m * N_ + n0);
        const __half2* e2 = (const __half2*)&u;
#pragma unroll
        for (int q = 0; q < 4; ++q) {
            const float2 f = __half22float2(e2[q]);
            a[q * 2 + 0] += wm * f.x;
            a[q * 2 + 1] += wm * f.y;
        }
    }
#pragma unroll
    for (int q = 0; q < 8; ++q) red[t][q] = a[q];
    __syncthreads();
    if (mh == 0) {
#pragma unroll
        for (int q = 0; q < 8; ++q) {
            float c = a[q];
#pragma unroll 1
            for (int sp = 1; sp < 16; ++sp) c += red[sp * 16 + c8][q];
            g_scale[(size_t)b * N_ + n0 + q] = c / (EPS_ + c);
        }
    }
}

extern "C" void kernel_launch(void* const* d_in, const int* in_sizes, int n_in,
                              void* d_out, int out_size)
{
    const float* x   = (const float*)d_in[0];
    const float* Wq  = (const float*)d_in[1];
    const float* bq  = (const float*)d_in[2];
    const float* Wk  = (const float*)d_in[3];
    const float* bk  = (const float*)d_in[4];  // unused: row bias cancels in softmax
    const float* Wv  = (const float*)d_in[5];
    const float* bv  = (const float*)d_in[6];
    const float* Wo  = (const float*)d_in[7];
    const float* bo  = (const float*)d_in[8];
    const float* bns = (const float*)d_in[9];
    const float* bnb = (const float*)d_in[10];
    const float* bnm = (const float*)d_in[11];
    const float* bnv = (const float*)d_in[12];
    float* out = (float*)d_out;
    (void)bk;

    cudaFuncSetAttribute(gemm_t,   cudaFuncAttributeMaxDynamicSharedMemorySize, DYN_SMEM);
    cudaFuncSetAttribute(gemm_s,   cudaFuncAttributeMaxDynamicSharedMemorySize, DYN_SMEM);
    cudaFuncSetAttribute(gemm_out, cudaFuncAttributeMaxDynamicSharedMemorySize, DYN_SMEM);

    h16 *mh, *ph;
    float *v1;
    cudaGetSymbolAddress((void**)&mh, g_mh);
    cudaGetSymbolAddress((void**)&ph, g_ph);
    cudaGetSymbolAddress((void**)&v1, g_v1);

    // v1 = Wk·bq, then fused prep (weight products + epilogue consts + x convert/bcol)
    gemv_w_kernel<<<16, 1024>>>(Wk, bq, v1);
    prep_kernel<<<144 + 4096, 256>>>(Wk, Wq, Wo, Wv, x, bv, bo, bns, bnb, bnm, bnv);

    gemm_t<<<dim3(256, 2), 512, DYN_SMEM>>>(mh);
    gemm_s<<<dim3(16, 8, 16), 512, DYN_SMEM>>>();
    colsum_kernel<<<dim3(16, B_), 256>>>();
    gemm_out<<<dim3(256, 2), 512, DYN_SMEM>>>(ph, x, out);
}

// round 16
// speedup vs baseline: 11.7349x; 1.0964x over previous
#include <cuda_runtime.h>
#include <cuda_fp16.h>
#include <math.h>
#include <float.h>
#include <stdint.h>

#define B_ 16
#define N_ 2048
#define C_ 512
#define EPS_ 1e-9f
#define BNEPS_ 1e-5f
#define EBIAS_ 10.0f   // fp16-E exponent bias; cancels exactly in col = Σ E·w

typedef __half h16;

__device__ h16 g_xh[B_ * N_ * C_];
__device__ h16 g_th[B_ * N_ * C_];
__device__ h16 g_mh[C_ * C_];
__device__ h16 g_ph[C_ * C_];
__device__ h16 g_E[(size_t)B_ * N_ * N_];
__device__ float g_pmax[B_ * 16 * N_], g_psum[B_ * 16 * N_];
__device__ float g_scale[B_ * N_], g_bcol[B_ * N_];
__device__ float g_v1[C_], g_c1k[C_], g_kmul[C_], g_kadd[C_];

__device__ __forceinline__ uint32_t smem_u32(const void* p) {
    uint32_t a;
    asm("{ .reg .u64 t; cvta.to.shared.u64 t, %1; cvt.u32.u64 %0, t; }" : "=r"(a) : "l"(p));
    return a;
}
#define SWZ(o) ((o) ^ (((o) >> 3) & 0x70))

#define CPASYNC(s, g) asm volatile("cp.async.cg.shared.global [%0], [%1], 16;" :: "r"(s), "l"(g))
#define CPCOMMIT()    asm volatile("cp.async.commit_group;" ::: "memory")
#define CPWAIT1()     asm volatile("cp.async.wait_group 1;" ::: "memory")
#define CPWAIT0()     asm volatile("cp.async.wait_group 0;" ::: "memory")

__device__ __forceinline__ void ldsm4(uint32_t addr, uint32_t& r0, uint32_t& r1,
                                      uint32_t& r2, uint32_t& r3) {
    asm volatile("ldmatrix.sync.aligned.m8n8.x4.shared.b16 {%0,%1,%2,%3}, [%4];"
                 : "=r"(r0), "=r"(r1), "=r"(r2), "=r"(r3) : "r"(addr));
}

__device__ __forceinline__ void mma16816(float* c, uint32_t a0, uint32_t a1,
                                         uint32_t a2, uint32_t a3,
                                         uint32_t b0, uint32_t b1) {
    asm volatile(
        "mma.sync.aligned.m16n8k16.row.col.f32.f16.f16.f32 "
        "{%0,%1,%2,%3}, {%4,%5,%6,%7}, {%8,%9}, {%0,%1,%2,%3};"
        : "+f"(c[0]), "+f"(c[1]), "+f"(c[2]), "+f"(c[3])
        : "r"(a0), "r"(a1), "r"(a2), "r"(a3), "r"(b0), "r"(b1));
}

// 3 stages of 32K (A 16K + B 16K); 96K stages + red; 2 CTAs/SM.
#define STAGE_STRIDE 32768
#define OFF_RED 98304
#define DYN_SMEM (98304 + 1280)
#define STG_STRIDE 272

// ---------------- cp.async stage loader (256 thr, M=128/N=128) ---------------
__device__ __forceinline__ void load_stage(uint32_t sb, int s, int tid,
        const h16* __restrict__ A, size_t arow0,
        const h16* __restrict__ Bh, size_t brow0)
{
    const int k0 = s * 64;
    const uint32_t stb = sb + (uint32_t)(s % 3) * STAGE_STRIDE;
    const int row = tid >> 3;            // 0..31
    const int c = tid & 7;               // 16B chunk
    const size_t gk = (size_t)(k0 + c * 8);
#pragma unroll
    for (int h = 0; h < 4; ++h) {
        const int r = row + h * 32;      // 0..127
        const uint32_t off = SWZ((uint32_t)(r * 128 + c * 16));
        CPASYNC(stb + off,         A  + (arow0 + r) * C_ + gk);
        CPASYNC(stb + 16384 + off, Bh + (brow0 + r) * C_ + gk);
    }
    CPCOMMIT();
}

// -------- compute one 64-K stage into acc (warp tile 32x64, 8 warps) ---------
__device__ __forceinline__ void compute_stage(uint32_t sb, int s, int lane,
                                              int wm, int wn, float acc[2][8][4])
{
    const uint32_t stb = sb + (uint32_t)(s % 3) * STAGE_STRIDE;
#pragma unroll
    for (int k16 = 0; k16 < 4; ++k16) {
        uint32_t ah[2][4], bh[4][4];
        const uint32_t akoff = (uint32_t)(k16 * 32 + (lane >> 4) * 16);
#pragma unroll
        for (int mt = 0; mt < 2; ++mt) {
            const int row = wm * 32 + mt * 16 + (lane & 15);
            const uint32_t a = SWZ((uint32_t)(row * 128) + akoff);
            ldsm4(stb + a, ah[mt][0], ah[mt][1], ah[mt][2], ah[mt][3]);
        }
        const int g = lane >> 3;
        const int nofs = (lane & 7) + (g >> 1) * 8;
        const uint32_t bk = (uint32_t)(k16 * 32 + (g & 1) * 16);
#pragma unroll
        for (int nt4 = 0; nt4 < 4; ++nt4) {
            const int n = wn * 64 + nt4 * 16 + nofs;
            const uint32_t a = SWZ((uint32_t)(n * 128) + bk);
            ldsm4(stb + 16384 + a, bh[nt4][0], bh[nt4][1], bh[nt4][2], bh[nt4][3]);
        }
#pragma unroll
        for (int mt = 0; mt < 2; ++mt)
#pragma unroll
            for (int j = 0; j < 8; ++j) {
                const int p = j >> 1, hi = (j & 1) * 2;
                mma16816(acc[mt][j], ah[mt][0], ah[mt][1], ah[mt][2], ah[mt][3],
                         bh[p][hi], bh[p][hi + 1]);
            }
    }
}

// ------ mainloop: D[128,128] = A·B^T, 3-stage ring, 1 sync/stage -------------
__device__ __forceinline__ void mma_mainloop(uint32_t sb,
        const h16* __restrict__ A, size_t arow0,
        const h16* __restrict__ Bh, size_t brow0,
        float acc[2][8][4])
{
    const int tid = threadIdx.x;
    const int lane = tid & 31;
    const int w = tid >> 5;
    const int wm = w & 3, wn = w >> 2;

#pragma unroll
    for (int mt = 0; mt < 2; ++mt)
#pragma unroll
        for (int j = 0; j < 8; ++j)
#pragma unroll
            for (int q = 0; q < 4; ++q) acc[mt][j][q] = 0.f;

    load_stage(sb, 0, tid, A, arow0, Bh, brow0);
    load_stage(sb, 1, tid, A, arow0, Bh, brow0);
#pragma unroll 1
    for (int s = 0; s < 8; ++s) {
        if (s < 7) CPWAIT1();
        else CPWAIT0();
        __syncthreads();
        // buffer (s+2)%3 == (s-1)%3: its readers finished before the sync.
        if (s < 6) load_stage(sb, s + 2, tid, A, arow0, Bh, brow0);
        compute_stage(sb, s, lane, wm, wn, acc);
    }
}

// ------------------- t = x·M GEMM (fp16, staged store) -----------------------
__global__ __launch_bounds__(256, 2)
void gemm_t(const h16* __restrict__ Bh)
{
    extern __shared__ __align__(128) char smem[];
    const uint32_t sb = smem_u32(smem);
    const size_t arow0 = (size_t)blockIdx.x * 128;
    const size_t brow0 = (size_t)blockIdx.y * 128;

    float acc[2][8][4];
    mma_mainloop(sb, g_xh, arow0, Bh, brow0, acc);

    const int tid = threadIdx.x, lane = tid & 31, w = tid >> 5;
    const int wm = w & 3, wn = w >> 2;

    __syncthreads();   // staging area overlaps last stage buffer
#pragma unroll
    for (int mt = 0; mt < 2; ++mt)
#pragma unroll
        for (int half = 0; half < 2; ++half) {
            const int r = wm * 32 + mt * 16 + half * 8 + lane / 4;
#pragma unroll
            for (int j = 0; j < 8; ++j) {
                const int col = wn * 64 + j * 8 + (lane & 3) * 2;
                *(__half2*)(smem + r * STG_STRIDE + col * 2) =
                    __halves2half2(__float2half_rn(acc[mt][j][half * 2 + 0]),
                                   __float2half_rn(acc[mt][j][half * 2 + 1]));
            }
        }
    __syncthreads();
#pragma unroll
    for (int pass = 0; pass < 8; ++pass) {
        const int r = pass * 16 + (tid >> 4);
        const int c16 = tid & 15;
        const uint4 v = *(const uint4*)(smem + r * STG_STRIDE + c16 * 16);
        *(uint4*)(g_th + (arow0 + r) * C_ + brow0 + c16 * 8) = v;
    }
}

// -------- S-pass: s = th·xh^T + b_n ; stats + staged biased fp16 exp ---------
__global__ __launch_bounds__(256, 2)
void gemm_s()
{
    extern __shared__ __align__(128) char smem[];
    const uint32_t sb = smem_u32(smem);
    float* red = (float*)(smem + OFF_RED);

    const int it = blockIdx.x, jt = blockIdx.y, bb = blockIdx.z;
    const size_t arow0 = (size_t)bb * N_ + (size_t)it * 128;
    const size_t brow0 = (size_t)bb * N_ + (size_t)jt * 128;

    float acc[2][8][4];
    mma_mainloop(sb, g_th, arow0, g_xh, brow0, acc);

    const int tid = threadIdx.x, lane = tid & 31, w = tid >> 5;
    const int wm = w & 3, wn = w >> 2;

    const int base_n = bb * N_ + jt * 128;
    float bc[8][2];
#pragma unroll
    for (int j = 0; j < 8; ++j) {
        const int col = wn * 64 + j * 8 + (lane & 3) * 2;
        bc[j][0] = __ldg(g_bcol + base_n + col);
        bc[j][1] = __ldg(g_bcol + base_n + col + 1);
    }

    float rmx[4];
#pragma unroll
    for (int slot = 0; slot < 4; ++slot) {
        const int mt = slot >> 1, half = slot & 1;
        float m = -FLT_MAX;
#pragma unroll
        for (int j = 0; j < 8; ++j) {
            m = fmaxf(m, acc[mt][j][half * 2 + 0] + bc[j][0]);
            m = fmaxf(m, acc[mt][j][half * 2 + 1] + bc[j][1]);
        }
        m = fmaxf(m, __shfl_xor_sync(0xffffffffu, m, 1));
        m = fmaxf(m, __shfl_xor_sync(0xffffffffu, m, 2));
        rmx[slot] = m;
    }
    __syncthreads();   // mainloop readers done; red area free
    if ((lane & 3) == 0) {
#pragma unroll
        for (int slot = 0; slot < 4; ++slot) {
            const int row = wm * 32 + (slot >> 1) * 16 + (slot & 1) * 8 + lane / 4;
            red[row * 2 + wn] = rmx[slot];
        }
    }
    __syncthreads();
    float rowmax[4];
#pragma unroll
    for (int slot = 0; slot < 4; ++slot) {
        const int row = wm * 32 + (slot >> 1) * 16 + (slot & 1) * 8 + lane / 4;
        rowmax[slot] = fmaxf(red[row * 2 + 0], red[row * 2 + 1]);
    }
    __syncthreads();

    // E = exp(s - rowmax + EBIAS) into smem staging; biased sums.
    // e^EBIAS appears in every E AND in psum -> cancels exactly in col = Σ E·w.
    float rsm[4];
#pragma unroll
    for (int slot = 0; slot < 4; ++slot) {
        const int mt = slot >> 1, half = slot & 1;
        const int r = wm * 32 + mt * 16 + half * 8 + lane / 4;
        float s = 0.f;
#pragma unroll
        for (int j = 0; j < 8; ++j) {
            const int col = wn * 64 + j * 8 + (lane & 3) * 2;
            const float e0 = __expf(acc[mt][j][half * 2 + 0] + bc[j][0] - rowmax[slot] + EBIAS_);
            const float e1 = __expf(acc[mt][j][half * 2 + 1] + bc[j][1] - rowmax[slot] + EBIAS_);
            *(__half2*)(smem + r * STG_STRIDE + col * 2) =
                __halves2half2(__float2half_rn(e0), __float2half_rn(e1));
            s += e0 + e1;
        }
        s += __shfl_xor_sync(0xffffffffu, s, 1);
        s += __shfl_xor_sync(0xffffffffu, s, 2);
        rsm[slot] = s;
    }
    if ((lane & 3) == 0) {
#pragma unroll
        for (int slot = 0; slot < 4; ++slot) {
            const int row = wm * 32 + (slot >> 1) * 16 + (slot & 1) * 8 + lane / 4;
            red[row * 2 + wn] = rsm[slot];
        }
    }
    __syncthreads();
    if (wn == 0 && (lane & 3) == 0) {
#pragma unroll
        for (int slot = 0; slot < 4; ++slot) {
            const int row = wm * 32 + (slot >> 1) * 16 + (slot & 1) * 8 + lane / 4;
            const size_t p = ((size_t)bb * 16 + jt) * N_ + it * 128 + row;
            g_pmax[p] = rowmax[slot];
            g_psum[p] = red[row * 2] + red[row * 2 + 1];
        }
    }
    // coalesced E copy-out (row stride N_)
    h16* Ebase = g_E + ((size_t)bb * N_ + it * 128) * N_ + jt * 128;
#pragma unroll
    for (int pass = 0; pass < 8; ++pass) {
        const int r = pass * 16 + (tid >> 4);
        const int c16 = tid & 15;
        const uint4 v = *(const uint4*)(smem + r * STG_STRIDE + c16 * 16);
        *(uint4*)(Ebase + (size_t)r * N_ + c16 * 8) = v;
    }
}

// ---------- final GEMM: x·P with fused scale/bias/BN/ReLU/residual ----------
__global__ __launch_bounds__(256, 2)
void gemm_out(const h16* __restrict__ Bh,
              const float* __restrict__ x, float* __restrict__ out)
{
    extern __shared__ __align__(128) char smem[];
    const uint32_t sb = smem_u32(smem);
    const size_t arow0 = (size_t)blockIdx.x * 128;
    const size_t brow0 = (size_t)blockIdx.y * 128;

    float acc[2][8][4];
    mma_mainloop(sb, g_xh, arow0, Bh, brow0, acc);

    const int tid = threadIdx.x, lane = tid & 31, w = tid >> 5;
    const int wm = w & 3, wn = w >> 2;

#pragma unroll
    for (int mt = 0; mt < 2; ++mt) {
#pragma unroll
        for (int half = 0; half < 2; ++half) {
            const size_t grow = arow0 + wm * 32 + mt * 16 + half * 8 + lane / 4;
            const float sc = g_scale[grow];
#pragma unroll
            for (int j = 0; j < 8; ++j) {
                const int col = (int)brow0 + wn * 64 + j * 8 + (lane & 3) * 2;
                const float2 xv = *(const float2*)(x + grow * C_ + col);
                const float km0 = __ldg(g_kmul + col), km1 = __ldg(g_kmul + col + 1);
                const float kd0 = __ldg(g_kadd + col), kd1 = __ldg(g_kadd + col + 1);
                const float ck0 = __ldg(g_c1k + col),  ck1 = __ldg(g_c1k + col + 1);
                float y0 = sc * (acc[mt][j][half * 2 + 0] * km0 + ck0) + kd0;
                float y1 = sc * (acc[mt][j][half * 2 + 1] * km1 + ck1) + kd1;
                float2 o;
                o.x = fmaxf(y0, 0.f) + xv.x;
                o.y = fmaxf(y1, 0.f) + xv.y;
                *(float2*)(out + grow * C_ + col) = o;
            }
        }
    }
}

// --------- merged prep: wgemm (128 blocks) + epiprep (16) + xprep (4096) -----
__global__ __launch_bounds__(256) void prep_kernel(
    const float* __restrict__ Wk, const float* __restrict__ Wq,
    const float* __restrict__ Wo, const float* __restrict__ Wv,
    const float* __restrict__ x,  const float* __restrict__ bv,
    const float* __restrict__ bo,
    const float* __restrict__ bns, const float* __restrict__ bnb,
    const float* __restrict__ bnm, const float* __restrict__ bnv)
{
    __shared__ __align__(16) char sh[2 * 64 * 65 * 4];
    const int bid = blockIdx.x;
    const int tid = threadIdx.x;

    if (bid < 128) {
        float (*As)[65] = (float(*)[65])sh;
        float (*Bs)[65] = (float(*)[65])(sh + 64 * 65 * 4);
        const int bx = bid & 7, by = (bid >> 3) & 7, z = bid >> 6;
        const float* A  = z ? Wo : Wk;
        const float* Bm = z ? Wv : Wq;
        const int sa1 = z ? 1 : C_, sa2 = z ? C_ : 1;
        h16* outH = z ? g_ph : g_mh;
        const int i0 = by * 64, l0 = bx * 64;
        const int ty = tid >> 4, tx = tid & 15;
        float acc[4][4] = {};
        for (int k0 = 0; k0 < C_; k0 += 64) {
            for (int v = tid; v < 4096; v += 256) {
                const int r = v >> 6, kk = v & 63;
                As[r][kk] = A[(size_t)(i0 + r) * sa1 + (size_t)(k0 + kk) * sa2];
                Bs[r][kk] = Bm[(size_t)(l0 + r) * C_ + (k0 + kk)];
            }
            __syncthreads();
#pragma unroll 8
            for (int kk = 0; kk < 64; ++kk) {
                float av[4], bvv[4];
#pragma unroll
                for (int u = 0; u < 4; ++u) { av[u] = As[ty * 4 + u][kk]; bvv[u] = Bs[tx * 4 + u][kk]; }
#pragma unroll
                for (int u = 0; u < 4; ++u)
#pragma unroll
                    for (int q = 0; q < 4; ++q) acc[u][q] += av[u] * bvv[q];
            }
            __syncthreads();
        }
#pragma unroll
        for (int u = 0; u < 4; ++u)
#pragma unroll
            for (int q = 0; q < 4; ++q) {
                const size_t o = (size_t)(i0 + ty * 4 + u) * C_ + l0 + tx * 4 + q;
                outH[o] = __float2half_rn(acc[u][q]);
            }
    } else if (bid < 144) {
        float (*part)[32] = (float(*)[32])sh;
        const int cl = tid & 31, jg = tid >> 5;
        const int c = (bid - 128) * 32 + cl;
        float s = 0.f;
        for (int j = jg * 64; j < jg * 64 + 64; ++j)
            s += bv[j] * Wo[(size_t)j * C_ + c];
        part[jg][cl] = s;
        __syncthreads();
        if (jg == 0) {
            float c1 = 0.f;
#pragma unroll
            for (int p = 0; p < 8; ++p) c1 += part[p][cl];
            const float ka = bns[c] * rsqrtf(bnv[c] + BNEPS_);
            g_kmul[c] = ka;
            g_kadd[c] = (bo[c] - bnm[c]) * ka + bnb[c];
            g_c1k[c] = c1 * ka;
        }
    } else {
        float* v1s = (float*)sh;
        for (int c = tid; c < C_; c += 256) v1s[c] = g_v1[c];
        __syncthreads();
        const int row = (bid - 144) * 8 + (tid >> 5);
        const int lane = tid & 31;
        float s = 0.f;
#pragma unroll
        for (int i = 0; i < 4; ++i) {
            const int c = lane * 4 + i * 128;
            const float4 xv = *(const float4*)(x + (size_t)row * C_ + c);
            s += xv.x * v1s[c] + xv.y * v1s[c + 1] + xv.z * v1s[c + 2] + xv.w * v1s[c + 3];
            *(__half2*)(g_xh + (size_t)row * C_ + c) =
                __halves2half2(__float2half_rn(xv.x), __float2half_rn(xv.y));
            *(__half2*)(g_xh + (size_t)row * C_ + c + 2) =
                __halves2half2(__float2half_rn(xv.z), __float2half_rn(xv.w));
        }
#pragma unroll
        for (int off = 16; off > 0; off >>= 1) s += __shfl_xor_sync(0xffffffffu, s, off);
        if (lane == 0) g_bcol[row] = s;
    }
}

__global__ __launch_bounds__(1024) void gemv_w_kernel(const float* __restrict__ W,
                                                      const float* __restrict__ vec,
                                                      float* __restrict__ outv)
{
    const int row = blockIdx.x * 32 + (threadIdx.x >> 5);
    const int lane = threadIdx.x & 31;
    float s = 0.f;
#pragma unroll
    for (int i = 0; i < 4; ++i) {
        const int c = lane * 4 + i * 128;
        const float4 wv = *(const float4*)(W + (size_t)row * C_ + c);
        const float4 vv = *(const float4*)(vec + c);
        s += wv.x * vv.x + wv.y * vv.y + wv.z * vv.z + wv.w * vv.w;
    }
#pragma unroll
    for (int off = 16; off > 0; off >>= 1) s += __shfl_xor_sync(0xffffffffu, s, off);
    if (lane == 0) outv[row] = s;
}

// colsum with inline stats over 16 tiles of 128 columns.
__global__ __launch_bounds__(256) void colsum_kernel()
{
    __shared__ float sw[N_];
    __shared__ float red[256][8];

    const int jt = blockIdx.x, b = blockIdx.y;   // jt: 0..15, 128-col tile
    const int t = threadIdx.x;

    for (int m = t; m < N_; m += 256) {
        float pm[16];
#pragma unroll
        for (int j = 0; j < 16; ++j) pm[j] = g_pmax[((size_t)b * 16 + j) * N_ + m];
        float rmax = -FLT_MAX;
#pragma unroll
        for (int j = 0; j < 16; ++j) rmax = fmaxf(rmax, pm[j]);
        float rsum = 0.f;
#pragma unroll
        for (int j = 0; j < 16; ++j)
            rsum += g_psum[((size_t)b * 16 + j) * N_ + m] * __expf(pm[j] - rmax);
        sw[m] = __expf(pm[jt] - rmax) / rsum;
    }
    __syncthreads();

    const int c8 = t & 15;
    const int mh = t >> 4;
    const int n0 = jt * 128 + c8 * 8;
    const h16* Eb = g_E + (size_t)b * N_ * N_;

    float a[8] = {};
#pragma unroll 4
    for (int m = mh * 128; m < mh * 128 + 128; ++m) {
        const float wm = sw[m];
        const uint4 u = *(const uint4*)(Eb + (size_t)m * N_ + n0);
        const __half2* e2 = (const __half2*)&u;
#pragma unroll
        for (int q = 0; q < 4; ++q) {
            const float2 f = __half22float2(e2[q]);
            a[q * 2 + 0] += wm * f.x;
            a[q * 2 + 1] += wm * f.y;
        }
    }
#pragma unroll
    for (int q = 0; q < 8; ++q) red[t][q] = a[q];
    __syncthreads();
    if (mh == 0) {
#pragma unroll
        for (int q = 0; q < 8; ++q) {
            float c = a[q];
#pragma unroll 1
            for (int sp = 1; sp < 16; ++sp) c += red[sp * 16 + c8][q];
            g_scale[(size_t)b * N_ + n0 + q] = c / (EPS_ + c);
        }
    }
}

extern "C" void kernel_launch(void* const* d_in, const int* in_sizes, int n_in,
                              void* d_out, int out_size)
{
    const float* x   = (const float*)d_in[0];
    const float* Wq  = (const float*)d_in[1];
    const float* bq  = (const float*)d_in[2];
    const float* Wk  = (const float*)d_in[3];
    const float* bk  = (const float*)d_in[4];  // unused: row bias cancels in softmax
    const float* Wv  = (const float*)d_in[5];
    const float* bv  = (const float*)d_in[6];
    const float* Wo  = (const float*)d_in[7];
    const float* bo  = (const float*)d_in[8];
    const float* bns = (const float*)d_in[9];
    const float* bnb = (const float*)d_in[10];
    const float* bnm = (const float*)d_in[11];
    const float* bnv = (const float*)d_in[12];
    float* out = (float*)d_out;
    (void)bk;

    cudaFuncSetAttribute(gemm_t,   cudaFuncAttributeMaxDynamicSharedMemorySize, DYN_SMEM);
    cudaFuncSetAttribute(gemm_s,   cudaFuncAttributeMaxDynamicSharedMemorySize, DYN_SMEM);
    cudaFuncSetAttribute(gemm_out, cudaFuncAttributeMaxDynamicSharedMemorySize, DYN_SMEM);

    h16 *mh, *ph;
    float *v1;
    cudaGetSymbolAddress((void**)&mh, g_mh);
    cudaGetSymbolAddress((void**)&ph, g_ph);
    cudaGetSymbolAddress((void**)&v1, g_v1);

    gemv_w_kernel<<<16, 1024>>>(Wk, bq, v1);
    prep_kernel<<<144 + 4096, 256>>>(Wk, Wq, Wo, Wv, x, bv, bo, bns, bnb, bnm, bnv);

    gemm_t<<<dim3(256, 4), 256, DYN_SMEM>>>(mh);
    gemm_s<<<dim3(16, 16, 16), 256, DYN_SMEM>>>();
    colsum_kernel<<<dim3(16, B_), 256>>>();
    gemm_out<<<dim3(256, 4), 256, DYN_SMEM>>>(ph, x, out);
}